// round 5
// baseline (speedup 1.0000x reference)
#include <cuda_runtime.h>
#include <cuda_bf16.h>
#include <cstdint>
#include <cstddef>

// ---------------- problem constants ----------------
#define NAG 64           // B*A
#define DIN 360          // logical dim
#define DD  (DIN*DIN)
#define MODE_LEN 60
#define DP  384          // padded dim (3 x 128)
#define DP2 (DP*DP)

// ---------------- scratch: bf16 hi/lo pairs ----------------
__device__ __align__(128) __nv_bfloat16 g_Sh [(size_t)NAG*DP2];
__device__ __align__(128) __nv_bfloat16 g_Sl [(size_t)NAG*DP2];
__device__ __align__(128) __nv_bfloat16 g_XAh[(size_t)NAG*DP2];
__device__ __align__(128) __nv_bfloat16 g_XAl[(size_t)NAG*DP2];
__device__ __align__(128) __nv_bfloat16 g_XBh[(size_t)NAG*DP2];
__device__ __align__(128) __nv_bfloat16 g_XBl[(size_t)NAG*DP2];
__device__ __align__(128) __nv_bfloat16 g_Yh [(size_t)NAG*DP2];
__device__ __align__(128) __nv_bfloat16 g_Yl [(size_t)NAG*DP2];
__device__ float g_r[NAG];
__device__ float g_c[NAG];
__device__ int   g_upd[NAG];
__device__ int   g_initnew[NAG];
__device__ int   g_initout[NAG];

__device__ __forceinline__ __nv_bfloat16* selH(int s) {
    switch (s) {
        case 0:  return g_Sh;
        case 1:  return g_XAh;
        case 2:  return g_XBh;
        default: return g_Yh;
    }
}
__device__ __forceinline__ __nv_bfloat16* selL(int s) {
    switch (s) {
        case 0:  return g_Sl;
        case 1:  return g_XAl;
        case 2:  return g_XBl;
        default: return g_Yl;
    }
}

__device__ __forceinline__ int srcIdx(int g) {
    int l = g % MODE_LEN;
    return (l < MODE_LEN - 2) ? (g + 2) : g;
}

// ---------------- small helpers ----------------
__device__ __forceinline__ uint32_t smem_u32(const void* p) {
    uint32_t a;
    asm("{ .reg .u64 t; cvta.to.shared.u64 t, %1; cvt.u32.u64 %0, t; }"
        : "=r"(a) : "l"(p));
    return a;
}
__device__ __forceinline__ uint32_t pack_bf2(float x, float y) {
    __nv_bfloat162 t = __floats2bfloat162_rn(x, y);
    return *reinterpret_cast<uint32_t*>(&t);
}
__device__ __forceinline__ float2 bf2f(uint32_t u) {
    __nv_bfloat162 t = *reinterpret_cast<__nv_bfloat162*>(&u);
    return make_float2(__bfloat162float(t.x), __bfloat162float(t.y));
}
// split (a,b) into hi/lo packed bf16x2 words
__device__ __forceinline__ void split2(float a, float b, uint32_t& h, uint32_t& l) {
    __nv_bfloat16 ah = __float2bfloat16_rn(a), bh = __float2bfloat16_rn(b);
    float ar = a - __bfloat162float(ah), br = b - __bfloat162float(bh);
    __nv_bfloat162 t; t.x = ah; t.y = bh;
    h = *reinterpret_cast<uint32_t*>(&t);
    l = pack_bf2(ar, br);
}

// ---------------- flag dtype sniffing (validated round 2) ----------------
__device__ int detect_mode(const unsigned char* p) {
    int n_off = 0, n_3f = 0;
    for (int t = 0; t < 64; t++) {
        unsigned char b = p[t];
        if ((t & 3) && b) n_off++;
        if (((t & 3) == 3) && b == 0x3F) n_3f++;
    }
    if (n_off == 0) return 1;
    if (n_3f > 0)  return 2;
    return 0;
}
__device__ __forceinline__ bool read_flag(const void* p, int t, int mode) {
    if (mode == 1) return ((const int*)p)[t] != 0;
    if (mode == 2) return ((const float*)p)[t] != 0.0f;
    return ((const unsigned char*)p)[t] != 0;
}

__global__ void prep_flags(const float* __restrict__ rs,
                           const void* __restrict__ ini,
                           const void* __restrict__ sel) {
    __shared__ int mode_i, mode_s;
    if (threadIdx.x == 0) {
        mode_i = detect_mode((const unsigned char*)ini);
        mode_s = detect_mode((const unsigned char*)sel);
    }
    __syncthreads();
    int t = threadIdx.x;
    if (t >= NAG) return;
    float r = rs[t] + 1.0f;
    bool i8 = read_flag(ini, t, mode_i);
    bool s8 = read_flag(sel, t, mode_s);
    g_r[t] = r;
    g_upd[t] = (s8 && i8);
    g_initnew[t] = (s8 && !i8);
    g_initout[t] = (s8 || i8);
}

// ---------------- S = A P A^T + (1+r) I  -> split bf16, padded to 384 ----
__global__ void build_S(const float* __restrict__ cov) {
    int a = blockIdx.y;
    if (!g_upd[a]) return;
    int e = blockIdx.x * blockDim.x + threadIdx.x;
    if (e >= DP2) return;
    int i = e / DP, j = e % DP;
    float v;
    if (i < DIN && j < DIN) {
        v = cov[(size_t)a * DD + (size_t)srcIdx(i) * DIN + srcIdx(j)];
        if (i == j) v += 1.0f + g_r[a];
    } else {
        v = (i == j) ? 1.0f : 0.0f;
    }
    __nv_bfloat16 h = __float2bfloat16_rn(v);
    g_Sh[(size_t)a * DP2 + e] = h;
    g_Sl[(size_t)a * DP2 + e] = __float2bfloat16_rn(v - __bfloat162float(h));
}

__global__ void gersh(void) {
    int a = blockIdx.x;
    if (!g_upd[a]) return;
    const __nv_bfloat16* Sh = g_Sh + (size_t)a * DP2;
    const __nv_bfloat16* Sl = g_Sl + (size_t)a * DP2;
    int warp = threadIdx.x >> 5, lane = threadIdx.x & 31;
    float m = 0.0f;
    for (int i = warp; i < DIN; i += 8) {
        float s = 0.0f;
        size_t row = (size_t)i * DP;
        for (int j = lane; j < DIN; j += 32)
            s += fabsf(__bfloat162float(Sh[row + j]) + __bfloat162float(Sl[row + j]));
        #pragma unroll
        for (int o = 16; o; o >>= 1) s += __shfl_xor_sync(0xffffffffu, s, o);
        m = fmaxf(m, s);
    }
    __shared__ float wm[8];
    if (lane == 0) wm[warp] = m;
    __syncthreads();
    if (threadIdx.x == 0) {
        float G = 0.0f;
        #pragma unroll
        for (int w = 0; w < 8; w++) G = fmaxf(G, wm[w]);
        float lmin = 1.0f + g_r[a];
        g_c[a] = 2.0f / (lmin + G * 1.0002f);
    }
}

// X0 = 2c I - c^2 S  -> split bf16 into XA
__global__ void fill_X(void) {
    int a = blockIdx.y;
    if (!g_upd[a]) return;
    int e = blockIdx.x * blockDim.x + threadIdx.x;
    if (e >= DP2) return;
    int i = e / DP, j = e % DP;
    float c = g_c[a];
    size_t idx = (size_t)a * DP2 + e;
    float s = __bfloat162float(g_Sh[idx]) + __bfloat162float(g_Sl[idx]);
    float v = ((i == j) ? 2.0f * c : 0.0f) - c * c * s;
    __nv_bfloat16 h = __float2bfloat16_rn(v);
    g_XAh[idx] = h;
    g_XAl[idx] = __float2bfloat16_rn(v - __bfloat162float(h));
}

// ================= mma.sync bf16 batched GEMM (symmetric, 6 tiles) =======
#define LDT 72
#define TILE_E (128 * LDT)
#define LDC 129

__device__ __forceinline__ void ldm_x4(uint32_t* r, uint32_t addr) {
    asm volatile("ldmatrix.sync.aligned.m8n8.x4.shared.b16 {%0,%1,%2,%3}, [%4];"
                 : "=r"(r[0]), "=r"(r[1]), "=r"(r[2]), "=r"(r[3]) : "r"(addr));
}
__device__ __forceinline__ void mma_bf16(float* d, const uint32_t* a, const uint32_t* b) {
    asm volatile(
        "mma.sync.aligned.m16n8k16.row.col.f32.bf16.bf16.f32 "
        "{%0,%1,%2,%3}, {%4,%5,%6,%7}, {%8,%9}, {%0,%1,%2,%3};"
        : "+f"(d[0]), "+f"(d[1]), "+f"(d[2]), "+f"(d[3])
        : "r"(a[0]), "r"(a[1]), "r"(a[2]), "r"(a[3]), "r"(b[0]), "r"(b[1]));
}

// copy one 128x64 bf16 panel global -> SMEM tile via cp.async (16B chunks)
__device__ __forceinline__ void stage_async(const __nv_bfloat16* __restrict__ g,
                                            int row0, int k0, uint32_t dst_base,
                                            int tid) {
    const __nv_bfloat16* src0 = g + (size_t)row0 * DP + k0;
    #pragma unroll
    for (int i = 0; i < 4; i++) {
        int id = i * 256 + tid;
        int row = id >> 3, part = id & 7;
        uint32_t dst = dst_base + (uint32_t)(row * LDT + part * 8) * 2;
        const void* src = src0 + (size_t)row * DP + part * 8;
        asm volatile("cp.async.cg.shared.global [%0], [%1], 16;"
                     :: "r"(dst), "l"(src));
    }
}

// SPLIT=0: hi*hi only. SPLIT=1: hi*hi + hi*lo + lo*hi.
// MODE=0: C = A*B. MODE=1: C = 2X - A*B (X read from bf16 hi/lo pair).
// Only 6 of 9 tiles computed; off-diagonal tiles also write the transpose.
template<int SPLIT, int MODE>
__global__ __launch_bounds__(256)
void gemm_mma(int sA, int sB, int sX, int sC) {
    int z = blockIdx.z;
    if (!g_upd[z]) return;

    const int bi_map[6] = {0, 1, 2, 0, 0, 1};
    const int bj_map[6] = {0, 1, 2, 1, 2, 2};
    int bi = bi_map[blockIdx.x], bj = bj_map[blockIdx.x];
    int m0 = bi * 128, n0 = bj * 128;
    bool offd = (bi != bj);

    size_t zo = (size_t)z * DP2;
    const __nv_bfloat16* AH = selH(sA) + zo;
    const __nv_bfloat16* AL = selL(sA) + zo;
    const __nv_bfloat16* BH = selH(sB) + zo;
    const __nv_bfloat16* BL = selL(sB) + zo;
    const __nv_bfloat16* XH = selH(sX) + zo;
    const __nv_bfloat16* XL = selL(sX) + zo;
    __nv_bfloat16* CH = selH(sC) + zo;
    __nv_bfloat16* CL = selL(sC) + zo;

    extern __shared__ __align__(16) __nv_bfloat16 sm[];
    __nv_bfloat16* Ah = sm;
    __nv_bfloat16* Bh = sm + TILE_E;
    __nv_bfloat16* Al = sm + 2 * TILE_E;
    __nv_bfloat16* Bl = sm + 3 * TILE_E;
    float* Cs = reinterpret_cast<float*>(sm);   // reused in epilogue

    int tid = threadIdx.x, wid = tid >> 5, lane = tid & 31;
    int wm = (wid & 1) * 64, wn = (wid >> 1) * 32;

    float acc[4][4][4];
    #pragma unroll
    for (int i = 0; i < 4; i++)
        #pragma unroll
        for (int j = 0; j < 4; j++)
            #pragma unroll
            for (int q = 0; q < 4; q++) acc[i][j][q] = 0.0f;

    int lt = lane >> 3, lr = lane & 7;
    int a_row = (lt & 1) * 8 + lr;
    int a_col = (lt >> 1) * 8;
    int b_row = (lt >> 1) * 8 + lr;
    int b_col = (lt & 1) * 8;

    for (int kc = 0; kc < 6; kc++) {
        int k0 = kc * 64;
        stage_async(AH, m0, k0, smem_u32(Ah), tid);
        stage_async(BH, n0, k0, smem_u32(Bh), tid);
        if (SPLIT) {
            stage_async(AL, m0, k0, smem_u32(Al), tid);
            stage_async(BL, n0, k0, smem_u32(Bl), tid);
        }
        asm volatile("cp.async.commit_group;");
        asm volatile("cp.async.wait_group 0;");
        __syncthreads();

        #pragma unroll
        for (int ks = 0; ks < 4; ks++) {
            int kk = ks * 16;
            uint32_t afh[4][4], bfh[4][2];
            #pragma unroll
            for (int mt = 0; mt < 4; mt++)
                ldm_x4(afh[mt], smem_u32(&Ah[(wm + mt * 16 + a_row) * LDT + kk + a_col]));
            #pragma unroll
            for (int np = 0; np < 2; np++) {
                uint32_t r[4];
                ldm_x4(r, smem_u32(&Bh[(wn + np * 16 + b_row) * LDT + kk + b_col]));
                bfh[np * 2][0] = r[0]; bfh[np * 2][1] = r[1];
                bfh[np * 2 + 1][0] = r[2]; bfh[np * 2 + 1][1] = r[3];
            }
            #pragma unroll
            for (int mt = 0; mt < 4; mt++)
                #pragma unroll
                for (int nt = 0; nt < 4; nt++)
                    mma_bf16(acc[mt][nt], afh[mt], bfh[nt]);

            if (SPLIT) {
                uint32_t afl[4][4], bfl[4][2];
                #pragma unroll
                for (int mt = 0; mt < 4; mt++)
                    ldm_x4(afl[mt], smem_u32(&Al[(wm + mt * 16 + a_row) * LDT + kk + a_col]));
                #pragma unroll
                for (int np = 0; np < 2; np++) {
                    uint32_t r[4];
                    ldm_x4(r, smem_u32(&Bl[(wn + np * 16 + b_row) * LDT + kk + b_col]));
                    bfl[np * 2][0] = r[0]; bfl[np * 2][1] = r[1];
                    bfl[np * 2 + 1][0] = r[2]; bfl[np * 2 + 1][1] = r[3];
                }
                #pragma unroll
                for (int mt = 0; mt < 4; mt++)
                    #pragma unroll
                    for (int nt = 0; nt < 4; nt++) {
                        mma_bf16(acc[mt][nt], afh[mt], bfl[nt]);
                        mma_bf16(acc[mt][nt], afl[mt], bfh[nt]);
                    }
            }
        }
        __syncthreads();
    }

    // ---- epilogue: combine, split-write direct tile, bounce transpose ----
    #pragma unroll
    for (int mt = 0; mt < 4; mt++) {
        int rl0 = wm + mt * 16 + (lane >> 2);
        #pragma unroll
        for (int nt = 0; nt < 4; nt++) {
            int cl0 = wn + nt * 8 + 2 * (lane & 3);
            float v00 = acc[mt][nt][0], v01 = acc[mt][nt][1];
            float v10 = acc[mt][nt][2], v11 = acc[mt][nt][3];
            size_t g0 = (size_t)(m0 + rl0) * DP + n0 + cl0;
            size_t g1 = g0 + 8 * DP;
            if (MODE == 1) {
                float2 x0h = bf2f(*(const uint32_t*)(XH + g0));
                float2 x0l = bf2f(*(const uint32_t*)(XL + g0));
                float2 x1h = bf2f(*(const uint32_t*)(XH + g1));
                float2 x1l = bf2f(*(const uint32_t*)(XL + g1));
                v00 = 2.0f * (x0h.x + x0l.x) - v00;
                v01 = 2.0f * (x0h.y + x0l.y) - v01;
                v10 = 2.0f * (x1h.x + x1l.x) - v10;
                v11 = 2.0f * (x1h.y + x1l.y) - v11;
            }
            uint32_t h0, l0, h1, l1;
            split2(v00, v01, h0, l0);
            split2(v10, v11, h1, l1);
            *(uint32_t*)(CH + g0) = h0; *(uint32_t*)(CL + g0) = l0;
            *(uint32_t*)(CH + g1) = h1; *(uint32_t*)(CL + g1) = l1;
            if (offd) {
                Cs[rl0 * LDC + cl0] = v00;
                Cs[rl0 * LDC + cl0 + 1] = v01;
                Cs[(rl0 + 8) * LDC + cl0] = v10;
                Cs[(rl0 + 8) * LDC + cl0 + 1] = v11;
            }
        }
    }

    if (offd) {
        __syncthreads();
        #pragma unroll
        for (int it = 0; it < 32; it++) {
            int p = it * 256 + tid;
            int cc = p >> 6, mp = (p & 63) * 2;
            float v0 = Cs[mp * LDC + cc];
            float v1 = Cs[(mp + 1) * LDC + cc];
            uint32_t h, l;
            split2(v0, v1, h, l);
            size_t g = (size_t)(n0 + cc) * DP + m0 + mp;
            *(uint32_t*)(CH + g) = h;
            *(uint32_t*)(CL + g) = l;
        }
    }
}

// ---------------- outputs ----------------
#define OUT_MEAN 0
#define OUT_COV  (NAG * DIN)
#define OUT_INIT (NAG * DIN + NAG * DD)

__global__ void finalize_cov(const float* __restrict__ cov,
                             float* __restrict__ out, int sinv) {
    int a = blockIdx.y;
    int e4 = blockIdx.x * blockDim.x + threadIdx.x;
    if (e4 >= DD / 4) return;
    int i = e4 / 90;
    int jj = (e4 % 90) * 4;
    float r = g_r[a];
    float4 o;
    if (g_initnew[a]) {
        o = *(const float4*)(cov + (size_t)a * DD + (size_t)i * DIN + jj);
        if (i >= jj && i < jj + 4) (&o.x)[i - jj] += r;
    } else if (g_upd[a]) {
        const __nv_bfloat16* Xh = selH(sinv) + (size_t)a * DP2;
        const __nv_bfloat16* Xl = selL(sinv) + (size_t)a * DP2;
        size_t off = (size_t)i * DP + jj;
        float2 h0 = bf2f(*(const uint32_t*)(Xh + off));
        float2 h1 = bf2f(*(const uint32_t*)(Xh + off + 2));
        float2 l0 = bf2f(*(const uint32_t*)(Xl + off));
        float2 l1 = bf2f(*(const uint32_t*)(Xl + off + 2));
        float rr = -r * r;
        o.x = rr * (h0.x + l0.x); o.y = rr * (h0.y + l0.y);
        o.z = rr * (h1.x + l1.x); o.w = rr * (h1.y + l1.y);
        if (i >= jj && i < jj + 4) (&o.x)[i - jj] += r;
    } else {
        o = *(const float4*)(cov + (size_t)a * DD + (size_t)i * DIN + jj);
    }
    *(float4*)(out + OUT_COV + (size_t)a * DD + (size_t)i * DIN + jj) = o;
}

__global__ void finalize_mean(const float* __restrict__ mean_in,
                              const float* __restrict__ obs,
                              float* __restrict__ out, int sinv) {
    int a = blockIdx.x;
    int tid = threadIdx.x;
    __shared__ float v[DIN];

    if (tid == 0) out[OUT_INIT + a] = g_initout[a] ? 1.0f : 0.0f;

    const float* m = mean_in + (size_t)a * DIN;
    const float* o = obs + (size_t)a * DIN;
    float* om = out + OUT_MEAN + (size_t)a * DIN;

    if (g_initnew[a]) {
        for (int i = tid; i < DIN; i += blockDim.x) om[i] = o[i];
    } else if (g_upd[a]) {
        float r = g_r[a];
        const __nv_bfloat16* Xh = selH(sinv) + (size_t)a * DP2;
        const __nv_bfloat16* Xl = selL(sinv) + (size_t)a * DP2;
        for (int j = tid; j < DIN; j += blockDim.x) v[j] = o[j] - m[srcIdx(j)];
        __syncthreads();
        int warp = tid >> 5, lane = tid & 31;
        for (int i = warp; i < DIN; i += 8) {
            float s = 0.0f;
            size_t row = (size_t)i * DP;
            for (int j = lane; j < DIN; j += 32)
                s += (__bfloat162float(Xh[row + j]) + __bfloat162float(Xl[row + j])) * v[j];
            #pragma unroll
            for (int off = 16; off; off >>= 1) s += __shfl_xor_sync(0xffffffffu, s, off);
            if (lane == 0) om[i] = o[i] - r * s;
        }
    } else {
        for (int i = tid; i < DIN; i += blockDim.x) om[i] = m[i];
    }
}

// ---------------- launch ----------------
extern "C" void kernel_launch(void* const* d_in, const int* in_sizes, int n_in,
                              void* d_out, int out_size) {
    const float* mean = (const float*)d_in[0];
    const float* cov  = (const float*)d_in[1];
    const float* obs  = (const float*)d_in[2];
    const float* rs   = (const float*)d_in[3];
    const void*  ini  = d_in[4];
    const void*  sel  = d_in[5];
    float* out = (float*)d_out;

    const int SM_PLAIN = 128 * LDC * 4;          // 66048 (Cs dominates)
    const int SM_SPLIT = 4 * TILE_E * 2;         // 73728

    cudaFuncSetAttribute(gemm_mma<0, 0>, cudaFuncAttributeMaxDynamicSharedMemorySize, SM_PLAIN);
    cudaFuncSetAttribute(gemm_mma<0, 1>, cudaFuncAttributeMaxDynamicSharedMemorySize, SM_PLAIN);
    cudaFuncSetAttribute(gemm_mma<1, 0>, cudaFuncAttributeMaxDynamicSharedMemorySize, SM_SPLIT);
    cudaFuncSetAttribute(gemm_mma<1, 1>, cudaFuncAttributeMaxDynamicSharedMemorySize, SM_SPLIT);

    const int EBP = (DP2 + 255) / 256;

    prep_flags<<<1, 64>>>(rs, ini, sel);
    build_S<<<dim3(EBP, NAG), 256>>>(cov);
    gersh<<<NAG, 256>>>();
    fill_X<<<dim3(EBP, NAG), 256>>>();

    dim3 g6(6, 1, NAG);
    // pairs: 0=S, 1=XA, 2=XB, 3=Y
    // iter1 (plain): Y = S*XA ; XB = 2XA - XA*Y
    gemm_mma<0, 0><<<g6, 256, SM_PLAIN>>>(0, 1, 0, 3);
    gemm_mma<0, 1><<<g6, 256, SM_PLAIN>>>(1, 3, 1, 2);
    // iter2 (plain): Y = S*XB ; XA = 2XB - XB*Y
    gemm_mma<0, 0><<<g6, 256, SM_PLAIN>>>(0, 2, 0, 3);
    gemm_mma<0, 1><<<g6, 256, SM_PLAIN>>>(2, 3, 2, 1);
    // iter3 (split): Y = S*XA ; XB = 2XA - XA*Y
    gemm_mma<1, 0><<<g6, 256, SM_SPLIT>>>(0, 1, 0, 3);
    gemm_mma<1, 1><<<g6, 256, SM_SPLIT>>>(1, 3, 1, 2);
    // iter4 (split): Y = S*XB ; XA = 2XB - XB*Y
    gemm_mma<1, 0><<<g6, 256, SM_SPLIT>>>(0, 2, 0, 3);
    gemm_mma<1, 1><<<g6, 256, SM_SPLIT>>>(2, 3, 2, 1);

    finalize_cov<<<dim3((DD / 4 + 255) / 256, NAG), 256>>>(cov, out, 1);
    finalize_mean<<<NAG, 256>>>(mean, obs, out, 1);
}

// round 6
// speedup vs baseline: 1.1730x; 1.1730x over previous
#include <cuda_runtime.h>
#include <cuda_bf16.h>
#include <cstdint>
#include <cstddef>

// ---------------- problem constants ----------------
#define NAG 64           // B*A
#define DIN 360          // logical dim
#define DD  (DIN*DIN)
#define MODE_LEN 60
#define DP  384          // padded dim (3 x 128)
#define DP2 (DP*DP)

// ---------------- scratch: bf16 hi/lo pairs ----------------
__device__ __align__(128) __nv_bfloat16 g_Sh [(size_t)NAG*DP2];
__device__ __align__(128) __nv_bfloat16 g_Sl [(size_t)NAG*DP2];
__device__ __align__(128) __nv_bfloat16 g_XAh[(size_t)NAG*DP2];
__device__ __align__(128) __nv_bfloat16 g_XAl[(size_t)NAG*DP2];
__device__ __align__(128) __nv_bfloat16 g_XBh[(size_t)NAG*DP2];
__device__ __align__(128) __nv_bfloat16 g_XBl[(size_t)NAG*DP2];
__device__ __align__(128) __nv_bfloat16 g_Yh [(size_t)NAG*DP2];
__device__ __align__(128) __nv_bfloat16 g_Yl [(size_t)NAG*DP2];
__device__ float g_rowsum[NAG * DIN];
__device__ float g_r[NAG];
__device__ float g_c[NAG];
__device__ int   g_upd[NAG];
__device__ int   g_initnew[NAG];
__device__ int   g_initout[NAG];

__device__ __forceinline__ __nv_bfloat16* selH(int s) {
    switch (s) {
        case 0:  return g_Sh;
        case 1:  return g_XAh;
        case 2:  return g_XBh;
        default: return g_Yh;
    }
}
__device__ __forceinline__ __nv_bfloat16* selL(int s) {
    switch (s) {
        case 0:  return g_Sl;
        case 1:  return g_XAl;
        case 2:  return g_XBl;
        default: return g_Yl;
    }
}

__device__ __forceinline__ int srcIdx(int g) {
    int l = g % MODE_LEN;
    return (l < MODE_LEN - 2) ? (g + 2) : g;
}

// ---------------- small helpers ----------------
__device__ __forceinline__ uint32_t smem_u32(const void* p) {
    uint32_t a;
    asm("{ .reg .u64 t; cvta.to.shared.u64 t, %1; cvt.u32.u64 %0, t; }"
        : "=r"(a) : "l"(p));
    return a;
}
__device__ __forceinline__ uint32_t pack_bf2(float x, float y) {
    __nv_bfloat162 t = __floats2bfloat162_rn(x, y);
    return *reinterpret_cast<uint32_t*>(&t);
}
__device__ __forceinline__ float2 bf2f(uint32_t u) {
    __nv_bfloat162 t = *reinterpret_cast<__nv_bfloat162*>(&u);
    return make_float2(__bfloat162float(t.x), __bfloat162float(t.y));
}
__device__ __forceinline__ void split2(float a, float b, uint32_t& h, uint32_t& l) {
    __nv_bfloat16 ah = __float2bfloat16_rn(a), bh = __float2bfloat16_rn(b);
    float ar = a - __bfloat162float(ah), br = b - __bfloat162float(bh);
    __nv_bfloat162 t; t.x = ah; t.y = bh;
    h = *reinterpret_cast<uint32_t*>(&t);
    l = pack_bf2(ar, br);
}

// ---------------- flag dtype sniffing (validated round 2) ----------------
__device__ int detect_mode(const unsigned char* p) {
    int n_off = 0, n_3f = 0;
    for (int t = 0; t < 64; t++) {
        unsigned char b = p[t];
        if ((t & 3) && b) n_off++;
        if (((t & 3) == 3) && b == 0x3F) n_3f++;
    }
    if (n_off == 0) return 1;
    if (n_3f > 0)  return 2;
    return 0;
}
__device__ __forceinline__ bool read_flag(const void* p, int t, int mode) {
    if (mode == 1) return ((const int*)p)[t] != 0;
    if (mode == 2) return ((const float*)p)[t] != 0.0f;
    return ((const unsigned char*)p)[t] != 0;
}

__global__ void prep_flags(const float* __restrict__ rs,
                           const void* __restrict__ ini,
                           const void* __restrict__ sel) {
    __shared__ int mode_i, mode_s;
    if (threadIdx.x == 0) {
        mode_i = detect_mode((const unsigned char*)ini);
        mode_s = detect_mode((const unsigned char*)sel);
    }
    __syncthreads();
    int t = threadIdx.x;
    if (t >= NAG) return;
    float r = rs[t] + 1.0f;
    bool i8 = read_flag(ini, t, mode_i);
    bool s8 = read_flag(sel, t, mode_s);
    g_r[t] = r;
    g_upd[t] = (s8 && i8);
    g_initnew[t] = (s8 && !i8);
    g_initout[t] = (s8 || i8);
}

// ---------------- S = A P A^T + (1+r)I -> split bf16 + fused Gershgorin ---
// grid (DP rows, NAG), 96 threads: 4 cols each. One block owns one row.
__global__ void build_S(const float* __restrict__ cov) {
    int a = blockIdx.y;
    if (!g_upd[a]) return;
    int i = blockIdx.x;
    int t = threadIdx.x;
    int j0 = t * 4;
    float r = g_r[a];
    float v[4];
    float asum = 0.0f;
    if (i < DIN) {
        int si = srcIdx(i);
        const float* row = cov + (size_t)a * DD + (size_t)si * DIN;
        #pragma unroll
        for (int q = 0; q < 4; q++) {
            int j = j0 + q;
            float x = 0.0f;
            if (j < DIN) {
                x = row[srcIdx(j)];
                if (j == i) x += 1.0f + r;
            }
            v[q] = x;
            asum += fabsf(x);
        }
    } else {
        #pragma unroll
        for (int q = 0; q < 4; q++) v[q] = (j0 + q == i) ? 1.0f : 0.0f;
    }
    uint32_t h0, l0, h1, l1;
    split2(v[0], v[1], h0, l0);
    split2(v[2], v[3], h1, l1);
    size_t off = (size_t)a * DP2 + (size_t)i * DP + j0;
    *(uint2*)(g_Sh + off) = make_uint2(h0, h1);
    *(uint2*)(g_Sl + off) = make_uint2(l0, l1);

    __shared__ float red[3];
    #pragma unroll
    for (int o = 16; o; o >>= 1) asum += __shfl_xor_sync(0xffffffffu, asum, o);
    if ((t & 31) == 0) red[t >> 5] = asum;
    __syncthreads();
    if (t == 0 && i < DIN) g_rowsum[a * DIN + i] = red[0] + red[1] + red[2];
}

__global__ void cmax(void) {
    int a = blockIdx.x;
    if (!g_upd[a]) return;
    int t = threadIdx.x;
    float m = 0.0f;
    for (int i = t; i < DIN; i += 128) m = fmaxf(m, g_rowsum[a * DIN + i]);
    __shared__ float wm[4];
    #pragma unroll
    for (int o = 16; o; o >>= 1) m = fmaxf(m, __shfl_xor_sync(0xffffffffu, m, o));
    if ((t & 31) == 0) wm[t >> 5] = m;
    __syncthreads();
    if (t == 0) {
        float G = fmaxf(fmaxf(wm[0], wm[1]), fmaxf(wm[2], wm[3]));
        g_c[a] = 2.0f / (1.0f + g_r[a] + G * 1.0002f);
    }
}

// X0 = 2c I - c^2 S  -> split bf16 into XA (vectorized, 4 elems/thread)
__global__ void fill_X(void) {
    int a = blockIdx.y;
    if (!g_upd[a]) return;
    int e4 = blockIdx.x * 256 + threadIdx.x;   // < DP2/4 = 36864
    int i = e4 / 96;
    int jj = (e4 - i * 96) * 4;
    float c = g_c[a];
    size_t off = (size_t)a * DP2 + (size_t)i * DP + jj;
    uint2 sh = *(const uint2*)(g_Sh + off);
    uint2 sl = *(const uint2*)(g_Sl + off);
    float2 h0 = bf2f(sh.x), h1 = bf2f(sh.y);
    float2 l0 = bf2f(sl.x), l1 = bf2f(sl.y);
    float s0 = h0.x + l0.x, s1 = h0.y + l0.y, s2 = h1.x + l1.x, s3 = h1.y + l1.y;
    float c2 = c * c;
    float v0 = ((i == jj)     ? 2.0f * c : 0.0f) - c2 * s0;
    float v1 = ((i == jj + 1) ? 2.0f * c : 0.0f) - c2 * s1;
    float v2 = ((i == jj + 2) ? 2.0f * c : 0.0f) - c2 * s2;
    float v3 = ((i == jj + 3) ? 2.0f * c : 0.0f) - c2 * s3;
    uint32_t a0, b0, a1, b1;
    split2(v0, v1, a0, b0);
    split2(v2, v3, a1, b1);
    *(uint2*)(g_XAh + off) = make_uint2(a0, a1);
    *(uint2*)(g_XAl + off) = make_uint2(b0, b1);
}

// ================= pipelined mma.sync bf16 GEMM (symmetric, 6 tiles) =====
#define LDT 72
#define TILE_E (128 * LDT)
#define LDC 129
#define SMB (2 * 2 * TILE_E * 2)   // 2 stages x (A,B) tiles x bf16 = 73728

__device__ __forceinline__ void ldm_x4(uint32_t* r, uint32_t addr) {
    asm volatile("ldmatrix.sync.aligned.m8n8.x4.shared.b16 {%0,%1,%2,%3}, [%4];"
                 : "=r"(r[0]), "=r"(r[1]), "=r"(r[2]), "=r"(r[3]) : "r"(addr));
}
__device__ __forceinline__ void mma_bf16(float* d, const uint32_t* a, const uint32_t* b) {
    asm volatile(
        "mma.sync.aligned.m16n8k16.row.col.f32.bf16.bf16.f32 "
        "{%0,%1,%2,%3}, {%4,%5,%6,%7}, {%8,%9}, {%0,%1,%2,%3};"
        : "+f"(d[0]), "+f"(d[1]), "+f"(d[2]), "+f"(d[3])
        : "r"(a[0]), "r"(a[1]), "r"(a[2]), "r"(a[3]), "r"(b[0]), "r"(b[1]));
}

// copy one 128x64 bf16 panel global -> SMEM tile via cp.async (16B chunks)
__device__ __forceinline__ void stage_async(const __nv_bfloat16* __restrict__ g,
                                            int row0, int k0, uint32_t dst_base,
                                            int tid) {
    const __nv_bfloat16* src0 = g + (size_t)row0 * DP + k0;
    #pragma unroll
    for (int i = 0; i < 4; i++) {
        int id = i * 256 + tid;
        int row = id >> 3, part = id & 7;
        uint32_t dst = dst_base + (uint32_t)(row * LDT + part * 8) * 2;
        const void* src = src0 + (size_t)row * DP + part * 8;
        asm volatile("cp.async.cg.shared.global [%0], [%1], 16;"
                     :: "r"(dst), "l"(src));
    }
}

// NPP=1: plain bf16 (hi*hi, 6 steps). NPP=3: split (hi*hi,hi*lo,lo*hi; 18 steps).
// MODE=0: C = A*B. MODE=1: C = 2X - A*B (X hi, +lo when NPP==3).
// WRITELO: also write C lo plane. FINAL: write r*I - r^2*C to outp (fp32) and
// C hi+lo planes (for the mean matvec). 6 of 9 tiles; off-diag write transpose.
template<int NPP, int MODE, int WRITELO, int FINAL>
__global__ __launch_bounds__(256, 2)
void gemm_mma(int sA, int sB, int sX, int sC, float* outp) {
    int z = blockIdx.z;
    if (!g_upd[z]) return;

    const int bi_map[6] = {0, 1, 2, 0, 0, 1};
    const int bj_map[6] = {0, 1, 2, 1, 2, 2};
    int bi = bi_map[blockIdx.x], bj = bj_map[blockIdx.x];
    int m0 = bi * 128, n0 = bj * 128;
    bool offd = (bi != bj);

    size_t zo = (size_t)z * DP2;
    const __nv_bfloat16* AH = selH(sA) + zo;
    const __nv_bfloat16* AL = selL(sA) + zo;
    const __nv_bfloat16* BH = selH(sB) + zo;
    const __nv_bfloat16* BL = selL(sB) + zo;
    const __nv_bfloat16* XH = selH(sX) + zo;
    const __nv_bfloat16* XL = selL(sX) + zo;
    __nv_bfloat16* CH = selH(sC) + zo;
    __nv_bfloat16* CL = selL(sC) + zo;

    extern __shared__ __align__(16) __nv_bfloat16 sm[];
    float* Cs = reinterpret_cast<float*>(sm);
    uint32_t sbase = smem_u32(sm);

    int tid = threadIdx.x, wid = tid >> 5, lane = tid & 31;
    int wm = (wid & 1) * 64, wn = (wid >> 1) * 32;

    float acc[4][4][4];
    #pragma unroll
    for (int i = 0; i < 4; i++)
        #pragma unroll
        for (int j = 0; j < 4; j++)
            #pragma unroll
            for (int q = 0; q < 4; q++) acc[i][j][q] = 0.0f;

    int lt = lane >> 3, lr = lane & 7;
    int a_row = (lt & 1) * 8 + lr;
    int a_col = (lt >> 1) * 8;
    int b_row = (lt >> 1) * 8 + lr;
    int b_col = (lt & 1) * 8;

    const int NSTEP = 6 * NPP;

    auto do_stage = [&](int s, int b) {
        int kc = s / NPP, p = s - kc * NPP;
        const __nv_bfloat16* Apan = (NPP == 3 && p == 2) ? AL : AH;
        const __nv_bfloat16* Bpan = (NPP == 3 && p == 1) ? BL : BH;
        uint32_t base = sbase + (uint32_t)b * (2 * TILE_E * 2);
        stage_async(Apan, m0, kc * 64, base, tid);
        stage_async(Bpan, n0, kc * 64, base + TILE_E * 2, tid);
    };

    do_stage(0, 0);
    asm volatile("cp.async.commit_group;");

    for (int s = 0; s < NSTEP; s++) {
        int cur = s & 1;
        if (s + 1 < NSTEP) {
            do_stage(s + 1, cur ^ 1);
            asm volatile("cp.async.commit_group;");
            asm volatile("cp.async.wait_group 1;");
        } else {
            asm volatile("cp.async.wait_group 0;");
        }
        __syncthreads();

        const __nv_bfloat16* At = sm + cur * (2 * TILE_E);
        const __nv_bfloat16* Bt = At + TILE_E;
        #pragma unroll
        for (int ks = 0; ks < 4; ks++) {
            int kk = ks * 16;
            uint32_t af[4][4], bf[4][2];
            #pragma unroll
            for (int mt = 0; mt < 4; mt++)
                ldm_x4(af[mt], smem_u32(&At[(wm + mt * 16 + a_row) * LDT + kk + a_col]));
            #pragma unroll
            for (int np = 0; np < 2; np++) {
                uint32_t r[4];
                ldm_x4(r, smem_u32(&Bt[(wn + np * 16 + b_row) * LDT + kk + b_col]));
                bf[np * 2][0] = r[0]; bf[np * 2][1] = r[1];
                bf[np * 2 + 1][0] = r[2]; bf[np * 2 + 1][1] = r[3];
            }
            #pragma unroll
            for (int mt = 0; mt < 4; mt++)
                #pragma unroll
                for (int nt = 0; nt < 4; nt++)
                    mma_bf16(acc[mt][nt], af[mt], bf[nt]);
        }
        __syncthreads();
    }

    // ---- epilogue ----
    float r = g_r[z];
    float rr = -r * r;
    #pragma unroll
    for (int mt = 0; mt < 4; mt++) {
        int rl0 = wm + mt * 16 + (lane >> 2);
        #pragma unroll
        for (int nt = 0; nt < 4; nt++) {
            int cl0 = wn + nt * 8 + 2 * (lane & 3);
            float v00 = acc[mt][nt][0], v01 = acc[mt][nt][1];
            float v10 = acc[mt][nt][2], v11 = acc[mt][nt][3];
            size_t g0 = (size_t)(m0 + rl0) * DP + n0 + cl0;
            size_t g1 = g0 + 8 * DP;
            if (MODE == 1) {
                float2 xh0 = bf2f(*(const uint32_t*)(XH + g0));
                float2 xh1 = bf2f(*(const uint32_t*)(XH + g1));
                float x00 = xh0.x, x01 = xh0.y, x10 = xh1.x, x11 = xh1.y;
                if (NPP == 3) {
                    float2 xl0 = bf2f(*(const uint32_t*)(XL + g0));
                    float2 xl1 = bf2f(*(const uint32_t*)(XL + g1));
                    x00 += xl0.x; x01 += xl0.y; x10 += xl1.x; x11 += xl1.y;
                }
                v00 = 2.0f * x00 - v00; v01 = 2.0f * x01 - v01;
                v10 = 2.0f * x10 - v10; v11 = 2.0f * x11 - v11;
            }
            uint32_t h, l;
            split2(v00, v01, h, l);
            *(uint32_t*)(CH + g0) = h;
            if (WRITELO || FINAL) *(uint32_t*)(CL + g0) = l;
            split2(v10, v11, h, l);
            *(uint32_t*)(CH + g1) = h;
            if (WRITELO || FINAL) *(uint32_t*)(CL + g1) = l;
            if (FINAL) {
                int gi0 = m0 + rl0, gj = n0 + cl0;
                if (gj < DIN) {
                    if (gi0 < DIN) {
                        float2 o;
                        o.x = rr * v00 + ((gi0 == gj) ? r : 0.0f);
                        o.y = rr * v01 + ((gi0 == gj + 1) ? r : 0.0f);
                        *(float2*)(outp + (size_t)z * DD + (size_t)gi0 * DIN + gj) = o;
                    }
                    int gi1 = gi0 + 8;
                    if (gi1 < DIN) {
                        float2 o;
                        o.x = rr * v10 + ((gi1 == gj) ? r : 0.0f);
                        o.y = rr * v11 + ((gi1 == gj + 1) ? r : 0.0f);
                        *(float2*)(outp + (size_t)z * DD + (size_t)gi1 * DIN + gj) = o;
                    }
                }
            }
            if (offd) {
                Cs[rl0 * LDC + cl0] = v00;
                Cs[rl0 * LDC + cl0 + 1] = v01;
                Cs[(rl0 + 8) * LDC + cl0] = v10;
                Cs[(rl0 + 8) * LDC + cl0 + 1] = v11;
            }
        }
    }

    if (offd) {
        __syncthreads();
        #pragma unroll
        for (int it = 0; it < 32; it++) {
            int p = it * 256 + tid;
            int cc = p >> 6, mp = (p & 63) * 2;
            float v0 = Cs[mp * LDC + cc];
            float v1 = Cs[(mp + 1) * LDC + cc];
            size_t g = (size_t)(n0 + cc) * DP + m0 + mp;
            uint32_t h, l;
            split2(v0, v1, h, l);
            *(uint32_t*)(CH + g) = h;
            if (WRITELO || FINAL) *(uint32_t*)(CL + g) = l;
            if (FINAL) {
                int gi = n0 + cc, gj = m0 + mp;
                if (gi < DIN && gj < DIN) {
                    float2 o;
                    o.x = rr * v0;
                    o.y = rr * v1;
                    *(float2*)(outp + (size_t)z * DD + (size_t)gi * DIN + gj) = o;
                }
            }
        }
    }
}

// ---------------- outputs ----------------
#define OUT_MEAN 0
#define OUT_COV  (NAG * DIN)
#define OUT_INIT (NAG * DIN + NAG * DD)

// cov output for NON-update agents only (update agents written by FINAL GEMM)
__global__ void finalize_cov_rest(const float* __restrict__ cov,
                                  float* __restrict__ out) {
    int a = blockIdx.y;
    if (g_upd[a]) return;
    int e4 = blockIdx.x * blockDim.x + threadIdx.x;
    if (e4 >= DD / 4) return;
    int i = e4 / 90;
    int jj = (e4 - i * 90) * 4;
    float4 o = *(const float4*)(cov + (size_t)a * DD + (size_t)i * DIN + jj);
    if (g_initnew[a]) {
        if (i >= jj && i < jj + 4) (&o.x)[i - jj] += g_r[a];
    }
    *(float4*)(out + OUT_COV + (size_t)a * DD + (size_t)i * DIN + jj) = o;
}

__global__ void finalize_mean(const float* __restrict__ mean_in,
                              const float* __restrict__ obs,
                              float* __restrict__ out, int sinv) {
    int a = blockIdx.x;
    int tid = threadIdx.x;
    __shared__ float v[DIN];

    if (tid == 0) out[OUT_INIT + a] = g_initout[a] ? 1.0f : 0.0f;

    const float* m = mean_in + (size_t)a * DIN;
    const float* o = obs + (size_t)a * DIN;
    float* om = out + OUT_MEAN + (size_t)a * DIN;

    if (g_initnew[a]) {
        for (int i = tid; i < DIN; i += blockDim.x) om[i] = o[i];
    } else if (g_upd[a]) {
        float r = g_r[a];
        const __nv_bfloat16* Xh = selH(sinv) + (size_t)a * DP2;
        const __nv_bfloat16* Xl = selL(sinv) + (size_t)a * DP2;
        for (int j = tid; j < DIN; j += blockDim.x) v[j] = o[j] - m[srcIdx(j)];
        __syncthreads();
        int warp = tid >> 5, lane = tid & 31;
        for (int i = warp; i < DIN; i += 8) {
            float s = 0.0f;
            size_t row = (size_t)i * DP;
            for (int j = lane; j < DIN; j += 32)
                s += (__bfloat162float(Xh[row + j]) + __bfloat162float(Xl[row + j])) * v[j];
            #pragma unroll
            for (int off = 16; off; off >>= 1) s += __shfl_xor_sync(0xffffffffu, s, off);
            if (lane == 0) om[i] = o[i] - r * s;
        }
    } else {
        for (int i = tid; i < DIN; i += blockDim.x) om[i] = m[i];
    }
}

// ---------------- launch ----------------
extern "C" void kernel_launch(void* const* d_in, const int* in_sizes, int n_in,
                              void* d_out, int out_size) {
    const float* mean = (const float*)d_in[0];
    const float* cov  = (const float*)d_in[1];
    const float* obs  = (const float*)d_in[2];
    const float* rs   = (const float*)d_in[3];
    const void*  ini  = d_in[4];
    const void*  sel  = d_in[5];
    float* out = (float*)d_out;

    cudaFuncSetAttribute(gemm_mma<1,0,0,0>, cudaFuncAttributeMaxDynamicSharedMemorySize, SMB);
    cudaFuncSetAttribute(gemm_mma<1,1,0,0>, cudaFuncAttributeMaxDynamicSharedMemorySize, SMB);
    cudaFuncSetAttribute(gemm_mma<1,1,1,0>, cudaFuncAttributeMaxDynamicSharedMemorySize, SMB);
    cudaFuncSetAttribute(gemm_mma<3,0,1,0>, cudaFuncAttributeMaxDynamicSharedMemorySize, SMB);
    cudaFuncSetAttribute(gemm_mma<3,1,1,0>, cudaFuncAttributeMaxDynamicSharedMemorySize, SMB);
    cudaFuncSetAttribute(gemm_mma<3,1,0,1>, cudaFuncAttributeMaxDynamicSharedMemorySize, SMB);

    prep_flags<<<1, 64>>>(rs, ini, sel);
    build_S<<<dim3(DP, NAG), 96>>>(cov);
    cmax<<<NAG, 128>>>();
    fill_X<<<dim3(144, NAG), 256>>>();

    dim3 g6(6, 1, NAG);
    // buffers: 0=S, 1=XA, 2=XB, 3=Y
    // plain iter 1
    gemm_mma<1,0,0,0><<<g6, 256, SMB>>>(0, 1, 0, 3, nullptr);  // Y  = S*XA   (hi)
    gemm_mma<1,1,0,0><<<g6, 256, SMB>>>(1, 3, 1, 2, nullptr);  // XB = 2XA-XA*Y (hi)
    // plain iter 2
    gemm_mma<1,0,0,0><<<g6, 256, SMB>>>(0, 2, 0, 3, nullptr);  // Y  = S*XB   (hi)
    gemm_mma<1,1,1,0><<<g6, 256, SMB>>>(2, 3, 2, 1, nullptr);  // XA = 2XB-XB*Y (hi+lo)
    // split iter 3
    gemm_mma<3,0,1,0><<<g6, 256, SMB>>>(0, 1, 0, 3, nullptr);  // Y  = S*XA   (hi+lo)
    gemm_mma<3,1,1,0><<<g6, 256, SMB>>>(1, 3, 1, 2, nullptr);  // XB = 2XA-XA*Y (hi+lo)
    // split iter 4 + fused cov output
    gemm_mma<3,0,1,0><<<g6, 256, SMB>>>(0, 2, 0, 3, nullptr);  // Y  = S*XB   (hi+lo)
    gemm_mma<3,1,0,1><<<g6, 256, SMB>>>(2, 3, 2, 1, out + OUT_COV); // XA + cov out

    finalize_cov_rest<<<dim3((DD / 4 + 255) / 256, NAG), 256>>>(cov, out);
    finalize_mean<<<NAG, 256>>>(mean, obs, out, 1);
}

// round 7
// speedup vs baseline: 1.3343x; 1.1375x over previous
#include <cuda_runtime.h>
#include <cuda_bf16.h>
#include <cstdint>
#include <cstddef>

// ---------------- problem constants ----------------
#define NAG 64           // B*A
#define DIN 360          // logical dim
#define DD  (DIN*DIN)
#define MODE_LEN 60
#define DP  384          // padded dim (3 x 128)
#define DP2 (DP*DP)

// ---------------- scratch: bf16 hi/lo pairs ----------------
__device__ __align__(128) __nv_bfloat16 g_Sh [(size_t)NAG*DP2];
__device__ __align__(128) __nv_bfloat16 g_Sl [(size_t)NAG*DP2];
__device__ __align__(128) __nv_bfloat16 g_XAh[(size_t)NAG*DP2];
__device__ __align__(128) __nv_bfloat16 g_XAl[(size_t)NAG*DP2];
__device__ __align__(128) __nv_bfloat16 g_XBh[(size_t)NAG*DP2];
__device__ __align__(128) __nv_bfloat16 g_XBl[(size_t)NAG*DP2];
__device__ __align__(128) __nv_bfloat16 g_Yh [(size_t)NAG*DP2];
__device__ __align__(128) __nv_bfloat16 g_Yl [(size_t)NAG*DP2];
__device__ float g_rowsum[NAG * DIN];
__device__ float g_r[NAG];
__device__ float g_c[NAG];
__device__ int   g_upd[NAG];
__device__ int   g_initnew[NAG];
__device__ int   g_initout[NAG];

__device__ __forceinline__ __nv_bfloat16* selH(int s) {
    switch (s) {
        case 0:  return g_Sh;
        case 1:  return g_XAh;
        case 2:  return g_XBh;
        default: return g_Yh;
    }
}
__device__ __forceinline__ __nv_bfloat16* selL(int s) {
    switch (s) {
        case 0:  return g_Sl;
        case 1:  return g_XAl;
        case 2:  return g_XBl;
        default: return g_Yl;
    }
}

__device__ __forceinline__ int srcIdx(int g) {
    int l = g % MODE_LEN;
    return (l < MODE_LEN - 2) ? (g + 2) : g;
}

// ---------------- small helpers ----------------
__device__ __forceinline__ uint32_t smem_u32(const void* p) {
    uint32_t a;
    asm("{ .reg .u64 t; cvta.to.shared.u64 t, %1; cvt.u32.u64 %0, t; }"
        : "=r"(a) : "l"(p));
    return a;
}
__device__ __forceinline__ uint32_t pack_bf2(float x, float y) {
    __nv_bfloat162 t = __floats2bfloat162_rn(x, y);
    return *reinterpret_cast<uint32_t*>(&t);
}
__device__ __forceinline__ float2 bf2f(uint32_t u) {
    __nv_bfloat162 t = *reinterpret_cast<__nv_bfloat162*>(&u);
    return make_float2(__bfloat162float(t.x), __bfloat162float(t.y));
}
__device__ __forceinline__ void split2(float a, float b, uint32_t& h, uint32_t& l) {
    __nv_bfloat16 ah = __float2bfloat16_rn(a), bh = __float2bfloat16_rn(b);
    float ar = a - __bfloat162float(ah), br = b - __bfloat162float(bh);
    __nv_bfloat162 t; t.x = ah; t.y = bh;
    h = *reinterpret_cast<uint32_t*>(&t);
    l = pack_bf2(ar, br);
}

// ---------------- flag dtype sniffing (validated round 2) ----------------
__device__ int detect_mode(const unsigned char* p) {
    int n_off = 0, n_3f = 0;
    for (int t = 0; t < 64; t++) {
        unsigned char b = p[t];
        if ((t & 3) && b) n_off++;
        if (((t & 3) == 3) && b == 0x3F) n_3f++;
    }
    if (n_off == 0) return 1;
    if (n_3f > 0)  return 2;
    return 0;
}
__device__ __forceinline__ bool read_flag(const void* p, int t, int mode) {
    if (mode == 1) return ((const int*)p)[t] != 0;
    if (mode == 2) return ((const float*)p)[t] != 0.0f;
    return ((const unsigned char*)p)[t] != 0;
}

__global__ void prep_flags(const float* __restrict__ rs,
                           const void* __restrict__ ini,
                           const void* __restrict__ sel) {
    __shared__ int mode_i, mode_s;
    if (threadIdx.x == 0) {
        mode_i = detect_mode((const unsigned char*)ini);
        mode_s = detect_mode((const unsigned char*)sel);
    }
    __syncthreads();
    int t = threadIdx.x;
    if (t >= NAG) return;
    float r = rs[t] + 1.0f;
    bool i8 = read_flag(ini, t, mode_i);
    bool s8 = read_flag(sel, t, mode_s);
    g_r[t] = r;
    g_upd[t] = (s8 && i8);
    g_initnew[t] = (s8 && !i8);
    g_initout[t] = (s8 || i8);
}

// ---------------- S = A P A^T + (1+r)I -> split bf16 + fused Gershgorin ---
__global__ void build_S(const float* __restrict__ cov) {
    int a = blockIdx.y;
    if (!g_upd[a]) return;
    int i = blockIdx.x;
    int t = threadIdx.x;
    int j0 = t * 4;
    float r = g_r[a];
    float v[4];
    float asum = 0.0f;
    if (i < DIN) {
        int si = srcIdx(i);
        const float* row = cov + (size_t)a * DD + (size_t)si * DIN;
        #pragma unroll
        for (int q = 0; q < 4; q++) {
            int j = j0 + q;
            float x = 0.0f;
            if (j < DIN) {
                x = row[srcIdx(j)];
                if (j == i) x += 1.0f + r;
            }
            v[q] = x;
            asum += fabsf(x);
        }
    } else {
        #pragma unroll
        for (int q = 0; q < 4; q++) v[q] = (j0 + q == i) ? 1.0f : 0.0f;
    }
    uint32_t h0, l0, h1, l1;
    split2(v[0], v[1], h0, l0);
    split2(v[2], v[3], h1, l1);
    size_t off = (size_t)a * DP2 + (size_t)i * DP + j0;
    *(uint2*)(g_Sh + off) = make_uint2(h0, h1);
    *(uint2*)(g_Sl + off) = make_uint2(l0, l1);

    __shared__ float red[3];
    #pragma unroll
    for (int o = 16; o; o >>= 1) asum += __shfl_xor_sync(0xffffffffu, asum, o);
    if ((t & 31) == 0) red[t >> 5] = asum;
    __syncthreads();
    if (t == 0 && i < DIN) g_rowsum[a * DIN + i] = red[0] + red[1] + red[2];
}

__global__ void cmax(void) {
    int a = blockIdx.x;
    if (!g_upd[a]) return;
    int t = threadIdx.x;
    float m = 0.0f;
    for (int i = t; i < DIN; i += 128) m = fmaxf(m, g_rowsum[a * DIN + i]);
    __shared__ float wm[4];
    #pragma unroll
    for (int o = 16; o; o >>= 1) m = fmaxf(m, __shfl_xor_sync(0xffffffffu, m, o));
    if ((t & 31) == 0) wm[t >> 5] = m;
    __syncthreads();
    if (t == 0) {
        float G = fmaxf(fmaxf(wm[0], wm[1]), fmaxf(wm[2], wm[3]));
        g_c[a] = 2.0f / (1.0f + g_r[a] + G * 1.0002f);
    }
}

// X0 = 2c I - c^2 S  -> split bf16 into XA
__global__ void fill_X(void) {
    int a = blockIdx.y;
    if (!g_upd[a]) return;
    int e4 = blockIdx.x * 256 + threadIdx.x;   // < DP2/4 = 36864
    int i = e4 / 96;
    int jj = (e4 - i * 96) * 4;
    float c = g_c[a];
    size_t off = (size_t)a * DP2 + (size_t)i * DP + jj;
    uint2 sh = *(const uint2*)(g_Sh + off);
    uint2 sl = *(const uint2*)(g_Sl + off);
    float2 h0 = bf2f(sh.x), h1 = bf2f(sh.y);
    float2 l0 = bf2f(sl.x), l1 = bf2f(sl.y);
    float s0 = h0.x + l0.x, s1 = h0.y + l0.y, s2 = h1.x + l1.x, s3 = h1.y + l1.y;
    float c2 = c * c;
    float v0 = ((i == jj)     ? 2.0f * c : 0.0f) - c2 * s0;
    float v1 = ((i == jj + 1) ? 2.0f * c : 0.0f) - c2 * s1;
    float v2 = ((i == jj + 2) ? 2.0f * c : 0.0f) - c2 * s2;
    float v3 = ((i == jj + 3) ? 2.0f * c : 0.0f) - c2 * s3;
    uint32_t a0, b0, a1, b1;
    split2(v0, v1, a0, b0);
    split2(v2, v3, a1, b1);
    *(uint2*)(g_XAh + off) = make_uint2(a0, a1);
    *(uint2*)(g_XAl + off) = make_uint2(b0, b1);
}

// ================= pipelined mma.sync bf16 GEMM (symmetric, 6 tiles) =====
// k-chunk 32, LDT=40 halves (80B rows: ldmatrix conflict-free).
#define LDT 40
#define PANEL_E (128 * LDT)          // 5120 bf16
#define PANEL_B (PANEL_E * 2)        // 10240 bytes
#define LDC 129
#define CS_BYTES (128 * LDC * 4)     // 66048

__device__ __forceinline__ void ldm_x4(uint32_t* r, uint32_t addr) {
    asm volatile("ldmatrix.sync.aligned.m8n8.x4.shared.b16 {%0,%1,%2,%3}, [%4];"
                 : "=r"(r[0]), "=r"(r[1]), "=r"(r[2]), "=r"(r[3]) : "r"(addr));
}
__device__ __forceinline__ void mma_bf16(float* d, const uint32_t* a, const uint32_t* b) {
    asm volatile(
        "mma.sync.aligned.m16n8k16.row.col.f32.bf16.bf16.f32 "
        "{%0,%1,%2,%3}, {%4,%5,%6,%7}, {%8,%9}, {%0,%1,%2,%3};"
        : "+f"(d[0]), "+f"(d[1]), "+f"(d[2]), "+f"(d[3])
        : "r"(a[0]), "r"(a[1]), "r"(a[2]), "r"(a[3]), "r"(b[0]), "r"(b[1]));
}

// stage one 128x32 bf16 panel global -> SMEM (2 x 16B per thread)
__device__ __forceinline__ void stage32(const __nv_bfloat16* __restrict__ g,
                                        int row0, int k0, uint32_t dst, int tid) {
    const __nv_bfloat16* src0 = g + (size_t)row0 * DP + k0;
    #pragma unroll
    for (int i = 0; i < 2; i++) {
        int id = i * 256 + tid;
        int row = id >> 2, part = id & 3;
        uint32_t d = dst + (uint32_t)(row * LDT + part * 8) * 2;
        const void* s = src0 + (size_t)row * DP + part * 8;
        asm volatile("cp.async.cg.shared.global [%0], [%1], 16;"
                     :: "r"(d), "l"(s));
    }
}

// SPLIT=0: hi*hi. SPLIT=1: 4 panels staged once, 3 passes (hh, hl, lh).
// MODE=0: C=A*B. MODE=1: C=2X-A*B. MODE=2: C=3I-3X+A*B (cubic T, X:=Y).
// WRITELO: write C lo plane. FINAL: also write r*I - r^2*C to outp (fp32).
template<int SPLIT, int MODE, int WRITELO, int FINAL>
__global__ __launch_bounds__(256, 2)
void gemm_mma(int sA, int sB, int sX, int sC, float* outp) {
    int z = blockIdx.z;
    if (!g_upd[z]) return;

    const int bi_map[6] = {0, 1, 2, 0, 0, 1};
    const int bj_map[6] = {0, 1, 2, 1, 2, 2};
    int bi = bi_map[blockIdx.x], bj = bj_map[blockIdx.x];
    int m0 = bi * 128, n0 = bj * 128;
    bool offd = (bi != bj);

    size_t zo = (size_t)z * DP2;
    const __nv_bfloat16* AH = selH(sA) + zo;
    const __nv_bfloat16* AL = selL(sA) + zo;
    const __nv_bfloat16* BH = selH(sB) + zo;
    const __nv_bfloat16* BL = selL(sB) + zo;
    const __nv_bfloat16* XH = selH(sX) + zo;
    const __nv_bfloat16* XL = selL(sX) + zo;
    __nv_bfloat16* CH = selH(sC) + zo;
    __nv_bfloat16* CL = selL(sC) + zo;

    extern __shared__ __align__(16) __nv_bfloat16 sm[];
    float* Cs = reinterpret_cast<float*>(sm);
    uint32_t sbase = smem_u32(sm);

    int tid = threadIdx.x, wid = tid >> 5, lane = tid & 31;
    int wm = (wid & 1) * 64, wn = (wid >> 1) * 32;

    float acc[4][4][4];
    #pragma unroll
    for (int i = 0; i < 4; i++)
        #pragma unroll
        for (int j = 0; j < 4; j++)
            #pragma unroll
            for (int q = 0; q < 4; q++) acc[i][j][q] = 0.0f;

    int lt = lane >> 3, lr = lane & 7;
    int a_row = (lt & 1) * 8 + lr;
    int a_col = (lt >> 1) * 8;
    int b_row = (lt >> 1) * 8 + lr;
    int b_col = (lt & 1) * 8;

    const int NP = SPLIT ? 4 : 2;
    const uint32_t STAGE_B = (uint32_t)NP * PANEL_B;

    auto do_stage = [&](int kc, int b) {
        uint32_t base = sbase + (uint32_t)b * STAGE_B;
        int k0 = kc * 32;
        stage32(AH, m0, k0, base, tid);
        stage32(BH, n0, k0, base + PANEL_B, tid);
        if (SPLIT) {
            stage32(AL, m0, k0, base + 2 * PANEL_B, tid);
            stage32(BL, n0, k0, base + 3 * PANEL_B, tid);
        }
    };

    do_stage(0, 0);
    asm volatile("cp.async.commit_group;");

    for (int kc = 0; kc < 12; kc++) {
        int cur = kc & 1;
        if (kc + 1 < 12) {
            do_stage(kc + 1, cur ^ 1);
            asm volatile("cp.async.commit_group;");
            asm volatile("cp.async.wait_group 1;");
        } else {
            asm volatile("cp.async.wait_group 0;");
        }
        __syncthreads();

        const __nv_bfloat16* At  = sm + (size_t)cur * NP * PANEL_E;
        const __nv_bfloat16* Bt  = At + PANEL_E;
        const __nv_bfloat16* Alt = At + 2 * PANEL_E;
        const __nv_bfloat16* Blt = At + 3 * PANEL_E;

        #pragma unroll
        for (int ks = 0; ks < 2; ks++) {
            int kk = ks * 16;
            uint32_t ah[4][4], bh[4][2];
            #pragma unroll
            for (int mt = 0; mt < 4; mt++)
                ldm_x4(ah[mt], smem_u32(&At[(wm + mt * 16 + a_row) * LDT + kk + a_col]));
            #pragma unroll
            for (int np = 0; np < 2; np++) {
                uint32_t r[4];
                ldm_x4(r, smem_u32(&Bt[(wn + np * 16 + b_row) * LDT + kk + b_col]));
                bh[np * 2][0] = r[0]; bh[np * 2][1] = r[1];
                bh[np * 2 + 1][0] = r[2]; bh[np * 2 + 1][1] = r[3];
            }
            #pragma unroll
            for (int mt = 0; mt < 4; mt++)
                #pragma unroll
                for (int nt = 0; nt < 4; nt++)
                    mma_bf16(acc[mt][nt], ah[mt], bh[nt]);

            if (SPLIT) {
                // hi*lo: ah x bl
                uint32_t bl[4][2];
                #pragma unroll
                for (int np = 0; np < 2; np++) {
                    uint32_t r[4];
                    ldm_x4(r, smem_u32(&Blt[(wn + np * 16 + b_row) * LDT + kk + b_col]));
                    bl[np * 2][0] = r[0]; bl[np * 2][1] = r[1];
                    bl[np * 2 + 1][0] = r[2]; bl[np * 2 + 1][1] = r[3];
                }
                #pragma unroll
                for (int mt = 0; mt < 4; mt++)
                    #pragma unroll
                    for (int nt = 0; nt < 4; nt++)
                        mma_bf16(acc[mt][nt], ah[mt], bl[nt]);
                // lo*hi: al x bh (al overwrites ah registers)
                uint32_t al[4][4];
                #pragma unroll
                for (int mt = 0; mt < 4; mt++)
                    ldm_x4(al[mt], smem_u32(&Alt[(wm + mt * 16 + a_row) * LDT + kk + a_col]));
                #pragma unroll
                for (int mt = 0; mt < 4; mt++)
                    #pragma unroll
                    for (int nt = 0; nt < 4; nt++)
                        mma_bf16(acc[mt][nt], al[mt], bh[nt]);
            }
        }
        __syncthreads();
    }

    // ---- epilogue ----
    float r = g_r[z];
    float rr = -r * r;
    #pragma unroll
    for (int mt = 0; mt < 4; mt++) {
        int rl0 = wm + mt * 16 + (lane >> 2);
        #pragma unroll
        for (int nt = 0; nt < 4; nt++) {
            int cl0 = wn + nt * 8 + 2 * (lane & 3);
            float v00 = acc[mt][nt][0], v01 = acc[mt][nt][1];
            float v10 = acc[mt][nt][2], v11 = acc[mt][nt][3];
            size_t g0 = (size_t)(m0 + rl0) * DP + n0 + cl0;
            size_t g1 = g0 + 8 * DP;
            if (MODE != 0) {
                float2 xh0 = bf2f(*(const uint32_t*)(XH + g0));
                float2 xh1 = bf2f(*(const uint32_t*)(XH + g1));
                float x00 = xh0.x, x01 = xh0.y, x10 = xh1.x, x11 = xh1.y;
                if (SPLIT) {
                    float2 xl0 = bf2f(*(const uint32_t*)(XL + g0));
                    float2 xl1 = bf2f(*(const uint32_t*)(XL + g1));
                    x00 += xl0.x; x01 += xl0.y; x10 += xl1.x; x11 += xl1.y;
                }
                if (MODE == 1) {
                    v00 = 2.0f * x00 - v00; v01 = 2.0f * x01 - v01;
                    v10 = 2.0f * x10 - v10; v11 = 2.0f * x11 - v11;
                } else {  // MODE 2: T = 3I - 3Y + acc
                    int gi0 = m0 + rl0, gj = n0 + cl0;
                    v00 = ((gi0 == gj)     ? 3.0f : 0.0f) - 3.0f * x00 + v00;
                    v01 = ((gi0 == gj + 1) ? 3.0f : 0.0f) - 3.0f * x01 + v01;
                    v10 = ((gi0 + 8 == gj)     ? 3.0f : 0.0f) - 3.0f * x10 + v10;
                    v11 = ((gi0 + 8 == gj + 1) ? 3.0f : 0.0f) - 3.0f * x11 + v11;
                }
            }
            uint32_t h, l;
            split2(v00, v01, h, l);
            *(uint32_t*)(CH + g0) = h;
            if (WRITELO || FINAL) *(uint32_t*)(CL + g0) = l;
            split2(v10, v11, h, l);
            *(uint32_t*)(CH + g1) = h;
            if (WRITELO || FINAL) *(uint32_t*)(CL + g1) = l;
            if (FINAL) {
                int gi0 = m0 + rl0, gj = n0 + cl0;
                if (gj < DIN) {
                    if (gi0 < DIN) {
                        float2 o;
                        o.x = rr * v00 + ((gi0 == gj) ? r : 0.0f);
                        o.y = rr * v01 + ((gi0 == gj + 1) ? r : 0.0f);
                        *(float2*)(outp + (size_t)z * DD + (size_t)gi0 * DIN + gj) = o;
                    }
                    int gi1 = gi0 + 8;
                    if (gi1 < DIN) {
                        float2 o;
                        o.x = rr * v10 + ((gi1 == gj) ? r : 0.0f);
                        o.y = rr * v11 + ((gi1 == gj + 1) ? r : 0.0f);
                        *(float2*)(outp + (size_t)z * DD + (size_t)gi1 * DIN + gj) = o;
                    }
                }
            }
            if (offd) {
                Cs[rl0 * LDC + cl0] = v00;
                Cs[rl0 * LDC + cl0 + 1] = v01;
                Cs[(rl0 + 8) * LDC + cl0] = v10;
                Cs[(rl0 + 8) * LDC + cl0 + 1] = v11;
            }
        }
    }

    if (offd) {
        __syncthreads();
        #pragma unroll
        for (int it = 0; it < 32; it++) {
            int p = it * 256 + tid;
            int cc = p >> 6, mp = (p & 63) * 2;
            float v0 = Cs[mp * LDC + cc];
            float v1 = Cs[(mp + 1) * LDC + cc];
            size_t g = (size_t)(n0 + cc) * DP + m0 + mp;
            uint32_t h, l;
            split2(v0, v1, h, l);
            *(uint32_t*)(CH + g) = h;
            if (WRITELO || FINAL) *(uint32_t*)(CL + g) = l;
            if (FINAL) {
                int gi = n0 + cc, gj = m0 + mp;
                if (gi < DIN && gj < DIN) {
                    float2 o;
                    o.x = rr * v0;
                    o.y = rr * v1;
                    *(float2*)(outp + (size_t)z * DD + (size_t)gi * DIN + gj) = o;
                }
            }
        }
    }
}

// ---------------- outputs ----------------
#define OUT_MEAN 0
#define OUT_COV  (NAG * DIN)
#define OUT_INIT (NAG * DIN + NAG * DD)

__global__ void finalize_cov_rest(const float* __restrict__ cov,
                                  float* __restrict__ out) {
    int a = blockIdx.y;
    if (g_upd[a]) return;
    int e4 = blockIdx.x * blockDim.x + threadIdx.x;
    if (e4 >= DD / 4) return;
    int i = e4 / 90;
    int jj = (e4 - i * 90) * 4;
    float4 o = *(const float4*)(cov + (size_t)a * DD + (size_t)i * DIN + jj);
    if (g_initnew[a]) {
        if (i >= jj && i < jj + 4) (&o.x)[i - jj] += g_r[a];
    }
    *(float4*)(out + OUT_COV + (size_t)a * DD + (size_t)i * DIN + jj) = o;
}

__global__ void finalize_mean(const float* __restrict__ mean_in,
                              const float* __restrict__ obs,
                              float* __restrict__ out, int sinv) {
    int a = blockIdx.x;
    int tid = threadIdx.x;
    __shared__ float v[DIN];

    if (tid == 0) out[OUT_INIT + a] = g_initout[a] ? 1.0f : 0.0f;

    const float* m = mean_in + (size_t)a * DIN;
    const float* o = obs + (size_t)a * DIN;
    float* om = out + OUT_MEAN + (size_t)a * DIN;

    if (g_initnew[a]) {
        for (int i = tid; i < DIN; i += blockDim.x) om[i] = o[i];
    } else if (g_upd[a]) {
        float r = g_r[a];
        const __nv_bfloat16* Xh = selH(sinv) + (size_t)a * DP2;
        const __nv_bfloat16* Xl = selL(sinv) + (size_t)a * DP2;
        for (int j = tid; j < DIN; j += blockDim.x) v[j] = o[j] - m[srcIdx(j)];
        __syncthreads();
        int warp = tid >> 5, lane = tid & 31;
        for (int i = warp; i < DIN; i += 8) {
            float s = 0.0f;
            size_t row = (size_t)i * DP;
            for (int j = lane; j < DIN; j += 32)
                s += (__bfloat162float(Xh[row + j]) + __bfloat162float(Xl[row + j])) * v[j];
            #pragma unroll
            for (int off = 16; off; off >>= 1) s += __shfl_xor_sync(0xffffffffu, s, off);
            if (lane == 0) om[i] = o[i] - r * s;
        }
    } else {
        for (int i = tid; i < DIN; i += blockDim.x) om[i] = m[i];
    }
}

// ---------------- launch ----------------
extern "C" void kernel_launch(void* const* d_in, const int* in_sizes, int n_in,
                              void* d_out, int out_size) {
    const float* mean = (const float*)d_in[0];
    const float* cov  = (const float*)d_in[1];
    const float* obs  = (const float*)d_in[2];
    const float* rs   = (const float*)d_in[3];
    const void*  ini  = d_in[4];
    const void*  sel  = d_in[5];
    float* out = (float*)d_out;

    const int SMB_P = (2 * 2 * PANEL_B > CS_BYTES) ? 2 * 2 * PANEL_B : CS_BYTES;  // 66048
    const int SMB_S = (2 * 4 * PANEL_B > CS_BYTES) ? 2 * 4 * PANEL_B : CS_BYTES;  // 81920

    cudaFuncSetAttribute(gemm_mma<0,0,0,0>, cudaFuncAttributeMaxDynamicSharedMemorySize, SMB_P);
    cudaFuncSetAttribute(gemm_mma<0,1,0,0>, cudaFuncAttributeMaxDynamicSharedMemorySize, SMB_P);
    cudaFuncSetAttribute(gemm_mma<0,1,1,0>, cudaFuncAttributeMaxDynamicSharedMemorySize, SMB_P);
    cudaFuncSetAttribute(gemm_mma<1,0,1,0>, cudaFuncAttributeMaxDynamicSharedMemorySize, SMB_S);
    cudaFuncSetAttribute(gemm_mma<1,2,1,0>, cudaFuncAttributeMaxDynamicSharedMemorySize, SMB_S);
    cudaFuncSetAttribute(gemm_mma<1,0,0,1>, cudaFuncAttributeMaxDynamicSharedMemorySize, SMB_S);

    prep_flags<<<1, 64>>>(rs, ini, sel);
    build_S<<<dim3(DP, NAG), 96>>>(cov);
    cmax<<<NAG, 128>>>();
    fill_X<<<dim3(144, NAG), 256>>>();

    dim3 g6(6, 1, NAG);
    // buffers: 0=S, 1=XA, 2=XB, 3=Y
    // plain iter 1
    gemm_mma<0,0,0,0><<<g6, 256, SMB_P>>>(0, 1, 0, 3, nullptr);  // Y  = S*XA   (hi)
    gemm_mma<0,1,0,0><<<g6, 256, SMB_P>>>(1, 3, 1, 2, nullptr);  // XB = 2XA-XA*Y (hi)
    // plain iter 2
    gemm_mma<0,0,0,0><<<g6, 256, SMB_P>>>(0, 2, 0, 3, nullptr);  // Y  = S*XB   (hi)
    gemm_mma<0,1,1,0><<<g6, 256, SMB_P>>>(2, 3, 2, 1, nullptr);  // XA = 2XB-XB*Y (hi+lo)
    // cubic split stage: E -> E^3
    gemm_mma<1,0,1,0><<<g6, 256, SMB_S>>>(0, 1, 0, 3, nullptr);  // Y  = S*XA     (hi+lo)
    gemm_mma<1,2,1,0><<<g6, 256, SMB_S>>>(3, 3, 3, 2, nullptr);  // T  = 3I-3Y+Y*Y -> XB
    gemm_mma<1,0,0,1><<<g6, 256, SMB_S>>>(1, 2, 0, 3, out + OUT_COV); // Xf = XA*T -> Y, +cov

    finalize_cov_rest<<<dim3((DD / 4 + 255) / 256, NAG), 256>>>(cov, out);
    finalize_mean<<<NAG, 256>>>(mean, obs, out, 3);
}

// round 9
// speedup vs baseline: 1.4667x; 1.0992x over previous
#include <cuda_runtime.h>
#include <cuda_bf16.h>
#include <cstdint>
#include <cstddef>

// ---------------- problem constants ----------------
#define NAG 64           // B*A
#define DIN 360          // logical dim
#define DD  (DIN*DIN)
#define MODE_LEN 60
#define DP  384          // padded dim (3 x 128)
#define DP2 (DP*DP)

// ---------------- scratch: bf16 hi/lo pairs ----------------
__device__ __align__(128) __nv_bfloat16 g_Sh [(size_t)NAG*DP2];
__device__ __align__(128) __nv_bfloat16 g_Sl [(size_t)NAG*DP2];
__device__ __align__(128) __nv_bfloat16 g_XAh[(size_t)NAG*DP2];
__device__ __align__(128) __nv_bfloat16 g_XAl[(size_t)NAG*DP2];
__device__ __align__(128) __nv_bfloat16 g_XBh[(size_t)NAG*DP2];
__device__ __align__(128) __nv_bfloat16 g_XBl[(size_t)NAG*DP2];
__device__ __align__(128) __nv_bfloat16 g_Yh [(size_t)NAG*DP2];
__device__ __align__(128) __nv_bfloat16 g_Yl [(size_t)NAG*DP2];
__device__ float g_rowsum[NAG * DIN];
__device__ float g_r[NAG];
__device__ float g_c[NAG];
__device__ int   g_upd[NAG];
__device__ int   g_initnew[NAG];
__device__ int   g_initout[NAG];

__device__ __forceinline__ __nv_bfloat16* selH(int s) {
    switch (s) {
        case 0:  return g_Sh;
        case 1:  return g_XAh;
        case 2:  return g_XBh;
        default: return g_Yh;
    }
}
__device__ __forceinline__ __nv_bfloat16* selL(int s) {
    switch (s) {
        case 0:  return g_Sl;
        case 1:  return g_XAl;
        case 2:  return g_XBl;
        default: return g_Yl;
    }
}

__device__ __forceinline__ int srcIdx(int g) {
    int l = g % MODE_LEN;
    return (l < MODE_LEN - 2) ? (g + 2) : g;
}

// ---------------- small helpers ----------------
__device__ __forceinline__ uint32_t smem_u32(const void* p) {
    uint32_t a;
    asm("{ .reg .u64 t; cvta.to.shared.u64 t, %1; cvt.u32.u64 %0, t; }"
        : "=r"(a) : "l"(p));
    return a;
}
__device__ __forceinline__ uint32_t pack_bf2(float x, float y) {
    __nv_bfloat162 t = __floats2bfloat162_rn(x, y);
    return *reinterpret_cast<uint32_t*>(&t);
}
__device__ __forceinline__ float2 bf2f(uint32_t u) {
    __nv_bfloat162 t = *reinterpret_cast<__nv_bfloat162*>(&u);
    return make_float2(__bfloat162float(t.x), __bfloat162float(t.y));
}
__device__ __forceinline__ void split2(float a, float b, uint32_t& h, uint32_t& l) {
    __nv_bfloat16 ah = __float2bfloat16_rn(a), bh = __float2bfloat16_rn(b);
    float ar = a - __bfloat162float(ah), br = b - __bfloat162float(bh);
    __nv_bfloat162 t; t.x = ah; t.y = bh;
    h = *reinterpret_cast<uint32_t*>(&t);
    l = pack_bf2(ar, br);
}

// ---------------- flag dtype sniffing (validated round 2) ----------------
__device__ int detect_mode(const unsigned char* p) {
    int n_off = 0, n_3f = 0;
    for (int t = 0; t < 64; t++) {
        unsigned char b = p[t];
        if ((t & 3) && b) n_off++;
        if (((t & 3) == 3) && b == 0x3F) n_3f++;
    }
    if (n_off == 0) return 1;
    if (n_3f > 0)  return 2;
    return 0;
}
__device__ __forceinline__ bool read_flag(const void* p, int t, int mode) {
    if (mode == 1) return ((const int*)p)[t] != 0;
    if (mode == 2) return ((const float*)p)[t] != 0.0f;
    return ((const unsigned char*)p)[t] != 0;
}

__global__ void prep_flags(const float* __restrict__ rs,
                           const void* __restrict__ ini,
                           const void* __restrict__ sel) {
    __shared__ int mode_i, mode_s;
    if (threadIdx.x == 0) {
        mode_i = detect_mode((const unsigned char*)ini);
        mode_s = detect_mode((const unsigned char*)sel);
    }
    __syncthreads();
    int t = threadIdx.x;
    if (t >= NAG) return;
    float r = rs[t] + 1.0f;
    bool i8 = read_flag(ini, t, mode_i);
    bool s8 = read_flag(sel, t, mode_s);
    g_r[t] = r;
    g_upd[t] = (s8 && i8);
    g_initnew[t] = (s8 && !i8);
    g_initout[t] = (s8 || i8);
}

// ---------------- S = A P A^T + (1+r)I -> split bf16 + fused Gershgorin ---
__global__ void build_S(const float* __restrict__ cov) {
    int a = blockIdx.y;
    if (!g_upd[a]) return;
    int i = blockIdx.x;
    int t = threadIdx.x;
    int j0 = t * 4;
    float r = g_r[a];
    float v[4];
    float asum = 0.0f;
    if (i < DIN) {
        int si = srcIdx(i);
        const float* row = cov + (size_t)a * DD + (size_t)si * DIN;
        #pragma unroll
        for (int q = 0; q < 4; q++) {
            int j = j0 + q;
            float x = 0.0f;
            if (j < DIN) {
                x = row[srcIdx(j)];
                if (j == i) x += 1.0f + r;
            }
            v[q] = x;
            asum += fabsf(x);
        }
    } else {
        #pragma unroll
        for (int q = 0; q < 4; q++) v[q] = (j0 + q == i) ? 1.0f : 0.0f;
    }
    uint32_t h0, l0, h1, l1;
    split2(v[0], v[1], h0, l0);
    split2(v[2], v[3], h1, l1);
    size_t off = (size_t)a * DP2 + (size_t)i * DP + j0;
    *(uint2*)(g_Sh + off) = make_uint2(h0, h1);
    *(uint2*)(g_Sl + off) = make_uint2(l0, l1);

    __shared__ float red[3];
    #pragma unroll
    for (int o = 16; o; o >>= 1) asum += __shfl_xor_sync(0xffffffffu, asum, o);
    if ((t & 31) == 0) red[t >> 5] = asum;
    __syncthreads();
    if (t == 0 && i < DIN) g_rowsum[a * DIN + i] = red[0] + red[1] + red[2];
}

__global__ void cmax(void) {
    int a = blockIdx.x;
    if (!g_upd[a]) return;
    int t = threadIdx.x;
    float m = 0.0f;
    for (int i = t; i < DIN; i += 128) m = fmaxf(m, g_rowsum[a * DIN + i]);
    __shared__ float wm[4];
    #pragma unroll
    for (int o = 16; o; o >>= 1) m = fmaxf(m, __shfl_xor_sync(0xffffffffu, m, o));
    if ((t & 31) == 0) wm[t >> 5] = m;
    __syncthreads();
    if (t == 0) {
        float G = fmaxf(fmaxf(wm[0], wm[1]), fmaxf(wm[2], wm[3]));
        g_c[a] = 2.0f / (1.0f + g_r[a] + G * 1.0002f);
    }
}

// X0 = 2c I - c^2 S  -> split bf16 into XA
__global__ void fill_X(void) {
    int a = blockIdx.y;
    if (!g_upd[a]) return;
    int e4 = blockIdx.x * 256 + threadIdx.x;   // < DP2/4 = 36864
    int i = e4 / 96;
    int jj = (e4 - i * 96) * 4;
    float c = g_c[a];
    size_t off = (size_t)a * DP2 + (size_t)i * DP + jj;
    uint2 sh = *(const uint2*)(g_Sh + off);
    uint2 sl = *(const uint2*)(g_Sl + off);
    float2 h0 = bf2f(sh.x), h1 = bf2f(sh.y);
    float2 l0 = bf2f(sl.x), l1 = bf2f(sl.y);
    float s0 = h0.x + l0.x, s1 = h0.y + l0.y, s2 = h1.x + l1.x, s3 = h1.y + l1.y;
    float c2 = c * c;
    float v0 = ((i == jj)     ? 2.0f * c : 0.0f) - c2 * s0;
    float v1 = ((i == jj + 1) ? 2.0f * c : 0.0f) - c2 * s1;
    float v2 = ((i == jj + 2) ? 2.0f * c : 0.0f) - c2 * s2;
    float v3 = ((i == jj + 3) ? 2.0f * c : 0.0f) - c2 * s3;
    uint32_t a0, b0, a1, b1;
    split2(v0, v1, a0, b0);
    split2(v2, v3, a1, b1);
    *(uint2*)(g_XAh + off) = make_uint2(a0, a1);
    *(uint2*)(g_XAl + off) = make_uint2(b0, b1);
}

// ================= pipelined mma.sync bf16 GEMM (symmetric, 6 tiles) =====
// k-chunk 32, LDT=40 halves (80B rows: ldmatrix conflict-free).
#define LDT 40
#define PANEL_E (128 * LDT)          // 5120 bf16
#define PANEL_B (PANEL_E * 2)        // 10240 bytes
#define LDC 129
#define CS_BYTES (128 * LDC * 4)     // 66048

__device__ __forceinline__ void ldm_x4(uint32_t* r, uint32_t addr) {
    asm volatile("ldmatrix.sync.aligned.m8n8.x4.shared.b16 {%0,%1,%2,%3}, [%4];"
                 : "=r"(r[0]), "=r"(r[1]), "=r"(r[2]), "=r"(r[3]) : "r"(addr));
}
__device__ __forceinline__ void mma_bf16(float* d, const uint32_t* a, const uint32_t* b) {
    asm volatile(
        "mma.sync.aligned.m16n8k16.row.col.f32.bf16.bf16.f32 "
        "{%0,%1,%2,%3}, {%4,%5,%6,%7}, {%8,%9}, {%0,%1,%2,%3};"
        : "+f"(d[0]), "+f"(d[1]), "+f"(d[2]), "+f"(d[3])
        : "r"(a[0]), "r"(a[1]), "r"(a[2]), "r"(a[3]), "r"(b[0]), "r"(b[1]));
}

// stage one 128x32 bf16 panel global -> SMEM (2 x 16B per thread)
__device__ __forceinline__ void stage32(const __nv_bfloat16* __restrict__ g,
                                        int row0, int k0, uint32_t dst, int tid) {
    const __nv_bfloat16* src0 = g + (size_t)row0 * DP + k0;
    #pragma unroll
    for (int i = 0; i < 2; i++) {
        int id = i * 256 + tid;
        int row = id >> 2, part = id & 3;
        uint32_t d = dst + (uint32_t)(row * LDT + part * 8) * 2;
        const void* s = src0 + (size_t)row * DP + part * 8;
        asm volatile("cp.async.cg.shared.global [%0], [%1], 16;"
                     :: "r"(d), "l"(s));
    }
}

// SPLIT=0: hi*hi (NS-stage pipeline). SPLIT=1: 4 panels staged once, 3 passes.
// MODE 0: C = A*B
// MODE 1: C = 2X - A*B
// MODE 3: C = A*B - I         (D capture)
// MODE 4: C = A*B + X         (cubic finish)
// MODE 5: C = A*B - X         (E = D*D - D)
// XLO: read X lo plane too. WRITELO: write C lo plane.
// FINAL: also write r*I - r^2*C to outp (fp32).
template<int SPLIT, int MODE, int XLO, int WRITELO, int FINAL, int NS>
__global__ __launch_bounds__(256, 2)
void gemm_mma(int sA, int sB, int sX, int sC, float* outp) {
    int z = blockIdx.z;
    if (!g_upd[z]) return;

    const int bi_map[6] = {0, 1, 2, 0, 0, 1};
    const int bj_map[6] = {0, 1, 2, 1, 2, 2};
    int bi = bi_map[blockIdx.x], bj = bj_map[blockIdx.x];
    int m0 = bi * 128, n0 = bj * 128;
    bool offd = (bi != bj);

    size_t zo = (size_t)z * DP2;
    const __nv_bfloat16* AH = selH(sA) + zo;
    const __nv_bfloat16* AL = selL(sA) + zo;
    const __nv_bfloat16* BH = selH(sB) + zo;
    const __nv_bfloat16* BL = selL(sB) + zo;
    const __nv_bfloat16* XH = selH(sX) + zo;
    const __nv_bfloat16* XL = selL(sX) + zo;
    __nv_bfloat16* CH = selH(sC) + zo;
    __nv_bfloat16* CL = selL(sC) + zo;

    extern __shared__ __align__(16) __nv_bfloat16 sm[];
    float* Cs = reinterpret_cast<float*>(sm);
    uint32_t sbase = smem_u32(sm);

    int tid = threadIdx.x, wid = tid >> 5, lane = tid & 31;
    int wm = (wid & 1) * 64, wn = (wid >> 1) * 32;

    float acc[4][4][4];
    #pragma unroll
    for (int i = 0; i < 4; i++)
        #pragma unroll
        for (int j = 0; j < 4; j++)
            #pragma unroll
            for (int q = 0; q < 4; q++) acc[i][j][q] = 0.0f;

    int lt = lane >> 3, lr = lane & 7;
    int a_row = (lt & 1) * 8 + lr;
    int a_col = (lt >> 1) * 8;
    int b_row = (lt >> 1) * 8 + lr;
    int b_col = (lt & 1) * 8;

    const int NP = SPLIT ? 4 : 2;
    const uint32_t STAGE_B = (uint32_t)NP * PANEL_B;

    auto do_stage = [&](int kc, int b) {
        uint32_t base = sbase + (uint32_t)b * STAGE_B;
        int k0 = kc * 32;
        stage32(AH, m0, k0, base, tid);
        stage32(BH, n0, k0, base + PANEL_B, tid);
        if (SPLIT) {
            stage32(AL, m0, k0, base + 2 * PANEL_B, tid);
            stage32(BL, n0, k0, base + 3 * PANEL_B, tid);
        }
        asm volatile("cp.async.commit_group;");
    };

    #pragma unroll
    for (int s = 0; s < NS - 1; s++) do_stage(s, s);

    for (int kc = 0; kc < 12; kc++) {
        if (NS == 3) {
            if (kc < 11) asm volatile("cp.async.wait_group 1;");
            else         asm volatile("cp.async.wait_group 0;");
        } else {
            asm volatile("cp.async.wait_group 0;");
        }
        __syncthreads();   // also certifies compute(kc-1) done by all warps

        int nxt = kc + NS - 1;
        if (nxt < 12) do_stage(nxt, nxt % NS);

        int cur = kc % NS;
        const __nv_bfloat16* At  = sm + (size_t)cur * NP * PANEL_E;
        const __nv_bfloat16* Bt  = At + PANEL_E;
        const __nv_bfloat16* Alt = At + 2 * PANEL_E;
        const __nv_bfloat16* Blt = At + 3 * PANEL_E;

        #pragma unroll
        for (int ks = 0; ks < 2; ks++) {
            int kk = ks * 16;
            uint32_t ah[4][4], bh[4][2];
            #pragma unroll
            for (int mt = 0; mt < 4; mt++)
                ldm_x4(ah[mt], smem_u32(&At[(wm + mt * 16 + a_row) * LDT + kk + a_col]));
            #pragma unroll
            for (int np = 0; np < 2; np++) {
                uint32_t r[4];
                ldm_x4(r, smem_u32(&Bt[(wn + np * 16 + b_row) * LDT + kk + b_col]));
                bh[np * 2][0] = r[0]; bh[np * 2][1] = r[1];
                bh[np * 2 + 1][0] = r[2]; bh[np * 2 + 1][1] = r[3];
            }
            #pragma unroll
            for (int mt = 0; mt < 4; mt++)
                #pragma unroll
                for (int nt = 0; nt < 4; nt++)
                    mma_bf16(acc[mt][nt], ah[mt], bh[nt]);

            if (SPLIT) {
                uint32_t bl[4][2];
                #pragma unroll
                for (int np = 0; np < 2; np++) {
                    uint32_t r[4];
                    ldm_x4(r, smem_u32(&Blt[(wn + np * 16 + b_row) * LDT + kk + b_col]));
                    bl[np * 2][0] = r[0]; bl[np * 2][1] = r[1];
                    bl[np * 2 + 1][0] = r[2]; bl[np * 2 + 1][1] = r[3];
                }
                #pragma unroll
                for (int mt = 0; mt < 4; mt++)
                    #pragma unroll
                    for (int nt = 0; nt < 4; nt++)
                        mma_bf16(acc[mt][nt], ah[mt], bl[nt]);
                uint32_t al[4][4];
                #pragma unroll
                for (int mt = 0; mt < 4; mt++)
                    ldm_x4(al[mt], smem_u32(&Alt[(wm + mt * 16 + a_row) * LDT + kk + a_col]));
                #pragma unroll
                for (int mt = 0; mt < 4; mt++)
                    #pragma unroll
                    for (int nt = 0; nt < 4; nt++)
                        mma_bf16(acc[mt][nt], al[mt], bh[nt]);
            }
        }
    }
    __syncthreads();   // protect Cs reuse of staging smem

    // ---- epilogue ----
    float r = g_r[z];
    float rr = -r * r;
    #pragma unroll
    for (int mt = 0; mt < 4; mt++) {
        int rl0 = wm + mt * 16 + (lane >> 2);
        #pragma unroll
        for (int nt = 0; nt < 4; nt++) {
            int cl0 = wn + nt * 8 + 2 * (lane & 3);
            float v00 = acc[mt][nt][0], v01 = acc[mt][nt][1];
            float v10 = acc[mt][nt][2], v11 = acc[mt][nt][3];
            size_t g0 = (size_t)(m0 + rl0) * DP + n0 + cl0;
            size_t g1 = g0 + 8 * DP;
            int gi0 = m0 + rl0, gj = n0 + cl0;
            if (MODE == 1 || MODE == 4 || MODE == 5) {
                float2 xh0 = bf2f(*(const uint32_t*)(XH + g0));
                float2 xh1 = bf2f(*(const uint32_t*)(XH + g1));
                float x00 = xh0.x, x01 = xh0.y, x10 = xh1.x, x11 = xh1.y;
                if (XLO) {
                    float2 xl0 = bf2f(*(const uint32_t*)(XL + g0));
                    float2 xl1 = bf2f(*(const uint32_t*)(XL + g1));
                    x00 += xl0.x; x01 += xl0.y; x10 += xl1.x; x11 += xl1.y;
                }
                if (MODE == 1) {
                    v00 = 2.0f * x00 - v00; v01 = 2.0f * x01 - v01;
                    v10 = 2.0f * x10 - v10; v11 = 2.0f * x11 - v11;
                } else if (MODE == 4) {  // C = A*B + X
                    v00 += x00; v01 += x01; v10 += x10; v11 += x11;
                } else {                 // MODE 5: C = A*B - X
                    v00 -= x00; v01 -= x01; v10 -= x10; v11 -= x11;
                }
            }
            if (MODE == 3) {   // C = A*B - I
                if (gi0 == gj)     v00 -= 1.0f;
                if (gi0 == gj + 1) v01 -= 1.0f;
                if (gi0 + 8 == gj)     v10 -= 1.0f;
                if (gi0 + 8 == gj + 1) v11 -= 1.0f;
            }
            uint32_t h, l;
            split2(v00, v01, h, l);
            *(uint32_t*)(CH + g0) = h;
            if (WRITELO) *(uint32_t*)(CL + g0) = l;
            split2(v10, v11, h, l);
            *(uint32_t*)(CH + g1) = h;
            if (WRITELO) *(uint32_t*)(CL + g1) = l;
            if (FINAL) {
                if (gj < DIN) {
                    if (gi0 < DIN) {
                        float2 o;
                        o.x = rr * v00 + ((gi0 == gj) ? r : 0.0f);
                        o.y = rr * v01 + ((gi0 == gj + 1) ? r : 0.0f);
                        *(float2*)(outp + (size_t)z * DD + (size_t)gi0 * DIN + gj) = o;
                    }
                    int gi1 = gi0 + 8;
                    if (gi1 < DIN) {
                        float2 o;
                        o.x = rr * v10 + ((gi1 == gj) ? r : 0.0f);
                        o.y = rr * v11 + ((gi1 == gj + 1) ? r : 0.0f);
                        *(float2*)(outp + (size_t)z * DD + (size_t)gi1 * DIN + gj) = o;
                    }
                }
            }
            if (offd) {
                Cs[rl0 * LDC + cl0] = v00;
                Cs[rl0 * LDC + cl0 + 1] = v01;
                Cs[(rl0 + 8) * LDC + cl0] = v10;
                Cs[(rl0 + 8) * LDC + cl0 + 1] = v11;
            }
        }
    }

    if (offd) {
        __syncthreads();
        #pragma unroll
        for (int it = 0; it < 32; it++) {
            int p = it * 256 + tid;
            int cc = p >> 6, mp = (p & 63) * 2;
            float v0 = Cs[mp * LDC + cc];
            float v1 = Cs[(mp + 1) * LDC + cc];
            size_t g = (size_t)(n0 + cc) * DP + m0 + mp;
            uint32_t h, l;
            split2(v0, v1, h, l);
            *(uint32_t*)(CH + g) = h;
            if (WRITELO) *(uint32_t*)(CL + g) = l;
            if (FINAL) {
                int gi = n0 + cc, gj = m0 + mp;
                if (gi < DIN && gj < DIN) {
                    float2 o;
                    o.x = rr * v0;
                    o.y = rr * v1;
                    *(float2*)(outp + (size_t)z * DD + (size_t)gi * DIN + gj) = o;
                }
            }
        }
    }
}

// ---------------- outputs ----------------
#define OUT_MEAN 0
#define OUT_COV  (NAG * DIN)
#define OUT_INIT (NAG * DIN + NAG * DD)

__global__ void finalize_cov_rest(const float* __restrict__ cov,
                                  float* __restrict__ out) {
    int a = blockIdx.y;
    if (g_upd[a]) return;
    int e4 = blockIdx.x * blockDim.x + threadIdx.x;
    if (e4 >= DD / 4) return;
    int i = e4 / 90;
    int jj = (e4 - i * 90) * 4;
    float4 o = *(const float4*)(cov + (size_t)a * DD + (size_t)i * DIN + jj);
    if (g_initnew[a]) {
        if (i >= jj && i < jj + 4) (&o.x)[i - jj] += g_r[a];
    }
    *(float4*)(out + OUT_COV + (size_t)a * DD + (size_t)i * DIN + jj) = o;
}

__global__ void finalize_mean(const float* __restrict__ mean_in,
                              const float* __restrict__ obs,
                              float* __restrict__ out, int sinv) {
    int a = blockIdx.x;
    int tid = threadIdx.x;
    __shared__ float v[DIN];

    if (tid == 0) out[OUT_INIT + a] = g_initout[a] ? 1.0f : 0.0f;

    const float* m = mean_in + (size_t)a * DIN;
    const float* o = obs + (size_t)a * DIN;
    float* om = out + OUT_MEAN + (size_t)a * DIN;

    if (g_initnew[a]) {
        for (int i = tid; i < DIN; i += blockDim.x) om[i] = o[i];
    } else if (g_upd[a]) {
        float r = g_r[a];
        const __nv_bfloat16* Xh = selH(sinv) + (size_t)a * DP2;
        const __nv_bfloat16* Xl = selL(sinv) + (size_t)a * DP2;
        for (int j = tid; j < DIN; j += blockDim.x) v[j] = o[j] - m[srcIdx(j)];
        __syncthreads();
        int warp = tid >> 5, lane = tid & 31;
        for (int i = warp; i < DIN; i += 8) {
            float s = 0.0f;
            size_t row = (size_t)i * DP;
            for (int j = lane; j < DIN; j += 32)
                s += (__bfloat162float(Xh[row + j]) + __bfloat162float(Xl[row + j])) * v[j];
            #pragma unroll
            for (int off = 16; off; off >>= 1) s += __shfl_xor_sync(0xffffffffu, s, off);
            if (lane == 0) om[i] = o[i] - r * s;
        }
    } else {
        for (int i = tid; i < DIN; i += blockDim.x) om[i] = m[i];
    }
}

// ---------------- launch ----------------
extern "C" void kernel_launch(void* const* d_in, const int* in_sizes, int n_in,
                              void* d_out, int out_size) {
    const float* mean = (const float*)d_in[0];
    const float* cov  = (const float*)d_in[1];
    const float* obs  = (const float*)d_in[2];
    const float* rs   = (const float*)d_in[3];
    const void*  ini  = d_in[4];
    const void*  sel  = d_in[5];
    float* out = (float*)d_out;

    // plain NS=3: 3 stages x 2 panels; split NS=2: 2 stages x 4 panels
    const int SMB_P = (3 * 2 * PANEL_B > CS_BYTES) ? 3 * 2 * PANEL_B : CS_BYTES;  // 66048
    const int SMB_S = (2 * 4 * PANEL_B > CS_BYTES) ? 2 * 4 * PANEL_B : CS_BYTES;  // 81920

    cudaFuncSetAttribute(gemm_mma<0,0,0,0,0,3>, cudaFuncAttributeMaxDynamicSharedMemorySize, SMB_P);
    cudaFuncSetAttribute(gemm_mma<0,1,0,0,0,3>, cudaFuncAttributeMaxDynamicSharedMemorySize, SMB_P);
    cudaFuncSetAttribute(gemm_mma<0,1,0,1,0,3>, cudaFuncAttributeMaxDynamicSharedMemorySize, SMB_P);
    cudaFuncSetAttribute(gemm_mma<1,3,0,1,0,2>, cudaFuncAttributeMaxDynamicSharedMemorySize, SMB_S);
    cudaFuncSetAttribute(gemm_mma<0,5,1,0,0,3>, cudaFuncAttributeMaxDynamicSharedMemorySize, SMB_P);
    cudaFuncSetAttribute(gemm_mma<0,4,1,1,1,3>, cudaFuncAttributeMaxDynamicSharedMemorySize, SMB_P);

    prep_flags<<<1, 64>>>(rs, ini, sel);
    build_S<<<dim3(DP, NAG), 96>>>(cov);
    cmax<<<NAG, 128>>>();
    fill_X<<<dim3(144, NAG), 256>>>();

    dim3 g6(6, 1, NAG);
    // buffers: 0=S, 1=XA, 2=XB, 3=Y/D/Xf
    // plain Newton iter 1
    gemm_mma<0,0,0,0,0,3><<<g6, 256, SMB_P>>>(0, 1, 0, 3, nullptr);  // Y  = S*XA        (hi)
    gemm_mma<0,1,0,0,0,3><<<g6, 256, SMB_P>>>(1, 3, 1, 2, nullptr);  // XB = 2XA - XA*Y  (hi)
    // plain Newton iter 2
    gemm_mma<0,0,0,0,0,3><<<g6, 256, SMB_P>>>(0, 2, 0, 3, nullptr);  // Y  = S*XB        (hi)
    gemm_mma<0,1,0,1,0,3><<<g6, 256, SMB_P>>>(2, 3, 2, 1, nullptr);  // XA = 2XB - XB*Y  (hi+lo)
    // cubic stage in D-form: Xf = XA*(I - D + D^2), D = S*XA - I
    gemm_mma<1,3,0,1,0,2><<<g6, 256, SMB_S>>>(0, 1, 0, 3, nullptr);  // D  = S*XA - I    (split, hi+lo)
    gemm_mma<0,5,1,0,0,3><<<g6, 256, SMB_P>>>(3, 3, 3, 2, nullptr);  // E  = D*D - D     (hi; X=D hi+lo)
    gemm_mma<0,4,1,1,1,3><<<g6, 256, SMB_P>>>(1, 2, 1, 3, out + OUT_COV); // Xf = XA*E + XA (+cov)

    finalize_cov_rest<<<dim3((DD / 4 + 255) / 256, NAG), 256>>>(cov, out);
    finalize_mean<<<NAG, 256>>>(mean, obs, out, 3);
}

// round 10
// speedup vs baseline: 1.5867x; 1.0819x over previous
#include <cuda_runtime.h>
#include <cuda_bf16.h>
#include <cstdint>
#include <cstddef>

// ---------------- problem constants ----------------
#define NAG 64           // B*A
#define DIN 360          // logical dim
#define DD  (DIN*DIN)
#define MODE_LEN 60
#define DP  384          // padded dim (3 x 128)
#define DP2 (DP*DP)

// ---------------- scratch: bf16 hi/lo pairs ----------------
__device__ __align__(128) __nv_bfloat16 g_Sh [(size_t)NAG*DP2];
__device__ __align__(128) __nv_bfloat16 g_Sl [(size_t)NAG*DP2];
__device__ __align__(128) __nv_bfloat16 g_XAh[(size_t)NAG*DP2];
__device__ __align__(128) __nv_bfloat16 g_XAl[(size_t)NAG*DP2];
__device__ __align__(128) __nv_bfloat16 g_XBh[(size_t)NAG*DP2];
__device__ __align__(128) __nv_bfloat16 g_XBl[(size_t)NAG*DP2];
__device__ __align__(128) __nv_bfloat16 g_Yh [(size_t)NAG*DP2];
__device__ __align__(128) __nv_bfloat16 g_Yl [(size_t)NAG*DP2];
__device__ float g_rowsum[NAG * DIN];
__device__ float g_r[NAG];
__device__ float g_c[NAG];
__device__ int   g_upd[NAG];
__device__ int   g_initnew[NAG];
__device__ int   g_initout[NAG];

__device__ __forceinline__ __nv_bfloat16* selH(int s) {
    switch (s) {
        case 0:  return g_Sh;
        case 1:  return g_XAh;
        case 2:  return g_XBh;
        default: return g_Yh;
    }
}
__device__ __forceinline__ __nv_bfloat16* selL(int s) {
    switch (s) {
        case 0:  return g_Sl;
        case 1:  return g_XAl;
        case 2:  return g_XBl;
        default: return g_Yl;
    }
}

__device__ __forceinline__ int srcIdx(int g) {
    int l = g % MODE_LEN;
    return (l < MODE_LEN - 2) ? (g + 2) : g;
}

// ---------------- small helpers ----------------
__device__ __forceinline__ uint32_t smem_u32(const void* p) {
    uint32_t a;
    asm("{ .reg .u64 t; cvta.to.shared.u64 t, %1; cvt.u32.u64 %0, t; }"
        : "=r"(a) : "l"(p));
    return a;
}
__device__ __forceinline__ uint32_t pack_bf2(float x, float y) {
    __nv_bfloat162 t = __floats2bfloat162_rn(x, y);
    return *reinterpret_cast<uint32_t*>(&t);
}
__device__ __forceinline__ float2 bf2f(uint32_t u) {
    __nv_bfloat162 t = *reinterpret_cast<__nv_bfloat162*>(&u);
    return make_float2(__bfloat162float(t.x), __bfloat162float(t.y));
}
__device__ __forceinline__ void split2(float a, float b, uint32_t& h, uint32_t& l) {
    __nv_bfloat16 ah = __float2bfloat16_rn(a), bh = __float2bfloat16_rn(b);
    float ar = a - __bfloat162float(ah), br = b - __bfloat162float(bh);
    __nv_bfloat162 t; t.x = ah; t.y = bh;
    h = *reinterpret_cast<uint32_t*>(&t);
    l = pack_bf2(ar, br);
}

// ---------------- flag dtype sniffing (validated round 2) ----------------
__device__ int detect_mode(const unsigned char* p) {
    int n_off = 0, n_3f = 0;
    for (int t = 0; t < 64; t++) {
        unsigned char b = p[t];
        if ((t & 3) && b) n_off++;
        if (((t & 3) == 3) && b == 0x3F) n_3f++;
    }
    if (n_off == 0) return 1;
    if (n_3f > 0)  return 2;
    return 0;
}
__device__ __forceinline__ bool read_flag(const void* p, int t, int mode) {
    if (mode == 1) return ((const int*)p)[t] != 0;
    if (mode == 2) return ((const float*)p)[t] != 0.0f;
    return ((const unsigned char*)p)[t] != 0;
}

__global__ void prep_flags(const float* __restrict__ rs,
                           const void* __restrict__ ini,
                           const void* __restrict__ sel) {
    __shared__ int mode_i, mode_s;
    if (threadIdx.x == 0) {
        mode_i = detect_mode((const unsigned char*)ini);
        mode_s = detect_mode((const unsigned char*)sel);
    }
    __syncthreads();
    int t = threadIdx.x;
    if (t >= NAG) return;
    float r = rs[t] + 1.0f;
    bool i8 = read_flag(ini, t, mode_i);
    bool s8 = read_flag(sel, t, mode_s);
    g_r[t] = r;
    g_upd[t] = (s8 && i8);
    g_initnew[t] = (s8 && !i8);
    g_initout[t] = (s8 || i8);
}

// ---------------- S = A P A^T + (1+r)I -> split bf16 + fused Gershgorin ---
// 256 threads = 8 warps; each warp owns one row (lane: 12 contiguous cols).
__global__ void build_S(const float* __restrict__ cov) {
    int a = blockIdx.y;
    if (!g_upd[a]) return;
    int warp = threadIdx.x >> 5, lane = threadIdx.x & 31;
    int i = blockIdx.x * 8 + warp;
    float r = g_r[a];
    size_t off = (size_t)a * DP2 + (size_t)i * DP + lane * 12;
    if (i < DIN) {
        const float* row = cov + (size_t)a * DD + (size_t)srcIdx(i) * DIN;
        float asum = 0.0f;
        #pragma unroll
        for (int g = 0; g < 3; g++) {
            float v[4];
            #pragma unroll
            for (int q = 0; q < 4; q++) {
                int j = lane * 12 + g * 4 + q;
                float x = 0.0f;
                if (j < DIN) {
                    x = row[srcIdx(j)];
                    if (j == i) x += 1.0f + r;
                }
                v[q] = x;
                asum += fabsf(x);
            }
            uint32_t h0, l0, h1, l1;
            split2(v[0], v[1], h0, l0);
            split2(v[2], v[3], h1, l1);
            *(uint2*)(g_Sh + off + g * 4) = make_uint2(h0, h1);
            *(uint2*)(g_Sl + off + g * 4) = make_uint2(l0, l1);
        }
        #pragma unroll
        for (int o = 16; o; o >>= 1) asum += __shfl_xor_sync(0xffffffffu, asum, o);
        if (lane == 0) g_rowsum[a * DIN + i] = asum;
    } else {
        #pragma unroll
        for (int g = 0; g < 3; g++) {
            float v[4];
            #pragma unroll
            for (int q = 0; q < 4; q++)
                v[q] = (lane * 12 + g * 4 + q == i) ? 1.0f : 0.0f;
            uint32_t h0, l0, h1, l1;
            split2(v[0], v[1], h0, l0);
            split2(v[2], v[3], h1, l1);
            *(uint2*)(g_Sh + off + g * 4) = make_uint2(h0, h1);
            *(uint2*)(g_Sl + off + g * 4) = make_uint2(l0, l1);
        }
    }
}

__global__ void cmax(void) {
    int a = blockIdx.x;
    if (!g_upd[a]) return;
    int t = threadIdx.x;
    float m = 0.0f;
    for (int i = t; i < DIN; i += 128) m = fmaxf(m, g_rowsum[a * DIN + i]);
    __shared__ float wm[4];
    #pragma unroll
    for (int o = 16; o; o >>= 1) m = fmaxf(m, __shfl_xor_sync(0xffffffffu, m, o));
    if ((t & 31) == 0) wm[t >> 5] = m;
    __syncthreads();
    if (t == 0) {
        float G = fmaxf(fmaxf(wm[0], wm[1]), fmaxf(wm[2], wm[3]));
        g_c[a] = 2.0f / (1.0f + g_r[a] + G * 1.0002f);
    }
}

// X0 = 2c I - c^2 S  -> split bf16 into XA
__global__ void fill_X(void) {
    int a = blockIdx.y;
    if (!g_upd[a]) return;
    int e4 = blockIdx.x * 256 + threadIdx.x;   // < DP2/4 = 36864
    int i = e4 / 96;
    int jj = (e4 - i * 96) * 4;
    float c = g_c[a];
    size_t off = (size_t)a * DP2 + (size_t)i * DP + jj;
    uint2 sh = *(const uint2*)(g_Sh + off);
    uint2 sl = *(const uint2*)(g_Sl + off);
    float2 h0 = bf2f(sh.x), h1 = bf2f(sh.y);
    float2 l0 = bf2f(sl.x), l1 = bf2f(sl.y);
    float s0 = h0.x + l0.x, s1 = h0.y + l0.y, s2 = h1.x + l1.x, s3 = h1.y + l1.y;
    float c2 = c * c;
    float v0 = ((i == jj)     ? 2.0f * c : 0.0f) - c2 * s0;
    float v1 = ((i == jj + 1) ? 2.0f * c : 0.0f) - c2 * s1;
    float v2 = ((i == jj + 2) ? 2.0f * c : 0.0f) - c2 * s2;
    float v3 = ((i == jj + 3) ? 2.0f * c : 0.0f) - c2 * s3;
    uint32_t a0, b0, a1, b1;
    split2(v0, v1, a0, b0);
    split2(v2, v3, a1, b1);
    *(uint2*)(g_XAh + off) = make_uint2(a0, a1);
    *(uint2*)(g_XAl + off) = make_uint2(b0, b1);
}

// ================= pipelined mma.sync bf16 GEMM (symmetric, 6 tiles) =====
// k-chunk 32, LDT=40 halves (80B rows: ldmatrix conflict-free).
#define LDT 40
#define PANEL_E (128 * LDT)          // 5120 bf16
#define PANEL_B (PANEL_E * 2)        // 10240 bytes
#define LDC 129
#define CS_BYTES (128 * LDC * 4)     // 66048

__device__ __forceinline__ void ldm_x4(uint32_t* r, uint32_t addr) {
    asm volatile("ldmatrix.sync.aligned.m8n8.x4.shared.b16 {%0,%1,%2,%3}, [%4];"
                 : "=r"(r[0]), "=r"(r[1]), "=r"(r[2]), "=r"(r[3]) : "r"(addr));
}
__device__ __forceinline__ void mma_bf16(float* d, const uint32_t* a, const uint32_t* b) {
    asm volatile(
        "mma.sync.aligned.m16n8k16.row.col.f32.bf16.bf16.f32 "
        "{%0,%1,%2,%3}, {%4,%5,%6,%7}, {%8,%9}, {%0,%1,%2,%3};"
        : "+f"(d[0]), "+f"(d[1]), "+f"(d[2]), "+f"(d[3])
        : "r"(a[0]), "r"(a[1]), "r"(a[2]), "r"(a[3]), "r"(b[0]), "r"(b[1]));
}

// stage one 128x32 bf16 panel global -> SMEM (2 x 16B per thread)
__device__ __forceinline__ void stage32(const __nv_bfloat16* __restrict__ g,
                                        int row0, int k0, uint32_t dst, int tid) {
    const __nv_bfloat16* src0 = g + (size_t)row0 * DP + k0;
    #pragma unroll
    for (int i = 0; i < 2; i++) {
        int id = i * 256 + tid;
        int row = id >> 2, part = id & 3;
        uint32_t d = dst + (uint32_t)(row * LDT + part * 8) * 2;
        const void* s = src0 + (size_t)row * DP + part * 8;
        asm volatile("cp.async.cg.shared.global [%0], [%1], 16;"
                     :: "r"(d), "l"(s));
    }
}

// SPLIT=0: hi*hi (NS-stage pipeline). SPLIT=1: 4 panels staged once, 3 passes.
// MODE 0: C = A*B
// MODE 1: C = 2X - A*B
// MODE 3: C = A*B - I         (D capture)
// MODE 6: C = X - A*B         (quadratic finish)
// XLO: read X lo plane too. WRITELO: write C lo plane.
// FINAL: also write r*I - r^2*C to outp (fp32).
template<int SPLIT, int MODE, int XLO, int WRITELO, int FINAL, int NS>
__global__ __launch_bounds__(256, 2)
void gemm_mma(int sA, int sB, int sX, int sC, float* outp) {
    int z = blockIdx.z;
    if (!g_upd[z]) return;

    const int bi_map[6] = {0, 1, 2, 0, 0, 1};
    const int bj_map[6] = {0, 1, 2, 1, 2, 2};
    int bi = bi_map[blockIdx.x], bj = bj_map[blockIdx.x];
    int m0 = bi * 128, n0 = bj * 128;
    bool offd = (bi != bj);

    size_t zo = (size_t)z * DP2;
    const __nv_bfloat16* AH = selH(sA) + zo;
    const __nv_bfloat16* AL = selL(sA) + zo;
    const __nv_bfloat16* BH = selH(sB) + zo;
    const __nv_bfloat16* BL = selL(sB) + zo;
    const __nv_bfloat16* XH = selH(sX) + zo;
    const __nv_bfloat16* XL = selL(sX) + zo;
    __nv_bfloat16* CH = selH(sC) + zo;
    __nv_bfloat16* CL = selL(sC) + zo;

    extern __shared__ __align__(16) __nv_bfloat16 sm[];
    float* Cs = reinterpret_cast<float*>(sm);
    uint32_t sbase = smem_u32(sm);

    int tid = threadIdx.x, wid = tid >> 5, lane = tid & 31;
    int wm = (wid & 1) * 64, wn = (wid >> 1) * 32;

    float acc[4][4][4];
    #pragma unroll
    for (int i = 0; i < 4; i++)
        #pragma unroll
        for (int j = 0; j < 4; j++)
            #pragma unroll
            for (int q = 0; q < 4; q++) acc[i][j][q] = 0.0f;

    int lt = lane >> 3, lr = lane & 7;
    int a_row = (lt & 1) * 8 + lr;
    int a_col = (lt >> 1) * 8;
    int b_row = (lt >> 1) * 8 + lr;
    int b_col = (lt & 1) * 8;

    const int NP = SPLIT ? 4 : 2;
    const uint32_t STAGE_B = (uint32_t)NP * PANEL_B;

    auto do_stage = [&](int kc, int b) {
        uint32_t base = sbase + (uint32_t)b * STAGE_B;
        int k0 = kc * 32;
        stage32(AH, m0, k0, base, tid);
        stage32(BH, n0, k0, base + PANEL_B, tid);
        if (SPLIT) {
            stage32(AL, m0, k0, base + 2 * PANEL_B, tid);
            stage32(BL, n0, k0, base + 3 * PANEL_B, tid);
        }
        asm volatile("cp.async.commit_group;");
    };

    #pragma unroll
    for (int s = 0; s < NS - 1; s++) do_stage(s, s);

    for (int kc = 0; kc < 12; kc++) {
        if (NS == 3) {
            if (kc < 11) asm volatile("cp.async.wait_group 1;");
            else         asm volatile("cp.async.wait_group 0;");
        } else {
            asm volatile("cp.async.wait_group 0;");
        }
        __syncthreads();   // also certifies compute(kc-1) done by all warps

        int nxt = kc + NS - 1;
        if (nxt < 12) do_stage(nxt, nxt % NS);

        int cur = kc % NS;
        const __nv_bfloat16* At  = sm + (size_t)cur * NP * PANEL_E;
        const __nv_bfloat16* Bt  = At + PANEL_E;
        const __nv_bfloat16* Alt = At + 2 * PANEL_E;
        const __nv_bfloat16* Blt = At + 3 * PANEL_E;

        #pragma unroll
        for (int ks = 0; ks < 2; ks++) {
            int kk = ks * 16;
            uint32_t ah[4][4], bh[4][2];
            #pragma unroll
            for (int mt = 0; mt < 4; mt++)
                ldm_x4(ah[mt], smem_u32(&At[(wm + mt * 16 + a_row) * LDT + kk + a_col]));
            #pragma unroll
            for (int np = 0; np < 2; np++) {
                uint32_t r[4];
                ldm_x4(r, smem_u32(&Bt[(wn + np * 16 + b_row) * LDT + kk + b_col]));
                bh[np * 2][0] = r[0]; bh[np * 2][1] = r[1];
                bh[np * 2 + 1][0] = r[2]; bh[np * 2 + 1][1] = r[3];
            }
            #pragma unroll
            for (int mt = 0; mt < 4; mt++)
                #pragma unroll
                for (int nt = 0; nt < 4; nt++)
                    mma_bf16(acc[mt][nt], ah[mt], bh[nt]);

            if (SPLIT) {
                uint32_t bl[4][2];
                #pragma unroll
                for (int np = 0; np < 2; np++) {
                    uint32_t r[4];
                    ldm_x4(r, smem_u32(&Blt[(wn + np * 16 + b_row) * LDT + kk + b_col]));
                    bl[np * 2][0] = r[0]; bl[np * 2][1] = r[1];
                    bl[np * 2 + 1][0] = r[2]; bl[np * 2 + 1][1] = r[3];
                }
                #pragma unroll
                for (int mt = 0; mt < 4; mt++)
                    #pragma unroll
                    for (int nt = 0; nt < 4; nt++)
                        mma_bf16(acc[mt][nt], ah[mt], bl[nt]);
                uint32_t al[4][4];
                #pragma unroll
                for (int mt = 0; mt < 4; mt++)
                    ldm_x4(al[mt], smem_u32(&Alt[(wm + mt * 16 + a_row) * LDT + kk + a_col]));
                #pragma unroll
                for (int mt = 0; mt < 4; mt++)
                    #pragma unroll
                    for (int nt = 0; nt < 4; nt++)
                        mma_bf16(acc[mt][nt], al[mt], bh[nt]);
            }
        }
    }
    __syncthreads();   // protect Cs reuse of staging smem

    // ---- epilogue ----
    float r = g_r[z];
    float rr = -r * r;
    #pragma unroll
    for (int mt = 0; mt < 4; mt++) {
        int rl0 = wm + mt * 16 + (lane >> 2);
        #pragma unroll
        for (int nt = 0; nt < 4; nt++) {
            int cl0 = wn + nt * 8 + 2 * (lane & 3);
            float v00 = acc[mt][nt][0], v01 = acc[mt][nt][1];
            float v10 = acc[mt][nt][2], v11 = acc[mt][nt][3];
            size_t g0 = (size_t)(m0 + rl0) * DP + n0 + cl0;
            size_t g1 = g0 + 8 * DP;
            int gi0 = m0 + rl0, gj = n0 + cl0;
            if (MODE == 1 || MODE == 6) {
                float2 xh0 = bf2f(*(const uint32_t*)(XH + g0));
                float2 xh1 = bf2f(*(const uint32_t*)(XH + g1));
                float x00 = xh0.x, x01 = xh0.y, x10 = xh1.x, x11 = xh1.y;
                if (XLO) {
                    float2 xl0 = bf2f(*(const uint32_t*)(XL + g0));
                    float2 xl1 = bf2f(*(const uint32_t*)(XL + g1));
                    x00 += xl0.x; x01 += xl0.y; x10 += xl1.x; x11 += xl1.y;
                }
                if (MODE == 1) {
                    v00 = 2.0f * x00 - v00; v01 = 2.0f * x01 - v01;
                    v10 = 2.0f * x10 - v10; v11 = 2.0f * x11 - v11;
                } else {                 // MODE 6: C = X - A*B
                    v00 = x00 - v00; v01 = x01 - v01;
                    v10 = x10 - v10; v11 = x11 - v11;
                }
            }
            if (MODE == 3) {   // C = A*B - I
                if (gi0 == gj)     v00 -= 1.0f;
                if (gi0 == gj + 1) v01 -= 1.0f;
                if (gi0 + 8 == gj)     v10 -= 1.0f;
                if (gi0 + 8 == gj + 1) v11 -= 1.0f;
            }
            uint32_t h, l;
            split2(v00, v01, h, l);
            *(uint32_t*)(CH + g0) = h;
            if (WRITELO) *(uint32_t*)(CL + g0) = l;
            split2(v10, v11, h, l);
            *(uint32_t*)(CH + g1) = h;
            if (WRITELO) *(uint32_t*)(CL + g1) = l;
            if (FINAL) {
                if (gj < DIN) {
                    if (gi0 < DIN) {
                        float2 o;
                        o.x = rr * v00 + ((gi0 == gj) ? r : 0.0f);
                        o.y = rr * v01 + ((gi0 == gj + 1) ? r : 0.0f);
                        *(float2*)(outp + (size_t)z * DD + (size_t)gi0 * DIN + gj) = o;
                    }
                    int gi1 = gi0 + 8;
                    if (gi1 < DIN) {
                        float2 o;
                        o.x = rr * v10 + ((gi1 == gj) ? r : 0.0f);
                        o.y = rr * v11 + ((gi1 == gj + 1) ? r : 0.0f);
                        *(float2*)(outp + (size_t)z * DD + (size_t)gi1 * DIN + gj) = o;
                    }
                }
            }
            if (offd) {
                Cs[rl0 * LDC + cl0] = v00;
                Cs[rl0 * LDC + cl0 + 1] = v01;
                Cs[(rl0 + 8) * LDC + cl0] = v10;
                Cs[(rl0 + 8) * LDC + cl0 + 1] = v11;
            }
        }
    }

    if (offd) {
        __syncthreads();
        #pragma unroll
        for (int it = 0; it < 32; it++) {
            int p = it * 256 + tid;
            int cc = p >> 6, mp = (p & 63) * 2;
            float v0 = Cs[mp * LDC + cc];
            float v1 = Cs[(mp + 1) * LDC + cc];
            size_t g = (size_t)(n0 + cc) * DP + m0 + mp;
            uint32_t h, l;
            split2(v0, v1, h, l);
            *(uint32_t*)(CH + g) = h;
            if (WRITELO) *(uint32_t*)(CL + g) = l;
            if (FINAL) {
                int gi = n0 + cc, gj = m0 + mp;
                if (gi < DIN && gj < DIN) {
                    float2 o;
                    o.x = rr * v0;
                    o.y = rr * v1;
                    *(float2*)(outp + (size_t)z * DD + (size_t)gi * DIN + gj) = o;
                }
            }
        }
    }
}

// ---------------- outputs ----------------
#define OUT_MEAN 0
#define OUT_COV  (NAG * DIN)
#define OUT_INIT (NAG * DIN + NAG * DD)

__global__ void finalize_cov_rest(const float* __restrict__ cov,
                                  float* __restrict__ out) {
    int a = blockIdx.y;
    if (g_upd[a]) return;
    int e4 = blockIdx.x * blockDim.x + threadIdx.x;
    if (e4 >= DD / 4) return;
    int i = e4 / 90;
    int jj = (e4 - i * 90) * 4;
    float4 o = *(const float4*)(cov + (size_t)a * DD + (size_t)i * DIN + jj);
    if (g_initnew[a]) {
        if (i >= jj && i < jj + 4) (&o.x)[i - jj] += g_r[a];
    }
    *(float4*)(out + OUT_COV + (size_t)a * DD + (size_t)i * DIN + jj) = o;
}

__global__ void finalize_mean(const float* __restrict__ mean_in,
                              const float* __restrict__ obs,
                              float* __restrict__ out, int sinv) {
    int a = blockIdx.x;
    int tid = threadIdx.x;
    __shared__ float v[DIN];

    if (tid == 0) out[OUT_INIT + a] = g_initout[a] ? 1.0f : 0.0f;

    const float* m = mean_in + (size_t)a * DIN;
    const float* o = obs + (size_t)a * DIN;
    float* om = out + OUT_MEAN + (size_t)a * DIN;

    if (g_initnew[a]) {
        for (int i = tid; i < DIN; i += blockDim.x) om[i] = o[i];
    } else if (g_upd[a]) {
        float r = g_r[a];
        const __nv_bfloat16* Xh = selH(sinv) + (size_t)a * DP2;
        const __nv_bfloat16* Xl = selL(sinv) + (size_t)a * DP2;
        for (int j = tid; j < DIN; j += blockDim.x) v[j] = o[j] - m[srcIdx(j)];
        __syncthreads();
        int warp = tid >> 5, lane = tid & 31;
        for (int i = warp; i < DIN; i += 8) {
            float s = 0.0f;
            size_t row = (size_t)i * DP;
            for (int j = lane; j < DIN; j += 32)
                s += (__bfloat162float(Xh[row + j]) + __bfloat162float(Xl[row + j])) * v[j];
            #pragma unroll
            for (int off = 16; off; off >>= 1) s += __shfl_xor_sync(0xffffffffu, s, off);
            if (lane == 0) om[i] = o[i] - r * s;
        }
    } else {
        for (int i = tid; i < DIN; i += blockDim.x) om[i] = m[i];
    }
}

// ---------------- launch ----------------
extern "C" void kernel_launch(void* const* d_in, const int* in_sizes, int n_in,
                              void* d_out, int out_size) {
    const float* mean = (const float*)d_in[0];
    const float* cov  = (const float*)d_in[1];
    const float* obs  = (const float*)d_in[2];
    const float* rs   = (const float*)d_in[3];
    const void*  ini  = d_in[4];
    const void*  sel  = d_in[5];
    float* out = (float*)d_out;

    // plain NS=3: 3 stages x 2 panels; split NS=2: 2 stages x 4 panels
    const int SMB_P = (3 * 2 * PANEL_B > CS_BYTES) ? 3 * 2 * PANEL_B : CS_BYTES;  // 66048
    const int SMB_S = (2 * 4 * PANEL_B > CS_BYTES) ? 2 * 4 * PANEL_B : CS_BYTES;  // 81920

    cudaFuncSetAttribute(gemm_mma<0,0,0,0,0,3>, cudaFuncAttributeMaxDynamicSharedMemorySize, SMB_P);
    cudaFuncSetAttribute(gemm_mma<0,1,0,0,0,3>, cudaFuncAttributeMaxDynamicSharedMemorySize, SMB_P);
    cudaFuncSetAttribute(gemm_mma<0,1,0,1,0,3>, cudaFuncAttributeMaxDynamicSharedMemorySize, SMB_P);
    cudaFuncSetAttribute(gemm_mma<1,3,0,0,0,2>, cudaFuncAttributeMaxDynamicSharedMemorySize, SMB_S);
    cudaFuncSetAttribute(gemm_mma<0,6,1,1,1,3>, cudaFuncAttributeMaxDynamicSharedMemorySize, SMB_P);

    prep_flags<<<1, 64>>>(rs, ini, sel);
    build_S<<<dim3(DP / 8, NAG), 256>>>(cov);
    cmax<<<NAG, 128>>>();
    fill_X<<<dim3(144, NAG), 256>>>();

    dim3 g6(6, 1, NAG);
    // buffers: 0=S, 1=XA, 2=XB, 3=Y/D
    // plain Newton iter 1
    gemm_mma<0,0,0,0,0,3><<<g6, 256, SMB_P>>>(0, 1, 0, 3, nullptr);  // Y  = S*XA        (hi)
    gemm_mma<0,1,0,0,0,3><<<g6, 256, SMB_P>>>(1, 3, 1, 2, nullptr);  // XB = 2XA - XA*Y  (hi)
    // plain Newton iter 2
    gemm_mma<0,0,0,0,0,3><<<g6, 256, SMB_P>>>(0, 2, 0, 3, nullptr);  // Y  = S*XB        (hi)
    gemm_mma<0,1,0,1,0,3><<<g6, 256, SMB_P>>>(2, 3, 2, 1, nullptr);  // XA = 2XB - XB*Y  (hi+lo)
    // quadratic finish: Xf = XA - XA*D, D = S*XA - I (split)
    gemm_mma<1,3,0,0,0,2><<<g6, 256, SMB_S>>>(0, 1, 0, 3, nullptr);  // D  = S*XA - I    (split, hi)
    gemm_mma<0,6,1,1,1,3><<<g6, 256, SMB_P>>>(1, 3, 1, 2, out + OUT_COV); // Xf = XA - XA*D -> XB (+cov)

    finalize_cov_rest<<<dim3((DD / 4 + 255) / 256, NAG), 256>>>(cov, out);
    finalize_mean<<<NAG, 256>>>(mean, obs, out, 2);
}

// round 11
// speedup vs baseline: 1.6156x; 1.0182x over previous
#include <cuda_runtime.h>
#include <cuda_bf16.h>
#include <cstdint>
#include <cstddef>

// ---------------- problem constants ----------------
#define NAG 64           // B*A
#define DIN 360          // logical dim
#define DD  (DIN*DIN)
#define MODE_LEN 60
#define DP  384          // padded dim (3 x 128)
#define DP2 (DP*DP)

// ---------------- scratch: bf16 hi/lo pairs ----------------
__device__ __align__(128) __nv_bfloat16 g_Sh [(size_t)NAG*DP2];
__device__ __align__(128) __nv_bfloat16 g_Sl [(size_t)NAG*DP2];
__device__ __align__(128) __nv_bfloat16 g_XAh[(size_t)NAG*DP2];
__device__ __align__(128) __nv_bfloat16 g_XAl[(size_t)NAG*DP2];
__device__ __align__(128) __nv_bfloat16 g_XBh[(size_t)NAG*DP2];
__device__ __align__(128) __nv_bfloat16 g_XBl[(size_t)NAG*DP2];
__device__ __align__(128) __nv_bfloat16 g_Yh [(size_t)NAG*DP2];
__device__ __align__(128) __nv_bfloat16 g_Yl [(size_t)NAG*DP2];
__device__ float g_rowsum[NAG * DIN];
__device__ float g_r[NAG];
__device__ int   g_upd[NAG];
__device__ int   g_initnew[NAG];
__device__ int   g_initout[NAG];

__device__ __forceinline__ __nv_bfloat16* selH(int s) {
    switch (s) {
        case 0:  return g_Sh;
        case 1:  return g_XAh;
        case 2:  return g_XBh;
        default: return g_Yh;
    }
}
__device__ __forceinline__ __nv_bfloat16* selL(int s) {
    switch (s) {
        case 0:  return g_Sl;
        case 1:  return g_XAl;
        case 2:  return g_XBl;
        default: return g_Yl;
    }
}

__device__ __forceinline__ int srcIdx(int g) {
    int l = g % MODE_LEN;
    return (l < MODE_LEN - 2) ? (g + 2) : g;
}

// ---------------- small helpers ----------------
__device__ __forceinline__ uint32_t smem_u32(const void* p) {
    uint32_t a;
    asm("{ .reg .u64 t; cvta.to.shared.u64 t, %1; cvt.u32.u64 %0, t; }"
        : "=r"(a) : "l"(p));
    return a;
}
__device__ __forceinline__ uint32_t pack_bf2(float x, float y) {
    __nv_bfloat162 t = __floats2bfloat162_rn(x, y);
    return *reinterpret_cast<uint32_t*>(&t);
}
__device__ __forceinline__ float2 bf2f(uint32_t u) {
    __nv_bfloat162 t = *reinterpret_cast<__nv_bfloat162*>(&u);
    return make_float2(__bfloat162float(t.x), __bfloat162float(t.y));
}
__device__ __forceinline__ void split2(float a, float b, uint32_t& h, uint32_t& l) {
    __nv_bfloat16 ah = __float2bfloat16_rn(a), bh = __float2bfloat16_rn(b);
    float ar = a - __bfloat162float(ah), br = b - __bfloat162float(bh);
    __nv_bfloat162 t; t.x = ah; t.y = bh;
    h = *reinterpret_cast<uint32_t*>(&t);
    l = pack_bf2(ar, br);
}

// ---------------- flag dtype sniffing (validated round 2) ----------------
__device__ int detect_mode(const unsigned char* p) {
    int n_off = 0, n_3f = 0;
    for (int t = 0; t < 64; t++) {
        unsigned char b = p[t];
        if ((t & 3) && b) n_off++;
        if (((t & 3) == 3) && b == 0x3F) n_3f++;
    }
    if (n_off == 0) return 1;
    if (n_3f > 0)  return 2;
    return 0;
}
__device__ __forceinline__ bool read_flag(const void* p, int t, int mode) {
    if (mode == 1) return ((const int*)p)[t] != 0;
    if (mode == 2) return ((const float*)p)[t] != 0.0f;
    return ((const unsigned char*)p)[t] != 0;
}

__global__ void prep_flags(const float* __restrict__ rs,
                           const void* __restrict__ ini,
                           const void* __restrict__ sel) {
    __shared__ int mode_i, mode_s;
    if (threadIdx.x == 0) {
        mode_i = detect_mode((const unsigned char*)ini);
        mode_s = detect_mode((const unsigned char*)sel);
    }
    __syncthreads();
    int t = threadIdx.x;
    if (t >= NAG) return;
    float r = rs[t] + 1.0f;
    bool i8 = read_flag(ini, t, mode_i);
    bool s8 = read_flag(sel, t, mode_s);
    g_r[t] = r;
    g_upd[t] = (s8 && i8);
    g_initnew[t] = (s8 && !i8);
    g_initout[t] = (s8 || i8);
}

// ---------------- S = A P A^T + (1+r)I -> split bf16 + fused Gershgorin ---
// 256 threads = 8 warps; each warp owns one row (lane: 12 contiguous cols).
__global__ void build_S(const float* __restrict__ cov) {
    int a = blockIdx.y;
    if (!g_upd[a]) return;
    int warp = threadIdx.x >> 5, lane = threadIdx.x & 31;
    int i = blockIdx.x * 8 + warp;
    float r = g_r[a];
    size_t off = (size_t)a * DP2 + (size_t)i * DP + lane * 12;
    if (i < DIN) {
        const float* row = cov + (size_t)a * DD + (size_t)srcIdx(i) * DIN;
        float asum = 0.0f;
        #pragma unroll
        for (int g = 0; g < 3; g++) {
            float v[4];
            #pragma unroll
            for (int q = 0; q < 4; q++) {
                int j = lane * 12 + g * 4 + q;
                float x = 0.0f;
                if (j < DIN) {
                    x = row[srcIdx(j)];
                    if (j == i) x += 1.0f + r;
                }
                v[q] = x;
                asum += fabsf(x);
            }
            uint32_t h0, l0, h1, l1;
            split2(v[0], v[1], h0, l0);
            split2(v[2], v[3], h1, l1);
            *(uint2*)(g_Sh + off + g * 4) = make_uint2(h0, h1);
            *(uint2*)(g_Sl + off + g * 4) = make_uint2(l0, l1);
        }
        #pragma unroll
        for (int o = 16; o; o >>= 1) asum += __shfl_xor_sync(0xffffffffu, asum, o);
        if (lane == 0) g_rowsum[a * DIN + i] = asum;
    } else {
        #pragma unroll
        for (int g = 0; g < 3; g++) {
            float v[4];
            #pragma unroll
            for (int q = 0; q < 4; q++)
                v[q] = (lane * 12 + g * 4 + q == i) ? 1.0f : 0.0f;
            uint32_t h0, l0, h1, l1;
            split2(v[0], v[1], h0, l0);
            split2(v[2], v[3], h1, l1);
            *(uint2*)(g_Sh + off + g * 4) = make_uint2(h0, h1);
            *(uint2*)(g_Sl + off + g * 4) = make_uint2(l0, l1);
        }
    }
}

// X0 = 2c I - c^2 S -> split bf16 into XA. Gershgorin max fused per block.
__global__ void fill_X(void) {
    int a = blockIdx.y;
    if (!g_upd[a]) return;
    int tid = threadIdx.x;
    __shared__ float wm8[8];
    __shared__ float sc;
    float m = 0.0f;
    for (int i = tid; i < DIN; i += 256) m = fmaxf(m, g_rowsum[a * DIN + i]);
    #pragma unroll
    for (int o = 16; o; o >>= 1) m = fmaxf(m, __shfl_xor_sync(0xffffffffu, m, o));
    if ((tid & 31) == 0) wm8[tid >> 5] = m;
    __syncthreads();
    if (tid == 0) {
        float G = 0.0f;
        #pragma unroll
        for (int w = 0; w < 8; w++) G = fmaxf(G, wm8[w]);
        sc = 2.0f / (1.0f + g_r[a] + G * 1.0002f);
    }
    __syncthreads();
    float c = sc;

    int e4 = blockIdx.x * 256 + tid;   // < DP2/4 = 36864
    int i = e4 / 96;
    int jj = (e4 - i * 96) * 4;
    size_t off = (size_t)a * DP2 + (size_t)i * DP + jj;
    uint2 sh = *(const uint2*)(g_Sh + off);
    uint2 sl = *(const uint2*)(g_Sl + off);
    float2 h0 = bf2f(sh.x), h1 = bf2f(sh.y);
    float2 l0 = bf2f(sl.x), l1 = bf2f(sl.y);
    float s0 = h0.x + l0.x, s1 = h0.y + l0.y, s2 = h1.x + l1.x, s3 = h1.y + l1.y;
    float c2 = c * c;
    float v0 = ((i == jj)     ? 2.0f * c : 0.0f) - c2 * s0;
    float v1 = ((i == jj + 1) ? 2.0f * c : 0.0f) - c2 * s1;
    float v2 = ((i == jj + 2) ? 2.0f * c : 0.0f) - c2 * s2;
    float v3 = ((i == jj + 3) ? 2.0f * c : 0.0f) - c2 * s3;
    uint32_t a0, b0, a1, b1;
    split2(v0, v1, a0, b0);
    split2(v2, v3, a1, b1);
    *(uint2*)(g_XAh + off) = make_uint2(a0, a1);
    *(uint2*)(g_XAl + off) = make_uint2(b0, b1);
}

// ================= pipelined mma.sync bf16 GEMM (symmetric tiles) =====
// k-chunk 32, LDT=40 halves (80B rows: ldmatrix conflict-free).
// NT = 128 (6 tile-jobs) or 64 (12 tile-jobs, better SM load balance).
#define LDT 40
#define PA_E (128 * LDT)             // A panel elems
#define PA_B (PA_E * 2)

__device__ __forceinline__ void ldm_x4(uint32_t* r, uint32_t addr) {
    asm volatile("ldmatrix.sync.aligned.m8n8.x4.shared.b16 {%0,%1,%2,%3}, [%4];"
                 : "=r"(r[0]), "=r"(r[1]), "=r"(r[2]), "=r"(r[3]) : "r"(addr));
}
__device__ __forceinline__ void mma_bf16(float* d, const uint32_t* a, const uint32_t* b) {
    asm volatile(
        "mma.sync.aligned.m16n8k16.row.col.f32.bf16.bf16.f32 "
        "{%0,%1,%2,%3}, {%4,%5,%6,%7}, {%8,%9}, {%0,%1,%2,%3};"
        : "+f"(d[0]), "+f"(d[1]), "+f"(d[2]), "+f"(d[3])
        : "r"(a[0]), "r"(a[1]), "r"(a[2]), "r"(a[3]), "r"(b[0]), "r"(b[1]));
}

// stage one ROWSx32 bf16 panel global -> SMEM
template<int ROWS>
__device__ __forceinline__ void stageP(const __nv_bfloat16* __restrict__ g,
                                       int row0, int k0, uint32_t dst, int tid) {
    const __nv_bfloat16* src0 = g + (size_t)row0 * DP + k0;
    #pragma unroll
    for (int i = 0; i < ROWS / 64; i++) {
        int id = i * 256 + tid;
        int row = id >> 2, part = id & 3;
        uint32_t d = dst + (uint32_t)(row * LDT + part * 8) * 2;
        const void* s = src0 + (size_t)row * DP + part * 8;
        asm volatile("cp.async.cg.shared.global [%0], [%1], 16;"
                     :: "r"(d), "l"(s));
    }
}

// SPLIT=0: hi*hi (NS-stage pipeline). SPLIT=1: 4 panels staged once, 3 passes.
// MODE 0: C = A*B ; MODE 1: C = 2X - A*B ; MODE 3: C = A*B - I ;
// MODE 6: C = X - A*B (quadratic finish).
// XLO: read X lo plane. WRITELO: write C lo plane.
// FINAL: also write r*I - r^2*C to outp (fp32).
template<int SPLIT, int MODE, int XLO, int WRITELO, int FINAL, int NS, int NT>
__global__ __launch_bounds__(256, 2)
void gemm_mma(int sA, int sB, int sX, int sC, float* outp) {
    int z = blockIdx.z;
    if (!g_upd[z]) return;

    int bi, bj;
    if (NT == 128) {
        const int bim[6] = {0, 1, 2, 0, 0, 1};
        const int bjm[6] = {0, 1, 2, 1, 2, 2};
        bi = bim[blockIdx.x]; bj = bjm[blockIdx.x];
    } else {
        const int bim[12] = {0, 0, 0, 0, 0, 0, 1, 1, 1, 1, 2, 2};
        const int bjm[12] = {0, 1, 2, 3, 4, 5, 2, 3, 4, 5, 4, 5};
        bi = bim[blockIdx.x]; bj = bjm[blockIdx.x];
    }
    int m0 = bi * 128, n0 = bj * NT;
    bool offd = (NT == 128) ? (bi != bj) : ((bj >> 1) != bi);

    constexpr int PB_E = NT * LDT;
    constexpr int PB_B = PB_E * 2;
    constexpr int MT = (NT == 128) ? 4 : 2;
    constexpr int LDCn = (NT == 128) ? 129 : 65;
    constexpr int STAGE_E = (SPLIT ? 2 : 1) * (PA_E + PB_E);
    constexpr uint32_t STAGE_B = STAGE_E * 2;

    size_t zo = (size_t)z * DP2;
    const __nv_bfloat16* AH = selH(sA) + zo;
    const __nv_bfloat16* AL = selL(sA) + zo;
    const __nv_bfloat16* BH = selH(sB) + zo;
    const __nv_bfloat16* BL = selL(sB) + zo;
    const __nv_bfloat16* XH = selH(sX) + zo;
    const __nv_bfloat16* XL = selL(sX) + zo;
    __nv_bfloat16* CH = selH(sC) + zo;
    __nv_bfloat16* CL = selL(sC) + zo;

    extern __shared__ __align__(16) __nv_bfloat16 sm[];
    float* Cs = reinterpret_cast<float*>(sm);
    uint32_t sbase = smem_u32(sm);

    int tid = threadIdx.x, wid = tid >> 5, lane = tid & 31;
    int wm = (NT == 128) ? (wid & 1) * 64 : (wid & 3) * 32;
    int wn = (NT == 128) ? (wid >> 1) * 32 : (wid >> 2) * 32;

    float acc[MT][4][4];
    #pragma unroll
    for (int i = 0; i < MT; i++)
        #pragma unroll
        for (int j = 0; j < 4; j++)
            #pragma unroll
            for (int q = 0; q < 4; q++) acc[i][j][q] = 0.0f;

    int lt = lane >> 3, lr = lane & 7;
    int a_row = (lt & 1) * 8 + lr;
    int a_col = (lt >> 1) * 8;
    int b_row = (lt >> 1) * 8 + lr;
    int b_col = (lt & 1) * 8;

    auto do_stage = [&](int kc, int b) {
        uint32_t base = sbase + (uint32_t)b * STAGE_B;
        int k0 = kc * 32;
        stageP<128>(AH, m0, k0, base, tid);
        stageP<NT>(BH, n0, k0, base + PA_B, tid);
        if (SPLIT) {
            stageP<128>(AL, m0, k0, base + PA_B + PB_B, tid);
            stageP<NT>(BL, n0, k0, base + 2 * PA_B + PB_B, tid);
        }
        asm volatile("cp.async.commit_group;");
    };

    #pragma unroll
    for (int s = 0; s < NS - 1; s++) do_stage(s, s);

    for (int kc = 0; kc < 12; kc++) {
        if (NS == 3) {
            if (kc < 11) asm volatile("cp.async.wait_group 1;");
            else         asm volatile("cp.async.wait_group 0;");
        } else {
            asm volatile("cp.async.wait_group 0;");
        }
        __syncthreads();   // also certifies compute(kc-1) done by all warps

        int nxt = kc + NS - 1;
        if (nxt < 12) do_stage(nxt, nxt % NS);

        int cur = kc % NS;
        const __nv_bfloat16* At  = sm + (size_t)cur * STAGE_E;
        const __nv_bfloat16* Bt  = At + PA_E;
        const __nv_bfloat16* Alt = Bt + PB_E;
        const __nv_bfloat16* Blt = Alt + PA_E;

        #pragma unroll
        for (int ks = 0; ks < 2; ks++) {
            int kk = ks * 16;
            uint32_t ah[MT][4], bh[4][2];
            #pragma unroll
            for (int mt = 0; mt < MT; mt++)
                ldm_x4(ah[mt], smem_u32(&At[(wm + mt * 16 + a_row) * LDT + kk + a_col]));
            #pragma unroll
            for (int np = 0; np < 2; np++) {
                uint32_t r[4];
                ldm_x4(r, smem_u32(&Bt[(wn + np * 16 + b_row) * LDT + kk + b_col]));
                bh[np * 2][0] = r[0]; bh[np * 2][1] = r[1];
                bh[np * 2 + 1][0] = r[2]; bh[np * 2 + 1][1] = r[3];
            }
            #pragma unroll
            for (int mt = 0; mt < MT; mt++)
                #pragma unroll
                for (int nt = 0; nt < 4; nt++)
                    mma_bf16(acc[mt][nt], ah[mt], bh[nt]);

            if (SPLIT) {
                uint32_t bl[4][2];
                #pragma unroll
                for (int np = 0; np < 2; np++) {
                    uint32_t r[4];
                    ldm_x4(r, smem_u32(&Blt[(wn + np * 16 + b_row) * LDT + kk + b_col]));
                    bl[np * 2][0] = r[0]; bl[np * 2][1] = r[1];
                    bl[np * 2 + 1][0] = r[2]; bl[np * 2 + 1][1] = r[3];
                }
                #pragma unroll
                for (int mt = 0; mt < MT; mt++)
                    #pragma unroll
                    for (int nt = 0; nt < 4; nt++)
                        mma_bf16(acc[mt][nt], ah[mt], bl[nt]);
                uint32_t al[MT][4];
                #pragma unroll
                for (int mt = 0; mt < MT; mt++)
                    ldm_x4(al[mt], smem_u32(&Alt[(wm + mt * 16 + a_row) * LDT + kk + a_col]));
                #pragma unroll
                for (int mt = 0; mt < MT; mt++)
                    #pragma unroll
                    for (int nt = 0; nt < 4; nt++)
                        mma_bf16(acc[mt][nt], al[mt], bh[nt]);
            }
        }
    }
    __syncthreads();   // protect Cs reuse of staging smem

    // ---- epilogue ----
    float r = g_r[z];
    float rr = -r * r;
    #pragma unroll
    for (int mt = 0; mt < MT; mt++) {
        int rl0 = wm + mt * 16 + (lane >> 2);
        #pragma unroll
        for (int nt = 0; nt < 4; nt++) {
            int cl0 = wn + nt * 8 + 2 * (lane & 3);
            float v00 = acc[mt][nt][0], v01 = acc[mt][nt][1];
            float v10 = acc[mt][nt][2], v11 = acc[mt][nt][3];
            size_t g0 = (size_t)(m0 + rl0) * DP + n0 + cl0;
            size_t g1 = g0 + 8 * DP;
            int gi0 = m0 + rl0, gj = n0 + cl0;
            if (MODE == 1 || MODE == 6) {
                float2 xh0 = bf2f(*(const uint32_t*)(XH + g0));
                float2 xh1 = bf2f(*(const uint32_t*)(XH + g1));
                float x00 = xh0.x, x01 = xh0.y, x10 = xh1.x, x11 = xh1.y;
                if (XLO) {
                    float2 xl0 = bf2f(*(const uint32_t*)(XL + g0));
                    float2 xl1 = bf2f(*(const uint32_t*)(XL + g1));
                    x00 += xl0.x; x01 += xl0.y; x10 += xl1.x; x11 += xl1.y;
                }
                if (MODE == 1) {
                    v00 = 2.0f * x00 - v00; v01 = 2.0f * x01 - v01;
                    v10 = 2.0f * x10 - v10; v11 = 2.0f * x11 - v11;
                } else {                 // MODE 6: C = X - A*B
                    v00 = x00 - v00; v01 = x01 - v01;
                    v10 = x10 - v10; v11 = x11 - v11;
                }
            }
            if (MODE == 3) {   // C = A*B - I
                if (gi0 == gj)     v00 -= 1.0f;
                if (gi0 == gj + 1) v01 -= 1.0f;
                if (gi0 + 8 == gj)     v10 -= 1.0f;
                if (gi0 + 8 == gj + 1) v11 -= 1.0f;
            }
            uint32_t h, l;
            split2(v00, v01, h, l);
            *(uint32_t*)(CH + g0) = h;
            if (WRITELO) *(uint32_t*)(CL + g0) = l;
            split2(v10, v11, h, l);
            *(uint32_t*)(CH + g1) = h;
            if (WRITELO) *(uint32_t*)(CL + g1) = l;
            if (FINAL) {
                if (gj < DIN) {
                    if (gi0 < DIN) {
                        float2 o;
                        o.x = rr * v00 + ((gi0 == gj) ? r : 0.0f);
                        o.y = rr * v01 + ((gi0 == gj + 1) ? r : 0.0f);
                        *(float2*)(outp + (size_t)z * DD + (size_t)gi0 * DIN + gj) = o;
                    }
                    int gi1 = gi0 + 8;
                    if (gi1 < DIN) {
                        float2 o;
                        o.x = rr * v10 + ((gi1 == gj) ? r : 0.0f);
                        o.y = rr * v11 + ((gi1 == gj + 1) ? r : 0.0f);
                        *(float2*)(outp + (size_t)z * DD + (size_t)gi1 * DIN + gj) = o;
                    }
                }
            }
            if (offd) {
                Cs[rl0 * LDCn + cl0] = v00;
                Cs[rl0 * LDCn + cl0 + 1] = v01;
                Cs[(rl0 + 8) * LDCn + cl0] = v10;
                Cs[(rl0 + 8) * LDCn + cl0 + 1] = v11;
            }
        }
    }

    if (offd) {
        __syncthreads();
        #pragma unroll
        for (int it = 0; it < NT / 4; it++) {
            int p = it * 256 + tid;
            int cc = p >> 6, mp = (p & 63) * 2;
            float v0 = Cs[mp * LDCn + cc];
            float v1 = Cs[(mp + 1) * LDCn + cc];
            int gi = n0 + cc, gj = m0 + mp;
            size_t g = (size_t)gi * DP + gj;
            uint32_t h, l;
            split2(v0, v1, h, l);
            *(uint32_t*)(CH + g) = h;
            if (WRITELO) *(uint32_t*)(CL + g) = l;
            if (FINAL) {
                if (gi < DIN && gj < DIN) {
                    float2 o;
                    o.x = rr * v0;
                    o.y = rr * v1;
                    *(float2*)(outp + (size_t)z * DD + (size_t)gi * DIN + gj) = o;
                }
            }
        }
    }
}

// ---------------- outputs ----------------
#define OUT_MEAN 0
#define OUT_COV  (NAG * DIN)
#define OUT_INIT (NAG * DIN + NAG * DD)

__global__ void finalize_cov_rest(const float* __restrict__ cov,
                                  float* __restrict__ out) {
    int a = blockIdx.y;
    if (g_upd[a]) return;
    int e4 = blockIdx.x * blockDim.x + threadIdx.x;
    if (e4 >= DD / 4) return;
    int i = e4 / 90;
    int jj = (e4 - i * 90) * 4;
    float4 o = *(const float4*)(cov + (size_t)a * DD + (size_t)i * DIN + jj);
    if (g_initnew[a]) {
        if (i >= jj && i < jj + 4) (&o.x)[i - jj] += g_r[a];
    }
    *(float4*)(out + OUT_COV + (size_t)a * DD + (size_t)i * DIN + jj) = o;
}

__global__ void finalize_mean(const float* __restrict__ mean_in,
                              const float* __restrict__ obs,
                              float* __restrict__ out, int sinv) {
    int a = blockIdx.x;
    int tid = threadIdx.x;
    __shared__ float v[DIN];

    if (tid == 0) out[OUT_INIT + a] = g_initout[a] ? 1.0f : 0.0f;

    const float* m = mean_in + (size_t)a * DIN;
    const float* o = obs + (size_t)a * DIN;
    float* om = out + OUT_MEAN + (size_t)a * DIN;

    if (g_initnew[a]) {
        for (int i = tid; i < DIN; i += blockDim.x) om[i] = o[i];
    } else if (g_upd[a]) {
        float r = g_r[a];
        const __nv_bfloat16* Xh = selH(sinv) + (size_t)a * DP2;
        const __nv_bfloat16* Xl = selL(sinv) + (size_t)a * DP2;
        for (int j = tid; j < DIN; j += blockDim.x) v[j] = o[j] - m[srcIdx(j)];
        __syncthreads();
        int warp = tid >> 5, lane = tid & 31;
        for (int i = warp; i < DIN; i += 8) {
            float s = 0.0f;
            size_t row = (size_t)i * DP;
            for (int j = lane; j < DIN; j += 32)
                s += (__bfloat162float(Xh[row + j]) + __bfloat162float(Xl[row + j])) * v[j];
            #pragma unroll
            for (int off = 16; off; off >>= 1) s += __shfl_xor_sync(0xffffffffu, s, off);
            if (lane == 0) om[i] = o[i] - r * s;
        }
    } else {
        for (int i = tid; i < DIN; i += blockDim.x) om[i] = m[i];
    }
}

// ---------------- launch ----------------
extern "C" void kernel_launch(void* const* d_in, const int* in_sizes, int n_in,
                              void* d_out, int out_size) {
    const float* mean = (const float*)d_in[0];
    const float* cov  = (const float*)d_in[1];
    const float* obs  = (const float*)d_in[2];
    const float* rs   = (const float*)d_in[3];
    const void*  ini  = d_in[4];
    const void*  sel  = d_in[5];
    float* out = (float*)d_out;

    // plain NT=64 NS=3: 3 x (A 10240 + B 5120) = 46080 > Cs 128*65*4=33280
    // split NT=128 NS=2: 2 x 4 x 10240 = 81920 > Cs 128*129*4=66048
    const int SMB_P = 46080;
    const int SMB_S = 81920;

    cudaFuncSetAttribute(gemm_mma<0,0,0,0,0,3,64>,  cudaFuncAttributeMaxDynamicSharedMemorySize, SMB_P);
    cudaFuncSetAttribute(gemm_mma<0,1,0,0,0,3,64>,  cudaFuncAttributeMaxDynamicSharedMemorySize, SMB_P);
    cudaFuncSetAttribute(gemm_mma<0,1,0,1,0,3,64>,  cudaFuncAttributeMaxDynamicSharedMemorySize, SMB_P);
    cudaFuncSetAttribute(gemm_mma<1,3,0,0,0,2,128>, cudaFuncAttributeMaxDynamicSharedMemorySize, SMB_S);
    cudaFuncSetAttribute(gemm_mma<0,6,1,1,1,3,64>,  cudaFuncAttributeMaxDynamicSharedMemorySize, SMB_P);

    prep_flags<<<1, 64>>>(rs, ini, sel);
    build_S<<<dim3(DP / 8, NAG), 256>>>(cov);
    fill_X<<<dim3(144, NAG), 256>>>();

    dim3 g12(12, 1, NAG);
    dim3 g6(6, 1, NAG);
    // buffers: 0=S, 1=XA, 2=XB, 3=Y/D
    // plain Newton iter 1
    gemm_mma<0,0,0,0,0,3,64><<<g12, 256, SMB_P>>>(0, 1, 0, 3, nullptr);  // Y  = S*XA        (hi)
    gemm_mma<0,1,0,0,0,3,64><<<g12, 256, SMB_P>>>(1, 3, 1, 2, nullptr);  // XB = 2XA - XA*Y  (hi)
    // plain Newton iter 2
    gemm_mma<0,0,0,0,0,3,64><<<g12, 256, SMB_P>>>(0, 2, 0, 3, nullptr);  // Y  = S*XB        (hi)
    gemm_mma<0,1,0,1,0,3,64><<<g12, 256, SMB_P>>>(2, 3, 2, 1, nullptr);  // XA = 2XB - XB*Y  (hi+lo)
    // quadratic finish: Xf = XA - XA*D, D = S*XA - I (split)
    gemm_mma<1,3,0,0,0,2,128><<<g6, 256, SMB_S>>>(0, 1, 0, 3, nullptr);  // D  = S*XA - I    (split, hi)
    gemm_mma<0,6,1,1,1,3,64><<<g12, 256, SMB_P>>>(1, 3, 1, 2, out + OUT_COV); // Xf = XA - XA*D -> XB (+cov)

    finalize_cov_rest<<<dim3((DD / 4 + 255) / 256, NAG), 256>>>(cov, out);
    finalize_mean<<<NAG, 256>>>(mean, obs, out, 2);
}

// round 12
// speedup vs baseline: 1.7005x; 1.0526x over previous
#include <cuda_runtime.h>
#include <cuda_bf16.h>
#include <cstdint>
#include <cstddef>

// ---------------- problem constants ----------------
#define NAG 64           // B*A
#define DIN 360          // logical dim
#define DD  (DIN*DIN)
#define MODE_LEN 60
#define DP  384          // padded dim (3 x 128)
#define DP2 (DP*DP)

// ---------------- scratch: bf16 hi/lo pairs ----------------
__device__ __align__(128) __nv_bfloat16 g_Sh [(size_t)NAG*DP2];
__device__ __align__(128) __nv_bfloat16 g_Sl [(size_t)NAG*DP2];
__device__ __align__(128) __nv_bfloat16 g_XAh[(size_t)NAG*DP2];
__device__ __align__(128) __nv_bfloat16 g_XAl[(size_t)NAG*DP2];
__device__ __align__(128) __nv_bfloat16 g_XBh[(size_t)NAG*DP2];
__device__ __align__(128) __nv_bfloat16 g_XBl[(size_t)NAG*DP2];
__device__ __align__(128) __nv_bfloat16 g_Yh [(size_t)NAG*DP2];
__device__ __align__(128) __nv_bfloat16 g_Yl [(size_t)NAG*DP2];
__device__ float g_rowsum[NAG * DIN];
__device__ float g_r[NAG];
__device__ int   g_upd[NAG];
__device__ int   g_initnew[NAG];
__device__ int   g_initout[NAG];

__device__ __forceinline__ __nv_bfloat16* selH(int s) {
    switch (s) {
        case 0:  return g_Sh;
        case 1:  return g_XAh;
        case 2:  return g_XBh;
        default: return g_Yh;
    }
}
__device__ __forceinline__ __nv_bfloat16* selL(int s) {
    switch (s) {
        case 0:  return g_Sl;
        case 1:  return g_XAl;
        case 2:  return g_XBl;
        default: return g_Yl;
    }
}

__device__ __forceinline__ int srcIdx(int g) {
    int l = g % MODE_LEN;
    return (l < MODE_LEN - 2) ? (g + 2) : g;
}

// ---------------- small helpers ----------------
__device__ __forceinline__ uint32_t smem_u32(const void* p) {
    uint32_t a;
    asm("{ .reg .u64 t; cvta.to.shared.u64 t, %1; cvt.u32.u64 %0, t; }"
        : "=r"(a) : "l"(p));
    return a;
}
__device__ __forceinline__ uint32_t pack_bf2(float x, float y) {
    __nv_bfloat162 t = __floats2bfloat162_rn(x, y);
    return *reinterpret_cast<uint32_t*>(&t);
}
__device__ __forceinline__ float2 bf2f(uint32_t u) {
    __nv_bfloat162 t = *reinterpret_cast<__nv_bfloat162*>(&u);
    return make_float2(__bfloat162float(t.x), __bfloat162float(t.y));
}
__device__ __forceinline__ void split2(float a, float b, uint32_t& h, uint32_t& l) {
    __nv_bfloat16 ah = __float2bfloat16_rn(a), bh = __float2bfloat16_rn(b);
    float ar = a - __bfloat162float(ah), br = b - __bfloat162float(bh);
    __nv_bfloat162 t; t.x = ah; t.y = bh;
    h = *reinterpret_cast<uint32_t*>(&t);
    l = pack_bf2(ar, br);
}

// ---------------- flag dtype sniffing (validated round 2) ----------------
__device__ int detect_mode(const unsigned char* p) {
    int n_off = 0, n_3f = 0;
    for (int t = 0; t < 64; t++) {
        unsigned char b = p[t];
        if ((t & 3) && b) n_off++;
        if (((t & 3) == 3) && b == 0x3F) n_3f++;
    }
    if (n_off == 0) return 1;
    if (n_3f > 0)  return 2;
    return 0;
}
__device__ __forceinline__ bool read_flag(const void* p, int t, int mode) {
    if (mode == 1) return ((const int*)p)[t] != 0;
    if (mode == 2) return ((const float*)p)[t] != 0.0f;
    return ((const unsigned char*)p)[t] != 0;
}

__global__ void prep_flags(const float* __restrict__ rs,
                           const void* __restrict__ ini,
                           const void* __restrict__ sel) {
    __shared__ int mode_i, mode_s;
    if (threadIdx.x == 0) {
        mode_i = detect_mode((const unsigned char*)ini);
        mode_s = detect_mode((const unsigned char*)sel);
    }
    __syncthreads();
    int t = threadIdx.x;
    if (t >= NAG) return;
    float r = rs[t] + 1.0f;
    bool i8 = read_flag(ini, t, mode_i);
    bool s8 = read_flag(sel, t, mode_s);
    g_r[t] = r;
    g_upd[t] = (s8 && i8);
    g_initnew[t] = (s8 && !i8);
    g_initout[t] = (s8 || i8);
}

// ---------------- S = A P A^T + (1+r)I -> split bf16 + fused Gershgorin ---
__global__ void build_S(const float* __restrict__ cov) {
    int a = blockIdx.y;
    if (!g_upd[a]) return;
    int warp = threadIdx.x >> 5, lane = threadIdx.x & 31;
    int i = blockIdx.x * 8 + warp;
    float r = g_r[a];
    size_t off = (size_t)a * DP2 + (size_t)i * DP + lane * 12;
    if (i < DIN) {
        const float* row = cov + (size_t)a * DD + (size_t)srcIdx(i) * DIN;
        float asum = 0.0f;
        #pragma unroll
        for (int g = 0; g < 3; g++) {
            float v[4];
            #pragma unroll
            for (int q = 0; q < 4; q++) {
                int j = lane * 12 + g * 4 + q;
                float x = 0.0f;
                if (j < DIN) {
                    x = row[srcIdx(j)];
                    if (j == i) x += 1.0f + r;
                }
                v[q] = x;
                asum += fabsf(x);
            }
            uint32_t h0, l0, h1, l1;
            split2(v[0], v[1], h0, l0);
            split2(v[2], v[3], h1, l1);
            *(uint2*)(g_Sh + off + g * 4) = make_uint2(h0, h1);
            *(uint2*)(g_Sl + off + g * 4) = make_uint2(l0, l1);
        }
        #pragma unroll
        for (int o = 16; o; o >>= 1) asum += __shfl_xor_sync(0xffffffffu, asum, o);
        if (lane == 0) g_rowsum[a * DIN + i] = asum;
    } else {
        #pragma unroll
        for (int g = 0; g < 3; g++) {
            float v[4];
            #pragma unroll
            for (int q = 0; q < 4; q++)
                v[q] = (lane * 12 + g * 4 + q == i) ? 1.0f : 0.0f;
            uint32_t h0, l0, h1, l1;
            split2(v[0], v[1], h0, l0);
            split2(v[2], v[3], h1, l1);
            *(uint2*)(g_Sh + off + g * 4) = make_uint2(h0, h1);
            *(uint2*)(g_Sl + off + g * 4) = make_uint2(l0, l1);
        }
    }
}

// X0 = 2c I - c^2 S -> split bf16 into XA. Gershgorin max fused per block.
__global__ void fill_X(void) {
    int a = blockIdx.y;
    if (!g_upd[a]) return;
    int tid = threadIdx.x;
    __shared__ float wm8[8];
    __shared__ float sc;
    float m = 0.0f;
    for (int i = tid; i < DIN; i += 256) m = fmaxf(m, g_rowsum[a * DIN + i]);
    #pragma unroll
    for (int o = 16; o; o >>= 1) m = fmaxf(m, __shfl_xor_sync(0xffffffffu, m, o));
    if ((tid & 31) == 0) wm8[tid >> 5] = m;
    __syncthreads();
    if (tid == 0) {
        float G = 0.0f;
        #pragma unroll
        for (int w = 0; w < 8; w++) G = fmaxf(G, wm8[w]);
        sc = 2.0f / (1.0f + g_r[a] + G * 1.0002f);
    }
    __syncthreads();
    float c = sc;

    int e4 = blockIdx.x * 256 + tid;   // < DP2/4 = 36864
    int i = e4 / 96;
    int jj = (e4 - i * 96) * 4;
    size_t off = (size_t)a * DP2 + (size_t)i * DP + jj;
    uint2 sh = *(const uint2*)(g_Sh + off);
    uint2 sl = *(const uint2*)(g_Sl + off);
    float2 h0 = bf2f(sh.x), h1 = bf2f(sh.y);
    float2 l0 = bf2f(sl.x), l1 = bf2f(sl.y);
    float s0 = h0.x + l0.x, s1 = h0.y + l0.y, s2 = h1.x + l1.x, s3 = h1.y + l1.y;
    float c2 = c * c;
    float v0 = ((i == jj)     ? 2.0f * c : 0.0f) - c2 * s0;
    float v1 = ((i == jj + 1) ? 2.0f * c : 0.0f) - c2 * s1;
    float v2 = ((i == jj + 2) ? 2.0f * c : 0.0f) - c2 * s2;
    float v3 = ((i == jj + 3) ? 2.0f * c : 0.0f) - c2 * s3;
    uint32_t a0, b0, a1, b1;
    split2(v0, v1, a0, b0);
    split2(v2, v3, a1, b1);
    *(uint2*)(g_XAh + off) = make_uint2(a0, a1);
    *(uint2*)(g_XAl + off) = make_uint2(b0, b1);
}

// ================= pipelined mma.sync bf16 GEMM (symmetric tiles) =====
#define LDT 40
#define PA_E (128 * LDT)
#define PA_B (PA_E * 2)

__device__ __forceinline__ void ldm_x4(uint32_t* r, uint32_t addr) {
    asm volatile("ldmatrix.sync.aligned.m8n8.x4.shared.b16 {%0,%1,%2,%3}, [%4];"
                 : "=r"(r[0]), "=r"(r[1]), "=r"(r[2]), "=r"(r[3]) : "r"(addr));
}
__device__ __forceinline__ void mma_bf16(float* d, const uint32_t* a, const uint32_t* b) {
    asm volatile(
        "mma.sync.aligned.m16n8k16.row.col.f32.bf16.bf16.f32 "
        "{%0,%1,%2,%3}, {%4,%5,%6,%7}, {%8,%9}, {%0,%1,%2,%3};"
        : "+f"(d[0]), "+f"(d[1]), "+f"(d[2]), "+f"(d[3])
        : "r"(a[0]), "r"(a[1]), "r"(a[2]), "r"(a[3]), "r"(b[0]), "r"(b[1]));
}

template<int ROWS>
__device__ __forceinline__ void stageP(const __nv_bfloat16* __restrict__ g,
                                       int row0, int k0, uint32_t dst, int tid) {
    const __nv_bfloat16* src0 = g + (size_t)row0 * DP + k0;
    #pragma unroll
    for (int i = 0; i < ROWS / 64; i++) {
        int id = i * 256 + tid;
        int row = id >> 2, part = id & 3;
        uint32_t d = dst + (uint32_t)(row * LDT + part * 8) * 2;
        const void* s = src0 + (size_t)row * DP + part * 8;
        asm volatile("cp.async.cg.shared.global [%0], [%1], 16;"
                     :: "r"(d), "l"(s));
    }
}

// SPLIT=0: hi*hi (NS-stage pipeline). SPLIT=1: 4 panels staged once, 3 passes.
// MODE 0: C = A*B ; MODE 1: C = 2X - A*B ; MODE 3: C = A*B - I ;
// MODE 6: C = X - A*B (quadratic finish).
// XLO: read X lo plane. WRITELO: write C lo plane.
// FINAL: also write r*I - r^2*C to outp (fp32). MINC: min CTAs/SM.
template<int SPLIT, int MODE, int XLO, int WRITELO, int FINAL, int NS, int NT, int MINC>
__global__ __launch_bounds__(256, MINC)
void gemm_mma(int sA, int sB, int sX, int sC, float* outp) {
    int z = blockIdx.z;
    if (!g_upd[z]) return;

    int bi, bj;
    if (NT == 128) {
        const int bim[6] = {0, 1, 2, 0, 0, 1};
        const int bjm[6] = {0, 1, 2, 1, 2, 2};
        bi = bim[blockIdx.x]; bj = bjm[blockIdx.x];
    } else {
        const int bim[12] = {0, 0, 0, 0, 0, 0, 1, 1, 1, 1, 2, 2};
        const int bjm[12] = {0, 1, 2, 3, 4, 5, 2, 3, 4, 5, 4, 5};
        bi = bim[blockIdx.x]; bj = bjm[blockIdx.x];
    }
    int m0 = bi * 128, n0 = bj * NT;
    bool offd = (NT == 128) ? (bi != bj) : ((bj >> 1) != bi);

    constexpr int PB_E = NT * LDT;
    constexpr int PB_B = PB_E * 2;
    constexpr int MT = (NT == 128) ? 4 : 2;
    constexpr int LDCn = (NT == 128) ? 129 : 65;
    constexpr int STAGE_E = (SPLIT ? 2 : 1) * (PA_E + PB_E);
    constexpr uint32_t STAGE_B = STAGE_E * 2;

    size_t zo = (size_t)z * DP2;
    const __nv_bfloat16* AH = selH(sA) + zo;
    const __nv_bfloat16* AL = selL(sA) + zo;
    const __nv_bfloat16* BH = selH(sB) + zo;
    const __nv_bfloat16* BL = selL(sB) + zo;
    const __nv_bfloat16* XH = selH(sX) + zo;
    const __nv_bfloat16* XL = selL(sX) + zo;
    __nv_bfloat16* CH = selH(sC) + zo;
    __nv_bfloat16* CL = selL(sC) + zo;

    extern __shared__ __align__(16) __nv_bfloat16 sm[];
    float* Cs = reinterpret_cast<float*>(sm);
    uint32_t sbase = smem_u32(sm);

    int tid = threadIdx.x, wid = tid >> 5, lane = tid & 31;
    int wm = (NT == 128) ? (wid & 1) * 64 : (wid & 3) * 32;
    int wn = (NT == 128) ? (wid >> 1) * 32 : (wid >> 2) * 32;

    float acc[MT][4][4];
    #pragma unroll
    for (int i = 0; i < MT; i++)
        #pragma unroll
        for (int j = 0; j < 4; j++)
            #pragma unroll
            for (int q = 0; q < 4; q++) acc[i][j][q] = 0.0f;

    int lt = lane >> 3, lr = lane & 7;
    int a_row = (lt & 1) * 8 + lr;
    int a_col = (lt >> 1) * 8;
    int b_row = (lt >> 1) * 8 + lr;
    int b_col = (lt & 1) * 8;

    auto do_stage = [&](int kc, int b) {
        uint32_t base = sbase + (uint32_t)b * STAGE_B;
        int k0 = kc * 32;
        stageP<128>(AH, m0, k0, base, tid);
        stageP<NT>(BH, n0, k0, base + PA_B, tid);
        if (SPLIT) {
            stageP<128>(AL, m0, k0, base + PA_B + PB_B, tid);
            stageP<NT>(BL, n0, k0, base + 2 * PA_B + PB_B, tid);
        }
        asm volatile("cp.async.commit_group;");
    };

    #pragma unroll
    for (int s = 0; s < NS - 1; s++) do_stage(s, s);

    for (int kc = 0; kc < 12; kc++) {
        // wait until chunk kc's group is complete (tail-aware)
        if (kc < 12 - (NS - 1)) {
            asm volatile("cp.async.wait_group %0;" :: "n"(NS - 2));
        } else {
            int rem = 11 - kc;
            if (rem >= 2)      asm volatile("cp.async.wait_group 2;");
            else if (rem == 1) asm volatile("cp.async.wait_group 1;");
            else               asm volatile("cp.async.wait_group 0;");
        }
        __syncthreads();   // also certifies compute(kc-1) done by all warps

        int nxt = kc + NS - 1;
        if (nxt < 12) do_stage(nxt, nxt % NS);

        int cur = kc % NS;
        const __nv_bfloat16* At  = sm + (size_t)cur * STAGE_E;
        const __nv_bfloat16* Bt  = At + PA_E;
        const __nv_bfloat16* Alt = Bt + PB_E;
        const __nv_bfloat16* Blt = Alt + PA_E;

        #pragma unroll
        for (int ks = 0; ks < 2; ks++) {
            int kk = ks * 16;
            uint32_t ah[MT][4], bh[4][2];
            #pragma unroll
            for (int mt = 0; mt < MT; mt++)
                ldm_x4(ah[mt], smem_u32(&At[(wm + mt * 16 + a_row) * LDT + kk + a_col]));
            #pragma unroll
            for (int np = 0; np < 2; np++) {
                uint32_t r[4];
                ldm_x4(r, smem_u32(&Bt[(wn + np * 16 + b_row) * LDT + kk + b_col]));
                bh[np * 2][0] = r[0]; bh[np * 2][1] = r[1];
                bh[np * 2 + 1][0] = r[2]; bh[np * 2 + 1][1] = r[3];
            }
            #pragma unroll
            for (int mt = 0; mt < MT; mt++)
                #pragma unroll
                for (int nt = 0; nt < 4; nt++)
                    mma_bf16(acc[mt][nt], ah[mt], bh[nt]);

            if (SPLIT) {
                uint32_t bl[4][2];
                #pragma unroll
                for (int np = 0; np < 2; np++) {
                    uint32_t r[4];
                    ldm_x4(r, smem_u32(&Blt[(wn + np * 16 + b_row) * LDT + kk + b_col]));
                    bl[np * 2][0] = r[0]; bl[np * 2][1] = r[1];
                    bl[np * 2 + 1][0] = r[2]; bl[np * 2 + 1][1] = r[3];
                }
                #pragma unroll
                for (int mt = 0; mt < MT; mt++)
                    #pragma unroll
                    for (int nt = 0; nt < 4; nt++)
                        mma_bf16(acc[mt][nt], ah[mt], bl[nt]);
                uint32_t al[MT][4];
                #pragma unroll
                for (int mt = 0; mt < MT; mt++)
                    ldm_x4(al[mt], smem_u32(&Alt[(wm + mt * 16 + a_row) * LDT + kk + a_col]));
                #pragma unroll
                for (int mt = 0; mt < MT; mt++)
                    #pragma unroll
                    for (int nt = 0; nt < 4; nt++)
                        mma_bf16(acc[mt][nt], al[mt], bh[nt]);
            }
        }
    }
    __syncthreads();   // protect Cs reuse of staging smem

    // ---- epilogue ----
    float r = g_r[z];
    float rr = -r * r;
    #pragma unroll
    for (int mt = 0; mt < MT; mt++) {
        int rl0 = wm + mt * 16 + (lane >> 2);
        #pragma unroll
        for (int nt = 0; nt < 4; nt++) {
            int cl0 = wn + nt * 8 + 2 * (lane & 3);
            float v00 = acc[mt][nt][0], v01 = acc[mt][nt][1];
            float v10 = acc[mt][nt][2], v11 = acc[mt][nt][3];
            size_t g0 = (size_t)(m0 + rl0) * DP + n0 + cl0;
            size_t g1 = g0 + 8 * DP;
            int gi0 = m0 + rl0, gj = n0 + cl0;
            if (MODE == 1 || MODE == 6) {
                float2 xh0 = bf2f(*(const uint32_t*)(XH + g0));
                float2 xh1 = bf2f(*(const uint32_t*)(XH + g1));
                float x00 = xh0.x, x01 = xh0.y, x10 = xh1.x, x11 = xh1.y;
                if (XLO) {
                    float2 xl0 = bf2f(*(const uint32_t*)(XL + g0));
                    float2 xl1 = bf2f(*(const uint32_t*)(XL + g1));
                    x00 += xl0.x; x01 += xl0.y; x10 += xl1.x; x11 += xl1.y;
                }
                if (MODE == 1) {
                    v00 = 2.0f * x00 - v00; v01 = 2.0f * x01 - v01;
                    v10 = 2.0f * x10 - v10; v11 = 2.0f * x11 - v11;
                } else {                 // MODE 6: C = X - A*B
                    v00 = x00 - v00; v01 = x01 - v01;
                    v10 = x10 - v10; v11 = x11 - v11;
                }
            }
            if (MODE == 3) {   // C = A*B - I
                if (gi0 == gj)     v00 -= 1.0f;
                if (gi0 == gj + 1) v01 -= 1.0f;
                if (gi0 + 8 == gj)     v10 -= 1.0f;
                if (gi0 + 8 == gj + 1) v11 -= 1.0f;
            }
            uint32_t h, l;
            split2(v00, v01, h, l);
            *(uint32_t*)(CH + g0) = h;
            if (WRITELO) *(uint32_t*)(CL + g0) = l;
            split2(v10, v11, h, l);
            *(uint32_t*)(CH + g1) = h;
            if (WRITELO) *(uint32_t*)(CL + g1) = l;
            if (FINAL) {
                if (gj < DIN) {
                    if (gi0 < DIN) {
                        float2 o;
                        o.x = rr * v00 + ((gi0 == gj) ? r : 0.0f);
                        o.y = rr * v01 + ((gi0 == gj + 1) ? r : 0.0f);
                        *(float2*)(outp + (size_t)z * DD + (size_t)gi0 * DIN + gj) = o;
                    }
                    int gi1 = gi0 + 8;
                    if (gi1 < DIN) {
                        float2 o;
                        o.x = rr * v10 + ((gi1 == gj) ? r : 0.0f);
                        o.y = rr * v11 + ((gi1 == gj + 1) ? r : 0.0f);
                        *(float2*)(outp + (size_t)z * DD + (size_t)gi1 * DIN + gj) = o;
                    }
                }
            }
            if (offd) {
                Cs[rl0 * LDCn + cl0] = v00;
                Cs[rl0 * LDCn + cl0 + 1] = v01;
                Cs[(rl0 + 8) * LDCn + cl0] = v10;
                Cs[(rl0 + 8) * LDCn + cl0 + 1] = v11;
            }
        }
    }

    if (offd) {
        __syncthreads();
        #pragma unroll
        for (int it = 0; it < NT / 4; it++) {
            int p = it * 256 + tid;
            int cc = p >> 6, mp = (p & 63) * 2;
            float v0 = Cs[mp * LDCn + cc];
            float v1 = Cs[(mp + 1) * LDCn + cc];
            int gi = n0 + cc, gj = m0 + mp;
            size_t g = (size_t)gi * DP + gj;
            uint32_t h, l;
            split2(v0, v1, h, l);
            *(uint32_t*)(CH + g) = h;
            if (WRITELO) *(uint32_t*)(CL + g) = l;
            if (FINAL) {
                if (gi < DIN && gj < DIN) {
                    float2 o;
                    o.x = rr * v0;
                    o.y = rr * v1;
                    *(float2*)(outp + (size_t)z * DD + (size_t)gi * DIN + gj) = o;
                }
            }
        }
    }
}

// ---------------- outputs ----------------
#define OUT_MEAN 0
#define OUT_COV  (NAG * DIN)
#define OUT_INIT (NAG * DIN + NAG * DD)

__global__ void finalize_cov_rest(const float* __restrict__ cov,
                                  float* __restrict__ out) {
    int a = blockIdx.y;
    if (g_upd[a]) return;
    int e4 = blockIdx.x * blockDim.x + threadIdx.x;
    if (e4 >= DD / 4) return;
    int i = e4 / 90;
    int jj = (e4 - i * 90) * 4;
    float4 o = *(const float4*)(cov + (size_t)a * DD + (size_t)i * DIN + jj);
    if (g_initnew[a]) {
        if (i >= jj && i < jj + 4) (&o.x)[i - jj] += g_r[a];
    }
    *(float4*)(out + OUT_COV + (size_t)a * DD + (size_t)i * DIN + jj) = o;
}

__global__ void finalize_mean(const float* __restrict__ mean_in,
                              const float* __restrict__ obs,
                              float* __restrict__ out, int sinv) {
    int a = blockIdx.x;
    int tid = threadIdx.x;
    __shared__ float v[DIN];

    if (tid == 0) out[OUT_INIT + a] = g_initout[a] ? 1.0f : 0.0f;

    const float* m = mean_in + (size_t)a * DIN;
    const float* o = obs + (size_t)a * DIN;
    float* om = out + OUT_MEAN + (size_t)a * DIN;

    if (g_initnew[a]) {
        for (int i = tid; i < DIN; i += blockDim.x) om[i] = o[i];
    } else if (g_upd[a]) {
        float r = g_r[a];
        const __nv_bfloat16* Xh = selH(sinv) + (size_t)a * DP2;
        const __nv_bfloat16* Xl = selL(sinv) + (size_t)a * DP2;
        for (int j = tid; j < DIN; j += blockDim.x) v[j] = o[j] - m[srcIdx(j)];
        __syncthreads();
        int warp = tid >> 5, lane = tid & 31;
        for (int i = warp; i < DIN; i += 8) {
            float s = 0.0f;
            size_t row = (size_t)i * DP;
            for (int j = lane; j < DIN; j += 32)
                s += (__bfloat162float(Xh[row + j]) + __bfloat162float(Xl[row + j])) * v[j];
            #pragma unroll
            for (int off = 16; off; off >>= 1) s += __shfl_xor_sync(0xffffffffu, s, off);
            if (lane == 0) om[i] = o[i] - r * s;
        }
    } else {
        for (int i = tid; i < DIN; i += blockDim.x) om[i] = m[i];
    }
}

// ---------------- launch ----------------
extern "C" void kernel_launch(void* const* d_in, const int* in_sizes, int n_in,
                              void* d_out, int out_size) {
    const float* mean = (const float*)d_in[0];
    const float* cov  = (const float*)d_in[1];
    const float* obs  = (const float*)d_in[2];
    const float* rs   = (const float*)d_in[3];
    const void*  ini  = d_in[4];
    const void*  sel  = d_in[5];
    float* out = (float*)d_out;

    // plain NT=64 NS=4: 4 x (10240 + 5120) = 61440 ; Cs = 128*65*4 = 33280
    // split NT=64 NS=2: 2 x 2 x (10240 + 5120) = 61440
    const int SMB_P = 61440;
    const int SMB_S = 61440;

    cudaFuncSetAttribute(gemm_mma<0,0,0,0,0,4,64,3>, cudaFuncAttributeMaxDynamicSharedMemorySize, SMB_P);
    cudaFuncSetAttribute(gemm_mma<0,1,0,0,0,4,64,3>, cudaFuncAttributeMaxDynamicSharedMemorySize, SMB_P);
    cudaFuncSetAttribute(gemm_mma<0,1,0,1,0,4,64,3>, cudaFuncAttributeMaxDynamicSharedMemorySize, SMB_P);
    cudaFuncSetAttribute(gemm_mma<1,3,0,0,0,2,64,2>, cudaFuncAttributeMaxDynamicSharedMemorySize, SMB_S);
    cudaFuncSetAttribute(gemm_mma<0,6,1,1,1,4,64,3>, cudaFuncAttributeMaxDynamicSharedMemorySize, SMB_P);

    prep_flags<<<1, 64>>>(rs, ini, sel);
    build_S<<<dim3(DP / 8, NAG), 256>>>(cov);
    fill_X<<<dim3(144, NAG), 256>>>();

    dim3 g12(12, 1, NAG);
    // buffers: 0=S, 1=XA, 2=XB, 3=Y/D
    // plain Newton iter 1
    gemm_mma<0,0,0,0,0,4,64,3><<<g12, 256, SMB_P>>>(0, 1, 0, 3, nullptr);  // Y  = S*XA        (hi)
    gemm_mma<0,1,0,0,0,4,64,3><<<g12, 256, SMB_P>>>(1, 3, 1, 2, nullptr);  // XB = 2XA - XA*Y  (hi)
    // plain Newton iter 2
    gemm_mma<0,0,0,0,0,4,64,3><<<g12, 256, SMB_P>>>(0, 2, 0, 3, nullptr);  // Y  = S*XB        (hi)
    gemm_mma<0,1,0,1,0,4,64,3><<<g12, 256, SMB_P>>>(2, 3, 2, 1, nullptr);  // XA = 2XB - XB*Y  (hi+lo)
    // quadratic finish: Xf = XA - XA*D, D = S*XA - I (split)
    gemm_mma<1,3,0,0,0,2,64,2><<<g12, 256, SMB_S>>>(0, 1, 0, 3, nullptr);  // D  = S*XA - I    (split, hi)
    gemm_mma<0,6,1,1,1,4,64,3><<<g12, 256, SMB_P>>>(1, 3, 1, 2, out + OUT_COV); // Xf = XA - XA*D -> XB (+cov)

    finalize_cov_rest<<<dim3((DD / 4 + 255) / 256, NAG), 256>>>(cov, out);
    finalize_mean<<<NAG, 256>>>(mean, obs, out, 2);
}

// round 13
// speedup vs baseline: 1.7500x; 1.0291x over previous
#include <cuda_runtime.h>
#include <cuda_bf16.h>
#include <cstdint>
#include <cstddef>

// ---------------- problem constants ----------------
#define NAG 64           // B*A
#define DIN 360          // logical dim
#define DD  (DIN*DIN)
#define MODE_LEN 60
#define DP  384          // padded dim (3 x 128)
#define DP2 (DP*DP)

// ---------------- scratch: bf16 hi/lo pairs ----------------
__device__ __align__(128) __nv_bfloat16 g_Sh [(size_t)NAG*DP2];
__device__ __align__(128) __nv_bfloat16 g_Sl [(size_t)NAG*DP2];
__device__ __align__(128) __nv_bfloat16 g_XAh[(size_t)NAG*DP2];
__device__ __align__(128) __nv_bfloat16 g_XAl[(size_t)NAG*DP2];
__device__ __align__(128) __nv_bfloat16 g_XBh[(size_t)NAG*DP2];
__device__ __align__(128) __nv_bfloat16 g_XBl[(size_t)NAG*DP2];
__device__ __align__(128) __nv_bfloat16 g_Yh [(size_t)NAG*DP2];
__device__ __align__(128) __nv_bfloat16 g_Yl [(size_t)NAG*DP2];
__device__ float g_rowsum[NAG * DIN];
__device__ float g_r[NAG];
__device__ int   g_upd[NAG];
__device__ int   g_initnew[NAG];
__device__ int   g_initout[NAG];

__device__ __forceinline__ __nv_bfloat16* selH(int s) {
    switch (s) {
        case 0:  return g_Sh;
        case 1:  return g_XAh;
        case 2:  return g_XBh;
        default: return g_Yh;
    }
}
__device__ __forceinline__ __nv_bfloat16* selL(int s) {
    switch (s) {
        case 0:  return g_Sl;
        case 1:  return g_XAl;
        case 2:  return g_XBl;
        default: return g_Yl;
    }
}

__device__ __forceinline__ int srcIdx(int g) {
    int l = g % MODE_LEN;
    return (l < MODE_LEN - 2) ? (g + 2) : g;
}

// ---------------- small helpers ----------------
__device__ __forceinline__ uint32_t smem_u32(const void* p) {
    uint32_t a;
    asm("{ .reg .u64 t; cvta.to.shared.u64 t, %1; cvt.u32.u64 %0, t; }"
        : "=r"(a) : "l"(p));
    return a;
}
__device__ __forceinline__ uint32_t pack_bf2(float x, float y) {
    __nv_bfloat162 t = __floats2bfloat162_rn(x, y);
    return *reinterpret_cast<uint32_t*>(&t);
}
__device__ __forceinline__ float2 bf2f(uint32_t u) {
    __nv_bfloat162 t = *reinterpret_cast<__nv_bfloat162*>(&u);
    return make_float2(__bfloat162float(t.x), __bfloat162float(t.y));
}
__device__ __forceinline__ void split2(float a, float b, uint32_t& h, uint32_t& l) {
    __nv_bfloat16 ah = __float2bfloat16_rn(a), bh = __float2bfloat16_rn(b);
    float ar = a - __bfloat162float(ah), br = b - __bfloat162float(bh);
    __nv_bfloat162 t; t.x = ah; t.y = bh;
    h = *reinterpret_cast<uint32_t*>(&t);
    l = pack_bf2(ar, br);
}

// ---------------- flag dtype sniffing (validated round 2) ----------------
__device__ int detect_mode(const unsigned char* p) {
    int n_off = 0, n_3f = 0;
    for (int t = 0; t < 64; t++) {
        unsigned char b = p[t];
        if ((t & 3) && b) n_off++;
        if (((t & 3) == 3) && b == 0x3F) n_3f++;
    }
    if (n_off == 0) return 1;
    if (n_3f > 0)  return 2;
    return 0;
}
__device__ __forceinline__ bool read_flag(const void* p, int t, int mode) {
    if (mode == 1) return ((const int*)p)[t] != 0;
    if (mode == 2) return ((const float*)p)[t] != 0.0f;
    return ((const unsigned char*)p)[t] != 0;
}

__global__ void prep_flags(const float* __restrict__ rs,
                           const void* __restrict__ ini,
                           const void* __restrict__ sel) {
    __shared__ int mode_i, mode_s;
    if (threadIdx.x == 0) {
        mode_i = detect_mode((const unsigned char*)ini);
        mode_s = detect_mode((const unsigned char*)sel);
    }
    __syncthreads();
    int t = threadIdx.x;
    if (t >= NAG) return;
    float r = rs[t] + 1.0f;
    bool i8 = read_flag(ini, t, mode_i);
    bool s8 = read_flag(sel, t, mode_s);
    g_r[t] = r;
    g_upd[t] = (s8 && i8);
    g_initnew[t] = (s8 && !i8);
    g_initout[t] = (s8 || i8);
}

// ---------------- S = A P A^T + (1+r)I -> split bf16 + fused Gershgorin ---
__global__ void build_S(const float* __restrict__ cov) {
    int a = blockIdx.y;
    if (!g_upd[a]) return;
    int warp = threadIdx.x >> 5, lane = threadIdx.x & 31;
    int i = blockIdx.x * 8 + warp;
    float r = g_r[a];
    size_t off = (size_t)a * DP2 + (size_t)i * DP + lane * 12;
    if (i < DIN) {
        const float* row = cov + (size_t)a * DD + (size_t)srcIdx(i) * DIN;
        float asum = 0.0f;
        #pragma unroll
        for (int g = 0; g < 3; g++) {
            float v[4];
            #pragma unroll
            for (int q = 0; q < 4; q++) {
                int j = lane * 12 + g * 4 + q;
                float x = 0.0f;
                if (j < DIN) {
                    x = row[srcIdx(j)];
                    if (j == i) x += 1.0f + r;
                }
                v[q] = x;
                asum += fabsf(x);
            }
            uint32_t h0, l0, h1, l1;
            split2(v[0], v[1], h0, l0);
            split2(v[2], v[3], h1, l1);
            *(uint2*)(g_Sh + off + g * 4) = make_uint2(h0, h1);
            *(uint2*)(g_Sl + off + g * 4) = make_uint2(l0, l1);
        }
        #pragma unroll
        for (int o = 16; o; o >>= 1) asum += __shfl_xor_sync(0xffffffffu, asum, o);
        if (lane == 0) g_rowsum[a * DIN + i] = asum;
    } else {
        #pragma unroll
        for (int g = 0; g < 3; g++) {
            float v[4];
            #pragma unroll
            for (int q = 0; q < 4; q++)
                v[q] = (lane * 12 + g * 4 + q == i) ? 1.0f : 0.0f;
            uint32_t h0, l0, h1, l1;
            split2(v[0], v[1], h0, l0);
            split2(v[2], v[3], h1, l1);
            *(uint2*)(g_Sh + off + g * 4) = make_uint2(h0, h1);
            *(uint2*)(g_Sl + off + g * 4) = make_uint2(l0, l1);
        }
    }
}

// X0 = 2c I - c^2 S -> split bf16 into XA. Gershgorin max fused per block.
__global__ void fill_X(void) {
    int a = blockIdx.y;
    if (!g_upd[a]) return;
    int tid = threadIdx.x;
    __shared__ float wm8[8];
    __shared__ float sc;
    float m = 0.0f;
    for (int i = tid; i < DIN; i += 256) m = fmaxf(m, g_rowsum[a * DIN + i]);
    #pragma unroll
    for (int o = 16; o; o >>= 1) m = fmaxf(m, __shfl_xor_sync(0xffffffffu, m, o));
    if ((tid & 31) == 0) wm8[tid >> 5] = m;
    __syncthreads();
    if (tid == 0) {
        float G = 0.0f;
        #pragma unroll
        for (int w = 0; w < 8; w++) G = fmaxf(G, wm8[w]);
        sc = 2.0f / (1.0f + g_r[a] + G * 1.0002f);
    }
    __syncthreads();
    float c = sc;

    int e4 = blockIdx.x * 256 + tid;   // < DP2/4 = 36864
    int i = e4 / 96;
    int jj = (e4 - i * 96) * 4;
    size_t off = (size_t)a * DP2 + (size_t)i * DP + jj;
    uint2 sh = *(const uint2*)(g_Sh + off);
    uint2 sl = *(const uint2*)(g_Sl + off);
    float2 h0 = bf2f(sh.x), h1 = bf2f(sh.y);
    float2 l0 = bf2f(sl.x), l1 = bf2f(sl.y);
    float s0 = h0.x + l0.x, s1 = h0.y + l0.y, s2 = h1.x + l1.x, s3 = h1.y + l1.y;
    float c2 = c * c;
    float v0 = ((i == jj)     ? 2.0f * c : 0.0f) - c2 * s0;
    float v1 = ((i == jj + 1) ? 2.0f * c : 0.0f) - c2 * s1;
    float v2 = ((i == jj + 2) ? 2.0f * c : 0.0f) - c2 * s2;
    float v3 = ((i == jj + 3) ? 2.0f * c : 0.0f) - c2 * s3;
    uint32_t a0, b0, a1, b1;
    split2(v0, v1, a0, b0);
    split2(v2, v3, a1, b1);
    *(uint2*)(g_XAh + off) = make_uint2(a0, a1);
    *(uint2*)(g_XAl + off) = make_uint2(b0, b1);
}

// ================= pipelined mma.sync bf16 GEMM (symmetric tiles) =====
// k-chunk 64, LDT=72 halves (144B rows: conflict-free ldmatrix, 6 chunks).
#define LDT 72
#define PA_E (128 * LDT)     // 9216 elems = 18432 B
#define PA_B (PA_E * 2)

__device__ __forceinline__ void ldm_x4(uint32_t* r, uint32_t addr) {
    asm volatile("ldmatrix.sync.aligned.m8n8.x4.shared.b16 {%0,%1,%2,%3}, [%4];"
                 : "=r"(r[0]), "=r"(r[1]), "=r"(r[2]), "=r"(r[3]) : "r"(addr));
}
__device__ __forceinline__ void mma_bf16(float* d, const uint32_t* a, const uint32_t* b) {
    asm volatile(
        "mma.sync.aligned.m16n8k16.row.col.f32.bf16.bf16.f32 "
        "{%0,%1,%2,%3}, {%4,%5,%6,%7}, {%8,%9}, {%0,%1,%2,%3};"
        : "+f"(d[0]), "+f"(d[1]), "+f"(d[2]), "+f"(d[3])
        : "r"(a[0]), "r"(a[1]), "r"(a[2]), "r"(a[3]), "r"(b[0]), "r"(b[1]));
}

// stage one ROWSx64 bf16 panel (128B rows = 8 x 16B) global -> SMEM
template<int ROWS>
__device__ __forceinline__ void stageP(const __nv_bfloat16* __restrict__ g,
                                       int row0, int k0, uint32_t dst, int tid) {
    const __nv_bfloat16* src0 = g + (size_t)row0 * DP + k0;
    #pragma unroll
    for (int i = 0; i < ROWS / 32; i++) {
        int id = i * 256 + tid;
        int row = id >> 3, part = id & 7;
        uint32_t d = dst + (uint32_t)(row * LDT + part * 8) * 2;
        const void* s = src0 + (size_t)row * DP + part * 8;
        asm volatile("cp.async.cg.shared.global [%0], [%1], 16;"
                     :: "r"(d), "l"(s));
    }
}

// SPLIT=0: hi*hi (2-stage pipeline). SPLIT=1: 4 panels staged once, 3 passes.
// MODE 0: C = A*B ; MODE 1: C = 2X - A*B ; MODE 3: C = A*B - I ;
// MODE 6: C = X - A*B (quadratic finish).
// XLO: read X lo plane. WRITELO: write C lo plane.
// FINAL: also write r*I - r^2*C to outp (fp32). MINC: min CTAs/SM.
template<int SPLIT, int MODE, int XLO, int WRITELO, int FINAL, int NT, int MINC>
__global__ __launch_bounds__(256, MINC)
void gemm_mma(int sA, int sB, int sX, int sC, float* outp) {
    int z = blockIdx.z;
    if (!g_upd[z]) return;

    const int bim[12] = {0, 0, 0, 0, 0, 0, 1, 1, 1, 1, 2, 2};
    const int bjm[12] = {0, 1, 2, 3, 4, 5, 2, 3, 4, 5, 4, 5};
    int bi = bim[blockIdx.x], bj = bjm[blockIdx.x];
    int m0 = bi * 128, n0 = bj * NT;
    bool offd = ((bj >> 1) != bi);

    constexpr int PB_E = NT * LDT;
    constexpr int PB_B = PB_E * 2;
    constexpr int MT = 2;              // NT = 64
    constexpr int LDCn = 65;
    constexpr int STAGE_E = (SPLIT ? 2 : 1) * (PA_E + PB_E);
    constexpr uint32_t STAGE_B = STAGE_E * 2;

    size_t zo = (size_t)z * DP2;
    const __nv_bfloat16* AH = selH(sA) + zo;
    const __nv_bfloat16* AL = selL(sA) + zo;
    const __nv_bfloat16* BH = selH(sB) + zo;
    const __nv_bfloat16* BL = selL(sB) + zo;
    const __nv_bfloat16* XH = selH(sX) + zo;
    const __nv_bfloat16* XL = selL(sX) + zo;
    __nv_bfloat16* CH = selH(sC) + zo;
    __nv_bfloat16* CL = selL(sC) + zo;

    extern __shared__ __align__(16) __nv_bfloat16 sm[];
    float* Cs = reinterpret_cast<float*>(sm);
    uint32_t sbase = smem_u32(sm);

    int tid = threadIdx.x, wid = tid >> 5, lane = tid & 31;
    int wm = (wid & 3) * 32;
    int wn = (wid >> 2) * 32;

    float acc[MT][4][4];
    #pragma unroll
    for (int i = 0; i < MT; i++)
        #pragma unroll
        for (int j = 0; j < 4; j++)
            #pragma unroll
            for (int q = 0; q < 4; q++) acc[i][j][q] = 0.0f;

    int lt = lane >> 3, lr = lane & 7;
    int a_row = (lt & 1) * 8 + lr;
    int a_col = (lt >> 1) * 8;
    int b_row = (lt >> 1) * 8 + lr;
    int b_col = (lt & 1) * 8;

    auto do_stage = [&](int kc, int b) {
        uint32_t base = sbase + (uint32_t)b * STAGE_B;
        int k0 = kc * 64;
        stageP<128>(AH, m0, k0, base, tid);
        stageP<NT>(BH, n0, k0, base + PA_B, tid);
        if (SPLIT) {
            stageP<128>(AL, m0, k0, base + PA_B + PB_B, tid);
            stageP<NT>(BL, n0, k0, base + 2 * PA_B + PB_B, tid);
        }
        asm volatile("cp.async.commit_group;");
    };

    do_stage(0, 0);

    for (int kc = 0; kc < 6; kc++) {
        asm volatile("cp.async.wait_group 0;");
        __syncthreads();   // certifies compute(kc-1) done; buffer kc+1 free

        if (kc + 1 < 6) do_stage(kc + 1, (kc + 1) & 1);

        int cur = kc & 1;
        const __nv_bfloat16* At  = sm + (size_t)cur * STAGE_E;
        const __nv_bfloat16* Bt  = At + PA_E;
        const __nv_bfloat16* Alt = Bt + PB_E;
        const __nv_bfloat16* Blt = Alt + PA_E;

        #pragma unroll
        for (int ks = 0; ks < 4; ks++) {
            int kk = ks * 16;
            uint32_t ah[MT][4], bh[4][2];
            #pragma unroll
            for (int mt = 0; mt < MT; mt++)
                ldm_x4(ah[mt], smem_u32(&At[(wm + mt * 16 + a_row) * LDT + kk + a_col]));
            #pragma unroll
            for (int np = 0; np < 2; np++) {
                uint32_t r[4];
                ldm_x4(r, smem_u32(&Bt[(wn + np * 16 + b_row) * LDT + kk + b_col]));
                bh[np * 2][0] = r[0]; bh[np * 2][1] = r[1];
                bh[np * 2 + 1][0] = r[2]; bh[np * 2 + 1][1] = r[3];
            }
            #pragma unroll
            for (int mt = 0; mt < MT; mt++)
                #pragma unroll
                for (int nt = 0; nt < 4; nt++)
                    mma_bf16(acc[mt][nt], ah[mt], bh[nt]);

            if (SPLIT) {
                uint32_t bl[4][2];
                #pragma unroll
                for (int np = 0; np < 2; np++) {
                    uint32_t r[4];
                    ldm_x4(r, smem_u32(&Blt[(wn + np * 16 + b_row) * LDT + kk + b_col]));
                    bl[np * 2][0] = r[0]; bl[np * 2][1] = r[1];
                    bl[np * 2 + 1][0] = r[2]; bl[np * 2 + 1][1] = r[3];
                }
                #pragma unroll
                for (int mt = 0; mt < MT; mt++)
                    #pragma unroll
                    for (int nt = 0; nt < 4; nt++)
                        mma_bf16(acc[mt][nt], ah[mt], bl[nt]);
                uint32_t al[MT][4];
                #pragma unroll
                for (int mt = 0; mt < MT; mt++)
                    ldm_x4(al[mt], smem_u32(&Alt[(wm + mt * 16 + a_row) * LDT + kk + a_col]));
                #pragma unroll
                for (int mt = 0; mt < MT; mt++)
                    #pragma unroll
                    for (int nt = 0; nt < 4; nt++)
                        mma_bf16(acc[mt][nt], al[mt], bh[nt]);
            }
        }
    }
    __syncthreads();   // protect Cs reuse of staging smem

    // ---- epilogue ----
    float r = g_r[z];
    float rr = -r * r;
    #pragma unroll
    for (int mt = 0; mt < MT; mt++) {
        int rl0 = wm + mt * 16 + (lane >> 2);
        #pragma unroll
        for (int nt = 0; nt < 4; nt++) {
            int cl0 = wn + nt * 8 + 2 * (lane & 3);
            float v00 = acc[mt][nt][0], v01 = acc[mt][nt][1];
            float v10 = acc[mt][nt][2], v11 = acc[mt][nt][3];
            size_t g0 = (size_t)(m0 + rl0) * DP + n0 + cl0;
            size_t g1 = g0 + 8 * DP;
            int gi0 = m0 + rl0, gj = n0 + cl0;
            if (MODE == 1 || MODE == 6) {
                float2 xh0 = bf2f(*(const uint32_t*)(XH + g0));
                float2 xh1 = bf2f(*(const uint32_t*)(XH + g1));
                float x00 = xh0.x, x01 = xh0.y, x10 = xh1.x, x11 = xh1.y;
                if (XLO) {
                    float2 xl0 = bf2f(*(const uint32_t*)(XL + g0));
                    float2 xl1 = bf2f(*(const uint32_t*)(XL + g1));
                    x00 += xl0.x; x01 += xl0.y; x10 += xl1.x; x11 += xl1.y;
                }
                if (MODE == 1) {
                    v00 = 2.0f * x00 - v00; v01 = 2.0f * x01 - v01;
                    v10 = 2.0f * x10 - v10; v11 = 2.0f * x11 - v11;
                } else {                 // MODE 6: C = X - A*B
                    v00 = x00 - v00; v01 = x01 - v01;
                    v10 = x10 - v10; v11 = x11 - v11;
                }
            }
            if (MODE == 3) {   // C = A*B - I
                if (gi0 == gj)     v00 -= 1.0f;
                if (gi0 == gj + 1) v01 -= 1.0f;
                if (gi0 + 8 == gj)     v10 -= 1.0f;
                if (gi0 + 8 == gj + 1) v11 -= 1.0f;
            }
            uint32_t h, l;
            split2(v00, v01, h, l);
            *(uint32_t*)(CH + g0) = h;
            if (WRITELO) *(uint32_t*)(CL + g0) = l;
            split2(v10, v11, h, l);
            *(uint32_t*)(CH + g1) = h;
            if (WRITELO) *(uint32_t*)(CL + g1) = l;
            if (FINAL) {
                if (gj < DIN) {
                    if (gi0 < DIN) {
                        float2 o;
                        o.x = rr * v00 + ((gi0 == gj) ? r : 0.0f);
                        o.y = rr * v01 + ((gi0 == gj + 1) ? r : 0.0f);
                        *(float2*)(outp + (size_t)z * DD + (size_t)gi0 * DIN + gj) = o;
                    }
                    int gi1 = gi0 + 8;
                    if (gi1 < DIN) {
                        float2 o;
                        o.x = rr * v10 + ((gi1 == gj) ? r : 0.0f);
                        o.y = rr * v11 + ((gi1 == gj + 1) ? r : 0.0f);
                        *(float2*)(outp + (size_t)z * DD + (size_t)gi1 * DIN + gj) = o;
                    }
                }
            }
            if (offd) {
                Cs[rl0 * LDCn + cl0] = v00;
                Cs[rl0 * LDCn + cl0 + 1] = v01;
                Cs[(rl0 + 8) * LDCn + cl0] = v10;
                Cs[(rl0 + 8) * LDCn + cl0 + 1] = v11;
            }
        }
    }

    if (offd) {
        __syncthreads();
        #pragma unroll
        for (int it = 0; it < NT / 4; it++) {
            int p = it * 256 + tid;
            int cc = p >> 6, mp = (p & 63) * 2;
            float v0 = Cs[mp * LDCn + cc];
            float v1 = Cs[(mp + 1) * LDCn + cc];
            int gi = n0 + cc, gj = m0 + mp;
            size_t g = (size_t)gi * DP + gj;
            uint32_t h, l;
            split2(v0, v1, h, l);
            *(uint32_t*)(CH + g) = h;
            if (WRITELO) *(uint32_t*)(CL + g) = l;
            if (FINAL) {
                if (gi < DIN && gj < DIN) {
                    float2 o;
                    o.x = rr * v0;
                    o.y = rr * v1;
                    *(float2*)(outp + (size_t)z * DD + (size_t)gi * DIN + gj) = o;
                }
            }
        }
    }
}

// ---------------- outputs ----------------
#define OUT_MEAN 0
#define OUT_COV  (NAG * DIN)
#define OUT_INIT (NAG * DIN + NAG * DD)

__global__ void finalize_cov_rest(const float* __restrict__ cov,
                                  float* __restrict__ out) {
    int a = blockIdx.y;
    if (g_upd[a]) return;
    int e4 = blockIdx.x * blockDim.x + threadIdx.x;
    if (e4 >= DD / 4) return;
    int i = e4 / 90;
    int jj = (e4 - i * 90) * 4;
    float4 o = *(const float4*)(cov + (size_t)a * DD + (size_t)i * DIN + jj);
    if (g_initnew[a]) {
        if (i >= jj && i < jj + 4) (&o.x)[i - jj] += g_r[a];
    }
    *(float4*)(out + OUT_COV + (size_t)a * DD + (size_t)i * DIN + jj) = o;
}

__global__ void finalize_mean(const float* __restrict__ mean_in,
                              const float* __restrict__ obs,
                              float* __restrict__ out, int sinv) {
    int a = blockIdx.x;
    int tid = threadIdx.x;
    __shared__ float v[DIN];

    if (tid == 0) out[OUT_INIT + a] = g_initout[a] ? 1.0f : 0.0f;

    const float* m = mean_in + (size_t)a * DIN;
    const float* o = obs + (size_t)a * DIN;
    float* om = out + OUT_MEAN + (size_t)a * DIN;

    if (g_initnew[a]) {
        for (int i = tid; i < DIN; i += blockDim.x) om[i] = o[i];
    } else if (g_upd[a]) {
        float r = g_r[a];
        const __nv_bfloat16* Xh = selH(sinv) + (size_t)a * DP2;
        const __nv_bfloat16* Xl = selL(sinv) + (size_t)a * DP2;
        for (int j = tid; j < DIN; j += blockDim.x) v[j] = o[j] - m[srcIdx(j)];
        __syncthreads();
        int warp = tid >> 5, lane = tid & 31;
        for (int i = warp; i < DIN; i += 8) {
            float s = 0.0f;
            size_t row = (size_t)i * DP;
            for (int j = lane; j < DIN; j += 32)
                s += (__bfloat162float(Xh[row + j]) + __bfloat162float(Xl[row + j])) * v[j];
            #pragma unroll
            for (int off = 16; off; off >>= 1) s += __shfl_xor_sync(0xffffffffu, s, off);
            if (lane == 0) om[i] = o[i] - r * s;
        }
    } else {
        for (int i = tid; i < DIN; i += blockDim.x) om[i] = m[i];
    }
}

// ---------------- launch ----------------
extern "C" void kernel_launch(void* const* d_in, const int* in_sizes, int n_in,
                              void* d_out, int out_size) {
    const float* mean = (const float*)d_in[0];
    const float* cov  = (const float*)d_in[1];
    const float* obs  = (const float*)d_in[2];
    const float* rs   = (const float*)d_in[3];
    const void*  ini  = d_in[4];
    const void*  sel  = d_in[5];
    float* out = (float*)d_out;

    // plain: 2 stages x (18432 + 9216) = 55296 B ; Cs = 128*65*4 = 33280 B
    // split: 2 stages x 2 x (18432 + 9216) = 110592 B
    const int SMB_P = 55296;
    const int SMB_S = 110592;

    cudaFuncSetAttribute(gemm_mma<0,0,0,0,0,64,3>, cudaFuncAttributeMaxDynamicSharedMemorySize, SMB_P);
    cudaFuncSetAttribute(gemm_mma<0,1,0,0,0,64,3>, cudaFuncAttributeMaxDynamicSharedMemorySize, SMB_P);
    cudaFuncSetAttribute(gemm_mma<0,1,0,1,0,64,3>, cudaFuncAttributeMaxDynamicSharedMemorySize, SMB_P);
    cudaFuncSetAttribute(gemm_mma<1,3,0,0,0,64,2>, cudaFuncAttributeMaxDynamicSharedMemorySize, SMB_S);
    cudaFuncSetAttribute(gemm_mma<0,6,1,1,1,64,3>, cudaFuncAttributeMaxDynamicSharedMemorySize, SMB_P);

    prep_flags<<<1, 64>>>(rs, ini, sel);
    build_S<<<dim3(DP / 8, NAG), 256>>>(cov);
    fill_X<<<dim3(144, NAG), 256>>>();

    dim3 g12(12, 1, NAG);
    // buffers: 0=S, 1=XA, 2=XB, 3=Y/D
    // plain Newton iter 1
    gemm_mma<0,0,0,0,0,64,3><<<g12, 256, SMB_P>>>(0, 1, 0, 3, nullptr);  // Y  = S*XA        (hi)
    gemm_mma<0,1,0,0,0,64,3><<<g12, 256, SMB_P>>>(1, 3, 1, 2, nullptr);  // XB = 2XA - XA*Y  (hi)
    // plain Newton iter 2
    gemm_mma<0,0,0,0,0,64,3><<<g12, 256, SMB_P>>>(0, 2, 0, 3, nullptr);  // Y  = S*XB        (hi)
    gemm_mma<0,1,0,1,0,64,3><<<g12, 256, SMB_P>>>(2, 3, 2, 1, nullptr);  // XA = 2XB - XB*Y  (hi+lo)
    // quadratic finish: Xf = XA - XA*D, D = S*XA - I (split)
    gemm_mma<1,3,0,0,0,64,2><<<g12, 256, SMB_S>>>(0, 1, 0, 3, nullptr);  // D  = S*XA - I    (split, hi)
    gemm_mma<0,6,1,1,1,64,3><<<g12, 256, SMB_P>>>(1, 3, 1, 2, out + OUT_COV); // Xf = XA - XA*D -> XB (+cov)

    finalize_cov_rest<<<dim3((DD / 4 + 255) / 256, NAG), 256>>>(cov, out);
    finalize_mean<<<NAG, 256>>>(mean, obs, out, 2);
}